// round 2
// baseline (speedup 1.0000x reference)
#include <cuda_runtime.h>
#include <float.h>

// ---------------- problem constants ----------------
#define B_   16
#define S_   512
#define D_   768
#define H_   12
#define HD_  64
#define K_   16
#define NS_  128
#define R_   32
#define BS_  (B_*S_)          // 8192 rows
#define SC_  (B_*H_*S_*S_)    // scores elements

// ---------------- scratch (__device__ globals; no allocs allowed) ----------------
__device__ float    g_xnorm[BS_];
__device__ float    g_sbuf[B_*NS_*D_];
__device__ float    g_dist[B_*S_*NS_];
__device__ double   g_sum[B_], g_sumsq[B_];
__device__ unsigned g_minb[B_], g_maxb[B_];
__device__ float    g_topo[B_*D_];
__device__ float    g_qkv[BS_*3*D_];
__device__ float    g_scores[SC_];
__device__ float    g_attnO[BS_*D_];
__device__ float    g_attnP[BS_*D_];
__device__ float    g_x1[BS_*D_];
__device__ float    g_ffnh[BS_*2*D_];
__device__ float    g_ffn2[BS_*D_];

// ---------------- generic tiled SGEMM ----------------
// C[M,N] = A[M,K] @ B (NN: B=[K,N], NT: B=[N,K]) with batched z-offsets and epilogues.
// EPI: 0 = +bias (bias may be null), 1 = gelu(exact)(x+bias), 2 = *alpha, 3 = cdist sqrt.
template<int BM,int BN,int BK,int TM,int TN,bool BNT,int EPI>
__global__ __launch_bounds__((BM/TM)*(BN/TN))
void gemm_k(const float* __restrict__ A, const float* __restrict__ Bp,
            float* __restrict__ C, const float* __restrict__ bias,
            int M, int N, int Kd, int lda, int ldb, int ldc,
            int Hdiv, long sAb, long sAh, long sBb, long sBh, long sCb, long sCh,
            float alpha, const float* __restrict__ xnorm, const int* __restrict__ sidx)
{
    constexpr int THREADS = (BM/TM)*(BN/TN);
    __shared__ float As[BK][BM];
    __shared__ float Bs[BK][BN];

    const int z  = blockIdx.z;
    const int zb = z / Hdiv, zh = z - zb*Hdiv;
    A  += zb*sAb + zh*sAh;
    Bp += zb*sBb + zh*sBh;
    C  += zb*sCb + zh*sCh;
    const float* xn = (EPI==3) ? (xnorm + (long)z*M) : xnorm;

    const int n0 = blockIdx.x * BN;
    const int m0 = blockIdx.y * BM;
    const int tid = threadIdx.x;
    const int tx = tid % (BN/TN);
    const int ty = tid / (BN/TN);

    float acc[TM][TN];
#pragma unroll
    for (int i=0;i<TM;i++)
#pragma unroll
        for (int j=0;j<TN;j++) acc[i][j]=0.f;

    constexpr int A4 = BM*BK/4;
    constexpr int B4 = BN*BK/4;

    for (int k0=0; k0<Kd; k0+=BK) {
        // load A tile (transpose to As[k][m])
#pragma unroll
        for (int i=tid; i<A4; i+=THREADS) {
            int r  = i / (BK/4);
            int c4 = (i % (BK/4))*4;
            float4 v = *(const float4*)(A + (long)(m0+r)*lda + k0 + c4);
            As[c4+0][r]=v.x; As[c4+1][r]=v.y; As[c4+2][r]=v.z; As[c4+3][r]=v.w;
        }
        if (BNT) {
#pragma unroll
            for (int i=tid; i<B4; i+=THREADS) {
                int r  = i / (BK/4);
                int c4 = (i % (BK/4))*4;
                float4 v = *(const float4*)(Bp + (long)(n0+r)*ldb + k0 + c4);
                Bs[c4+0][r]=v.x; Bs[c4+1][r]=v.y; Bs[c4+2][r]=v.z; Bs[c4+3][r]=v.w;
            }
        } else {
#pragma unroll
            for (int i=tid; i<B4; i+=THREADS) {
                int r  = i / (BN/4);
                int c4 = (i % (BN/4))*4;
                float4 v = *(const float4*)(Bp + (long)(k0+r)*ldb + n0 + c4);
                *(float4*)&Bs[r][c4] = v;
            }
        }
        __syncthreads();
#pragma unroll
        for (int kk=0; kk<BK; kk++) {
            float ar[TM], br[TN];
#pragma unroll
            for (int i=0;i<TM;i+=4) *(float4*)&ar[i] = *(const float4*)&As[kk][ty*TM+i];
#pragma unroll
            for (int j=0;j<TN;j+=4) *(float4*)&br[j] = *(const float4*)&Bs[kk][tx*TN+j];
#pragma unroll
            for (int i=0;i<TM;i++)
#pragma unroll
                for (int j=0;j<TN;j++) acc[i][j] = fmaf(ar[i], br[j], acc[i][j]);
        }
        __syncthreads();
    }

    // epilogue (vectorized stores; all dims/offsets are multiples of 4)
#pragma unroll
    for (int i=0;i<TM;i++) {
        int gm = m0 + ty*TM + i;
#pragma unroll
        for (int j4=0;j4<TN;j4+=4) {
            int gn = n0 + tx*TN + j4;
            float4 v;
            float* vp = &v.x;
#pragma unroll
            for (int u=0;u<4;u++) {
                float a = acc[i][j4+u];
                if (EPI==0) {
                    if (bias) a += bias[gn+u];
                } else if (EPI==1) {
                    float t = a + bias[gn+u];
                    a = t * normcdff(t);            // exact GELU
                } else if (EPI==2) {
                    a *= alpha;
                } else if (EPI==3) {
                    float nx = xn[gm];
                    float ns = xn[sidx[gn+u]];
                    a = sqrtf(fmaxf(nx + ns - 2.f*a, 0.f));
                }
                vp[u] = a;
            }
            *(float4*)(C + (long)gm*ldc + gn) = v;
        }
    }
}

// ---------------- block reduce helper (256 threads) ----------------
__device__ __forceinline__ float blockReduceSum256(float v, float* red) {
#pragma unroll
    for (int o=16;o;o>>=1) v += __shfl_xor_sync(0xffffffffu, v, o);
    int w = threadIdx.x>>5, l = threadIdx.x&31;
    if (l==0) red[w] = v;
    __syncthreads();
    float r = (threadIdx.x < 8) ? red[threadIdx.x] : 0.f;
    if (w==0) {
#pragma unroll
        for (int o=4;o;o>>=1) r += __shfl_xor_sync(0xffffffffu, r, o);
        if (l==0) red[0] = r;
    }
    __syncthreads();
    float out = red[0];
    __syncthreads();
    return out;
}

// ---------------- small kernels ----------------
__global__ void init_k() {
    int t = threadIdx.x;
    if (t < B_) { g_sum[t]=0.0; g_sumsq[t]=0.0; g_minb[t]=0x7f7fffffu; g_maxb[t]=0u; }
}

__global__ void xnorm_k(const float* __restrict__ x) {
    __shared__ float red[8];
    long r = blockIdx.x; int tid = threadIdx.x;
    float loc = 0.f;
    for (int d=tid; d<D_; d+=256) { float t = x[r*D_+d]; loc += t*t; }
    float s = blockReduceSum256(loc, red);
    if (tid==0) g_xnorm[r] = s;
}

__global__ void gather_k(const float* __restrict__ x, const int* __restrict__ sidx) {
    int j = blockIdx.x, b = blockIdx.y;
    int s = sidx[j];
    const float4* src = (const float4*)(x + ((long)b*S_ + s)*D_);
    float4* dst = (float4*)(g_sbuf + ((long)b*NS_ + j)*D_);
    dst[threadIdx.x] = src[threadIdx.x];   // 192 threads * float4 = 768 floats
}

// one warp per (b,s) row of 128 distances; extract 16 smallest iteratively
__global__ void topk_stats_k() {
    int warp = threadIdx.x >> 5, lane = threadIdx.x & 31;
    long row = (long)blockIdx.x*8 + warp;          // 8192 rows total
    const float4* p = (const float4*)(g_dist + row*NS_);
    float4 v4 = p[lane];
    float v[4] = {v4.x, v4.y, v4.z, v4.w};
    float lsum=0.f, lsq=0.f, mn0=0.f, mx15=0.f;
#pragma unroll
    for (int it=0; it<K_; ++it) {
        float lv = fminf(fminf(v[0],v[1]), fminf(v[2],v[3]));
        float m = lv;
#pragma unroll
        for (int o=16;o;o>>=1) m = fminf(m, __shfl_xor_sync(0xffffffffu, m, o));
        unsigned bal = __ballot_sync(0xffffffffu, lv==m);
        int src = __ffs(bal)-1;
        if (lane==src) {
            if      (v[0]==m) v[0]=FLT_MAX;
            else if (v[1]==m) v[1]=FLT_MAX;
            else if (v[2]==m) v[2]=FLT_MAX;
            else              v[3]=FLT_MAX;
        }
        lsum += m; lsq += m*m;
        if (it==0) mn0 = m;
        mx15 = m;
    }
    if (lane==0) {
        int b = (int)(row >> 9);
        atomicAdd(&g_sum[b],   (double)lsum);
        atomicAdd(&g_sumsq[b], (double)lsq);
        atomicMin(&g_minb[b], __float_as_uint(mn0));
        atomicMax(&g_maxb[b], __float_as_uint(mx15));
    }
}

// stats -> landscape MLP -> gated topo embedding, one block per batch
__global__ void mlp_topo_k(const float* __restrict__ w1, const float* __restrict__ b1,
                           const float* __restrict__ w2, const float* __restrict__ b2,
                           const float* __restrict__ wd0, const float* __restrict__ bd0,
                           const float* __restrict__ topo_w, const float* __restrict__ topo_b,
                           const float* __restrict__ gate) {
    int b = blockIdx.x, tid = threadIdx.x;
    __shared__ float st[6], h1[192], h2[R_], land[R_];
    if (tid==0) {
        double n = 8192.0;
        double s = g_sum[b], sq = g_sumsq[b];
        double mean = s / n;
        double var  = (sq - s*s/n) / (n - 1.0);    // unbiased (torch.std)
        float  sd   = sqrtf(fmaxf((float)var, 0.f));
        st[0]=(float)mean; st[1]=sd;
        st[2]=__uint_as_float(g_minb[b]); st[3]=__uint_as_float(g_maxb[b]);
        st[4]=(float)mean*0.5f; st[5]=sd*0.5f;
    }
    __syncthreads();
    if (tid < 192) {
        float a = b1[tid];
#pragma unroll
        for (int i=0;i<6;i++) a += st[i]*w1[i*192+tid];
        h1[tid] = fmaxf(a, 0.f);
    }
    __syncthreads();
    if (tid < R_) {
        float a = b2[tid];
        for (int i=0;i<192;i++) a += h1[i]*w2[i*R_+tid];
        h2[tid] = a;
    }
    __syncthreads();
    if (tid < R_) {
        float a = bd0[tid];
#pragma unroll
        for (int i=0;i<R_;i++) a += h2[i]*wd0[i*R_+tid];
        land[tid] = a;
    }
    __syncthreads();
    float gt = *gate;
    for (int d=tid; d<D_; d+=blockDim.x) {
        float a = topo_b[d];
#pragma unroll
        for (int i=0;i<R_;i++) a += land[i]*topo_w[i*D_+d];
        g_topo[b*D_+d] = gt*a;
    }
}

// softmax over rows of 512, in place; one block (128 thr) per row
__global__ void softmax_k() {
    long r = blockIdx.x;
    float4* p4 = (float4*)(g_scores + r*(long)S_);
    int tid = threadIdx.x, w = tid>>5, l = tid&31;
    __shared__ float red[4];
    float4 v = p4[tid];
    float m = fmaxf(fmaxf(v.x,v.y), fmaxf(v.z,v.w));
#pragma unroll
    for (int o=16;o;o>>=1) m = fmaxf(m, __shfl_xor_sync(0xffffffffu, m, o));
    if (l==0) red[w]=m;
    __syncthreads();
    m = fmaxf(fmaxf(red[0],red[1]), fmaxf(red[2],red[3]));
    __syncthreads();
    v.x = __expf(v.x-m); v.y = __expf(v.y-m); v.z = __expf(v.z-m); v.w = __expf(v.w-m);
    float s = v.x+v.y+v.z+v.w;
#pragma unroll
    for (int o=16;o;o>>=1) s += __shfl_xor_sync(0xffffffffu, s, o);
    if (l==0) red[w]=s;
    __syncthreads();
    s = red[0]+red[1]+red[2]+red[3];
    float inv = __frcp_rn(s);
    v.x*=inv; v.y*=inv; v.z*=inv; v.w*=inv;
    p4[tid] = v;
}

// layernorm over 768: FIRST => t = x + attnP + topo[b]; else t = x1 + ffn2
template<bool FIRST>
__global__ void ln_k(const float* __restrict__ a, const float* __restrict__ br,
                     const float* __restrict__ gamma, const float* __restrict__ beta,
                     float* __restrict__ out) {
    __shared__ float tv[D_];
    __shared__ float red[8];
    long r = blockIdx.x; int tid = threadIdx.x;
    float loc = 0.f;
    for (int d=tid; d<D_; d+=256) {
        float t = a[r*D_+d] + br[r*D_+d];
        if (FIRST) t += g_topo[(r>>9)*D_ + d];
        tv[d] = t; loc += t;
    }
    float mean = blockReduceSum256(loc, red) * (1.f/D_);
    float lv = 0.f;
    for (int d=tid; d<D_; d+=256) { float c = tv[d]-mean; lv += c*c; }
    float var = blockReduceSum256(lv, red) * (1.f/D_);
    float rs = rsqrtf(var + 1e-5f);
    for (int d=tid; d<D_; d+=256)
        out[r*D_+d] = (tv[d]-mean)*rs*gamma[d] + beta[d];
}

// ---------------- host-side symbol helpers ----------------
static float* symaddr(const void* sym) {
    void* p = nullptr;
    cudaGetSymbolAddress(&p, sym);
    return (float*)p;
}

extern "C" void kernel_launch(void* const* d_in, const int* in_sizes, int n_in,
                              void* d_out, int out_size) {
    const float* x        = (const float*)d_in[0];
    const int*   sidx     = (const int*)  d_in[1];
    const float* w1       = (const float*)d_in[2];
    const float* b1       = (const float*)d_in[3];
    const float* w2       = (const float*)d_in[4];
    const float* b2       = (const float*)d_in[5];
    const float* wd0      = (const float*)d_in[6];
    const float* bd0      = (const float*)d_in[7];
    // d_in[8], d_in[9] = wd1, bd1 (unused by reference)
    const float* in_w     = (const float*)d_in[10];
    const float* in_b     = (const float*)d_in[11];
    const float* out_w    = (const float*)d_in[12];
    const float* out_b    = (const float*)d_in[13];
    const float* topo_w   = (const float*)d_in[14];
    const float* topo_b   = (const float*)d_in[15];
    const float* gate     = (const float*)d_in[16];
    const float* ln1_g    = (const float*)d_in[17];
    const float* ln1_b    = (const float*)d_in[18];
    const float* ln2_g    = (const float*)d_in[19];
    const float* ln2_b    = (const float*)d_in[20];
    const float* ffn_w1   = (const float*)d_in[21];
    const float* ffn_b1   = (const float*)d_in[22];
    const float* ffn_w2   = (const float*)d_in[23];
    const float* ffn_b2   = (const float*)d_in[24];
    float* out = (float*)d_out;

    float* p_xnorm  = symaddr(g_xnorm);
    float* p_sbuf   = symaddr(g_sbuf);
    float* p_dist   = symaddr(g_dist);
    float* p_qkv    = symaddr(g_qkv);
    float* p_scores = symaddr(g_scores);
    float* p_attnO  = symaddr(g_attnO);
    float* p_attnP  = symaddr(g_attnP);
    float* p_x1     = symaddr(g_x1);
    float* p_ffnh   = symaddr(g_ffnh);
    float* p_ffn2   = symaddr(g_ffn2);

    // 1) per-row squared norms + sample gather + batch-stat init
    init_k<<<1,32>>>();
    xnorm_k<<<BS_,256>>>(x);
    gather_k<<<dim3(NS_,B_),192>>>(x, sidx);

    // 2) cdist: dist[b,s,n] = sqrt(|x|^2 + |s|^2 - 2 x.s)   (NT batched GEMM, EPI=3)
    gemm_k<128,128,8,8,8,true,3><<<dim3(1,4,B_),256>>>(
        x, p_sbuf, p_dist, nullptr,
        S_, NS_, D_, D_, D_, NS_,
        1, (long)S_*D_, 0, (long)NS_*D_, 0, (long)S_*NS_, 0,
        0.f, p_xnorm, sidx);

    // 3) top-16 per row + per-batch stats
    topk_stats_k<<<BS_/8,256>>>();

    // 4) stats -> landscape -> gated topo embedding
    mlp_topo_k<<<B_,256>>>(w1,b1,w2,b2,wd0,bd0,topo_w,topo_b,gate);

    // 5) QKV projection: [8192,768]@[768,2304]+bias
    gemm_k<128,128,8,8,8,false,0><<<dim3(3*D_/128, BS_/128, 1),256>>>(
        x, in_w, p_qkv, in_b,
        BS_, 3*D_, D_, D_, 3*D_, 3*D_,
        1, 0,0,0,0,0,0, 0.f, nullptr, nullptr);

    // 6) scores = Q @ K^T / 8  (batched over b,h; NT; EPI=2)
    gemm_k<128,128,8,8,8,true,2><<<dim3(S_/128, S_/128, B_*H_),256>>>(
        p_qkv, p_qkv + D_, p_scores, nullptr,
        S_, S_, HD_, 3*D_, 3*D_, S_,
        H_, (long)S_*3*D_, HD_, (long)S_*3*D_, HD_,
        (long)H_*S_*S_, (long)S_*S_,
        0.125f, nullptr, nullptr);

    // 7) softmax rows
    softmax_k<<<B_*H_*S_,128>>>();

    // 8) O = P @ V  (batched NN, BN=64)
    gemm_k<128,64,8,8,4,false,0><<<dim3(1, S_/128, B_*H_),256>>>(
        p_scores, p_qkv + 2*D_, p_attnO, nullptr,
        S_, HD_, S_, S_, 3*D_, D_,
        H_, (long)H_*S_*S_, (long)S_*S_, (long)S_*3*D_, HD_,
        (long)S_*D_, HD_,
        0.f, nullptr, nullptr);

    // 9) attn projection
    gemm_k<128,128,8,8,8,false,0><<<dim3(D_/128, BS_/128, 1),256>>>(
        p_attnO, out_w, p_attnP, out_b,
        BS_, D_, D_, D_, D_, D_,
        1, 0,0,0,0,0,0, 0.f, nullptr, nullptr);

    // 10) x1 = LN(x + attnP + gate*topo)
    ln_k<true><<<BS_,256>>>(x, p_attnP, ln1_g, ln1_b, p_x1);

    // 11) FFN1 with exact GELU
    gemm_k<128,128,8,8,8,false,1><<<dim3(2*D_/128, BS_/128, 1),256>>>(
        p_x1, ffn_w1, p_ffnh, ffn_b1,
        BS_, 2*D_, D_, D_, 2*D_, 2*D_,
        1, 0,0,0,0,0,0, 0.f, nullptr, nullptr);

    // 12) FFN2
    gemm_k<128,128,8,8,8,false,0><<<dim3(D_/128, BS_/128, 1),256>>>(
        p_ffnh, ffn_w2, p_ffn2, ffn_b2,
        BS_, D_, 2*D_, 2*D_, D_, D_,
        1, 0,0,0,0,0,0, 0.f, nullptr, nullptr);

    // 13) out = LN(x1 + ffn)
    ln_k<false><<<BS_,256>>>(p_x1, p_ffn2, ln2_g, ln2_b, out);
}

// round 4
// speedup vs baseline: 1.8619x; 1.8619x over previous
#include <cuda_runtime.h>
#include <cuda_bf16.h>
#include <float.h>
#include <cstdint>

#define B_   16
#define S_   512
#define D_   768
#define H_   12
#define HD_  64
#define K_   16
#define NS_  128
#define R_   32
#define BS_  (B_*S_)
#define Z_   (B_*H_)

// ================= PTX helpers (baseline sm_80+ features only) =================
__device__ __forceinline__ uint32_t smem_to_u32(const void* p) {
    uint32_t a;
    asm("{ .reg .u64 t; cvta.to.shared.u64 t, %1; cvt.u32.u64 %0, t; }" : "=r"(a) : "l"(p));
    return a;
}
__device__ __forceinline__ void cpa16(uint32_t dst, const void* src) {
    asm volatile("cp.async.ca.shared.global [%0], [%1], 16;" :: "r"(dst), "l"(src));
}
__device__ __forceinline__ void ldsm4(uint32_t* r, uint32_t addr) {
    asm volatile("ldmatrix.sync.aligned.m8n8.x4.shared.b16 {%0,%1,%2,%3}, [%4];"
        : "=r"(r[0]), "=r"(r[1]), "=r"(r[2]), "=r"(r[3]) : "r"(addr));
}
__device__ __forceinline__ void ldsm2(uint32_t* r, uint32_t addr) {
    asm volatile("ldmatrix.sync.aligned.m8n8.x2.shared.b16 {%0,%1}, [%2];"
        : "=r"(r[0]), "=r"(r[1]) : "r"(addr));
}
__device__ __forceinline__ void mma16816(float* c, const uint32_t* a, const uint32_t* b) {
    asm volatile("mma.sync.aligned.m16n8k16.row.col.f32.bf16.bf16.f32 "
        "{%0,%1,%2,%3}, {%4,%5,%6,%7}, {%8,%9}, {%0,%1,%2,%3};"
        : "+f"(c[0]), "+f"(c[1]), "+f"(c[2]), "+f"(c[3])
        : "r"(a[0]), "r"(a[1]), "r"(a[2]), "r"(a[3]), "r"(b[0]), "r"(b[1]));
}
__device__ __forceinline__ void splitf(float v, __nv_bfloat16& h, __nv_bfloat16& l) {
    h = __float2bfloat16(v);
    l = __float2bfloat16(v - __bfloat162float(h));
}

// ================= scratch =================
__device__ float    g_xnorm[BS_];
__device__ double   g_sum[B_], g_sumsq[B_];
__device__ unsigned g_minb[B_], g_maxb[B_];
__device__ float    g_dist[B_*S_*NS_];
__device__ float    g_topo[B_*D_];
__device__ __align__(16) __nv_bfloat16 g_xpack [BS_*2*D_];
__device__ __align__(16) __nv_bfloat16 g_spack [B_*NS_*2*D_];
__device__ __align__(16) __nv_bfloat16 g_qkvpack[(size_t)BS_*6*D_];
__device__ __align__(16) __nv_bfloat16 g_vtpack[(size_t)Z_*HD_*2*S_];
__device__ float    g_scores[(size_t)Z_*S_*S_];
__device__ __align__(16) __nv_bfloat16 g_ppack [(size_t)Z_*S_*2*S_];
__device__ __align__(16) __nv_bfloat16 g_opack [BS_*2*D_];
__device__ float    g_attnP[BS_*D_];
__device__ float    g_x1[BS_*D_];
__device__ __align__(16) __nv_bfloat16 g_x1pack[BS_*2*D_];
__device__ __align__(16) __nv_bfloat16 g_hpack [(size_t)BS_*4*D_];
__device__ float    g_ffn2[BS_*D_];
__device__ __align__(16) __nv_bfloat16 g_wqkvt[3*D_*2*D_];
__device__ __align__(16) __nv_bfloat16 g_woutt[D_*2*D_];
__device__ __align__(16) __nv_bfloat16 g_wf1t [2*D_*2*D_];
__device__ __align__(16) __nv_bfloat16 g_wf2t [D_*4*D_];

// ================= HMMA GEMM =================
// C[128,BN] per block = A[M,K] * B[N,K]^T, bf16 hi/lo split, 3-product fp32 accum.
// A row layout [lda]: hi at [0,Kd), lo at [aHL, aHL+Kd). B likewise with bHL.
// EPI: 0=+bias, 1=gelu(x+bias), 2=*alpha, 3=cdist sqrt. PACKOUT: bf16 hi/lo out.
// 256 threads = 8 warps (2 m x 4 n), warp tile 64 x BN/4, BK=32 (per seg).
template<int BN, int EPI, bool PACKOUT>
__global__ __launch_bounds__(256)
void hgemm(const __nv_bfloat16* __restrict__ A, const __nv_bfloat16* __restrict__ Bm,
           void* __restrict__ Cv, const float* __restrict__ bias,
           int M, int Kd, int lda, int ldb, int ldc, int aHL, int bHL, int cHL,
           int Hdiv, long sAb, long sAh, long sBb, long sBh, long sCb, long sCh,
           float alpha, const float* __restrict__ xn, const int* __restrict__ sidx)
{
    constexpr int NT = BN/32;                  // 8-col n-tiles per warp
    constexpr int NW = BN/4;                   // warp n extent
    constexpr int ABYTES = 128*40*2;           // one A stage (with 16B row pad)
    constexpr int BBYTES = BN*40*2;
    __shared__ __nv_bfloat16 As[2][128*40];
    __shared__ __nv_bfloat16 Bs[2][BN*40];

    const int tid = threadIdx.x, warp = tid>>5, lane = tid&31;
    const int wm = (warp>>2)*64, wn = (warp&3)*NW;
    const int z = blockIdx.z, zb = z/Hdiv, zh = z - zb*Hdiv;
    A  += zb*sAb + zh*sAh;
    Bm += zb*sBb + zh*sBh;
    const int n0 = blockIdx.x*BN, m0 = blockIdx.y*128;
    const uint32_t sa = smem_to_u32(As), sb = smem_to_u32(Bs);

    float acc[4][NT][4];
    #pragma unroll
    for (int i=0;i<4;i++)
        #pragma unroll
        for (int j=0;j<NT;j++)
            #pragma unroll
            for (int q=0;q<4;q++) acc[i][j][q]=0.f;

    const int kch = Kd>>5, nch = 3*kch;

    // prefetch tile 0
    {
        for (int u = tid; u < 512; u += 256) {
            int r = u>>2, c = u&3;
            cpa16(sa + (r*40+c*8)*2, A + (long)(m0+r)*lda + c*8);
        }
        for (int u = tid; u < BN*4; u += 256) {
            int r = u>>2, c = u&3;
            cpa16(sb + (r*40+c*8)*2, Bm + (long)(n0+r)*ldb + c*8);
        }
        asm volatile("cp.async.commit_group;");
    }

    for (int it = 0; it < nch; ++it) {
        const int buf = it&1;
        if (it+1 < nch) {
            int nit = it+1;
            int seg = nit/kch, kc = nit - seg*kch;
            int ao = (seg==2?aHL:0) + (kc<<5);
            int bo = (seg==1?bHL:0) + (kc<<5);
            int nb = buf^1;
            for (int u = tid; u < 512; u += 256) {
                int r = u>>2, c = u&3;
                cpa16(sa + nb*ABYTES + (r*40+c*8)*2, A + (long)(m0+r)*lda + ao + c*8);
            }
            for (int u = tid; u < BN*4; u += 256) {
                int r = u>>2, c = u&3;
                cpa16(sb + nb*BBYTES + (r*40+c*8)*2, Bm + (long)(n0+r)*ldb + bo + c*8);
            }
            asm volatile("cp.async.commit_group;");
            asm volatile("cp.async.wait_group 1;");
        } else {
            asm volatile("cp.async.wait_group 0;");
        }
        __syncthreads();

        const uint32_t sab = sa + buf*ABYTES;
        const uint32_t sbb = sb + buf*BBYTES;
        #pragma unroll
        for (int kk = 0; kk < 32; kk += 16) {
            uint32_t af[4][4], bf[NT][2];
            #pragma unroll
            for (int mt = 0; mt < 4; mt++) {
                int r = wm + mt*16 + (lane&15);
                ldsm4(af[mt], sab + (r*40 + kk + (lane>>4)*8)*2);
            }
            #pragma unroll
            for (int nt = 0; nt < NT; nt++) {
                int r = wn + nt*8 + (lane&7);
                int co = kk + ((lane>>3)&1)*8;
                ldsm2(bf[nt], sbb + (r*40 + co)*2);
            }
            #pragma unroll
            for (int mt = 0; mt < 4; mt++)
                #pragma unroll
                for (int nt = 0; nt < NT; nt++)
                    mma16816(acc[mt][nt], af[mt], bf[nt]);
        }
        __syncthreads();
    }

    // ---- epilogue: direct global stores ----
    float* Cf = (float*)Cv;
    __nv_bfloat16* Cb = (__nv_bfloat16*)Cv;
    const long coff = zb*sCb + zh*sCh;
    #pragma unroll
    for (int mt = 0; mt < 4; mt++) {
        #pragma unroll
        for (int hf = 0; hf < 2; hf++) {
            const int gm = m0 + wm + mt*16 + (lane>>2) + hf*8;
            const float xnr = (EPI==3) ? xn[(long)z*M + gm] : 0.f;
            #pragma unroll
            for (int nt = 0; nt < NT; nt++) {
                const int gn = n0 + wn + nt*8 + (lane&3)*2;
                float v0 = acc[mt][nt][hf*2+0];
                float v1 = acc[mt][nt][hf*2+1];
                if (EPI==0) {
                    if (bias) { v0 += bias[gn]; v1 += bias[gn+1]; }
                } else if (EPI==1) {
                    float t0 = v0 + bias[gn];   v0 = t0 * normcdff(t0);
                    float t1 = v1 + bias[gn+1]; v1 = t1 * normcdff(t1);
                } else if (EPI==2) {
                    v0 *= alpha; v1 *= alpha;
                } else if (EPI==3) {
                    v0 = sqrtf(fmaxf(xnr + xn[(long)z*M + sidx[gn]]   - 2.f*v0, 0.f));
                    v1 = sqrtf(fmaxf(xnr + xn[(long)z*M + sidx[gn+1]] - 2.f*v1, 0.f));
                }
                if (PACKOUT) {
                    __nv_bfloat16 h0,l0,h1,l1;
                    splitf(v0,h0,l0); splitf(v1,h1,l1);
                    __nv_bfloat162 hh; hh.x=h0; hh.y=h1;
                    __nv_bfloat162 ll; ll.x=l0; ll.y=l1;
                    *(__nv_bfloat162*)(Cb + coff + (long)gm*ldc + gn)       = hh;
                    *(__nv_bfloat162*)(Cb + coff + (long)gm*ldc + cHL + gn) = ll;
                } else {
                    float2 st; st.x=v0; st.y=v1;
                    *(float2*)(Cf + coff + (long)gm*ldc + gn) = st;
                }
            }
        }
    }
}

// ================= pack / transform kernels =================
__global__ void xsplit_k(const float* __restrict__ x) {
    long r = blockIdx.x; int t = threadIdx.x;             // 96 thr * 8
    const float* s = x + r*D_ + t*8;
    __nv_bfloat16 h[8], l[8];
    #pragma unroll
    for (int u = 0; u < 8; u++) splitf(s[u], h[u], l[u]);
    __nv_bfloat16* d = g_xpack + r*(2*D_) + t*8;
    *(uint4*)d = *(uint4*)h; *(uint4*)(d + D_) = *(uint4*)l;
}

__global__ void gatherpack_k(const float* __restrict__ x, const int* __restrict__ sidx) {
    int j = blockIdx.x, b = blockIdx.y, t = threadIdx.x;
    const float* s = x + ((long)b*S_ + sidx[j])*D_ + t*8;
    __nv_bfloat16 h[8], l[8];
    #pragma unroll
    for (int u = 0; u < 8; u++) splitf(s[u], h[u], l[u]);
    __nv_bfloat16* d = g_spack + ((long)b*NS_ + j)*(2*D_) + t*8;
    *(uint4*)d = *(uint4*)h; *(uint4*)(d + D_) = *(uint4*)l;
}

__global__ void wsplit_k(const float* __restrict__ W, __nv_bfloat16* __restrict__ Wt, int Kd, int N) {
    __shared__ float t[32][33];
    int n0 = blockIdx.x*32, k0 = blockIdx.y*32;
    int tx = threadIdx.x, ty = threadIdx.y;
    for (int i = ty; i < 32; i += 8) t[i][tx] = W[(long)(k0+i)*N + n0+tx];
    __syncthreads();
    for (int i = ty; i < 32; i += 8) {
        __nv_bfloat16 h, l; splitf(t[tx][i], h, l);
        Wt[(long)(n0+i)*2*Kd + k0+tx] = h;
        Wt[(long)(n0+i)*2*Kd + Kd + k0+tx] = l;
    }
}

__global__ void vtrans_k() {
    __shared__ __nv_bfloat16 t0[32][33], t1[32][33];
    int z = blockIdx.z, b = z/H_, h = z - b*H_;
    int n0 = blockIdx.x*32, s0 = blockIdx.y*32;
    int tx = threadIdx.x, ty = threadIdx.y;
    const __nv_bfloat16* src = g_qkvpack + (long)b*S_*4608 + 2*D_ + h*64;
    for (int i = ty; i < 32; i += 8) {
        t0[i][tx] = src[(long)(s0+i)*4608 + n0+tx];
        t1[i][tx] = src[(long)(s0+i)*4608 + 2304 + n0+tx];
    }
    __syncthreads();
    __nv_bfloat16* dst = g_vtpack + (long)z*HD_*1024;
    for (int i = ty; i < 32; i += 8) {
        dst[(long)(n0+i)*1024 + s0+tx]       = t0[tx][i];
        dst[(long)(n0+i)*1024 + 512 + s0+tx] = t1[tx][i];
    }
}

// ================= misc =================
__device__ __forceinline__ float blockReduceSum256(float v, float* red) {
    #pragma unroll
    for (int o = 16; o; o >>= 1) v += __shfl_xor_sync(0xffffffffu, v, o);
    int w = threadIdx.x>>5, l = threadIdx.x&31;
    if (l==0) red[w] = v;
    __syncthreads();
    float r = (threadIdx.x < 8) ? red[threadIdx.x] : 0.f;
    if (w==0) {
        #pragma unroll
        for (int o = 4; o; o >>= 1) r += __shfl_xor_sync(0xffffffffu, r, o);
        if (l==0) red[0] = r;
    }
    __syncthreads();
    float out = red[0];
    __syncthreads();
    return out;
}

__global__ void init_k() {
    int t = threadIdx.x;
    if (t < B_) { g_sum[t]=0.0; g_sumsq[t]=0.0; g_minb[t]=0x7f7fffffu; g_maxb[t]=0u; }
}

__global__ void xnorm_k(const float* __restrict__ x) {
    __shared__ float red[8];
    long r = blockIdx.x; int tid = threadIdx.x;
    float loc = 0.f;
    for (int d = tid; d < D_; d += 256) { float t = x[r*D_+d]; loc += t*t; }
    float s = blockReduceSum256(loc, red);
    if (tid==0) g_xnorm[r] = s;
}

__global__ void topk_stats_k() {
    int warp = threadIdx.x >> 5, lane = threadIdx.x & 31;
    long row = (long)blockIdx.x*8 + warp;
    const float4* p = (const float4*)(g_dist + row*NS_);
    float4 v4 = p[lane];
    float v[4] = {v4.x, v4.y, v4.z, v4.w};
    float lsum=0.f, lsq=0.f, mn0=0.f, mx15=0.f;
    #pragma unroll
    for (int it = 0; it < K_; ++it) {
        float lv = fminf(fminf(v[0],v[1]), fminf(v[2],v[3]));
        float m = lv;
        #pragma unroll
        for (int o = 16; o; o >>= 1) m = fminf(m, __shfl_xor_sync(0xffffffffu, m, o));
        unsigned bal = __ballot_sync(0xffffffffu, lv==m);
        if (lane == __ffs(bal)-1) {
            if      (v[0]==m) v[0]=FLT_MAX;
            else if (v[1]==m) v[1]=FLT_MAX;
            else if (v[2]==m) v[2]=FLT_MAX;
            else              v[3]=FLT_MAX;
        }
        lsum += m; lsq += m*m;
        if (it==0) mn0 = m;
        mx15 = m;
    }
    if (lane==0) {
        int b = (int)(row >> 9);
        atomicAdd(&g_sum[b], (double)lsum);
        atomicAdd(&g_sumsq[b], (double)lsq);
        atomicMin(&g_minb[b], __float_as_uint(mn0));
        atomicMax(&g_maxb[b], __float_as_uint(mx15));
    }
}

__global__ void mlp_topo_k(const float* __restrict__ w1, const float* __restrict__ b1,
                           const float* __restrict__ w2, const float* __restrict__ b2,
                           const float* __restrict__ wd0, const float* __restrict__ bd0,
                           const float* __restrict__ topo_w, const float* __restrict__ topo_b,
                           const float* __restrict__ gate) {
    int b = blockIdx.x, tid = threadIdx.x;
    __shared__ float st[6], h1[192], h2[R_], land[R_];
    if (tid==0) {
        double n = 8192.0, s = g_sum[b], sq = g_sumsq[b];
        double mean = s / n;
        double var = (sq - s*s/n) / (n - 1.0);
        float sd = sqrtf(fmaxf((float)var, 0.f));
        st[0]=(float)mean; st[1]=sd;
        st[2]=__uint_as_float(g_minb[b]); st[3]=__uint_as_float(g_maxb[b]);
        st[4]=(float)mean*0.5f; st[5]=sd*0.5f;
    }
    __syncthreads();
    if (tid < 192) {
        float a = b1[tid];
        #pragma unroll
        for (int i = 0; i < 6; i++) a += st[i]*w1[i*192+tid];
        h1[tid] = fmaxf(a, 0.f);
    }
    __syncthreads();
    if (tid < R_) {
        float a = b2[tid];
        for (int i = 0; i < 192; i++) a += h1[i]*w2[i*R_+tid];
        h2[tid] = a;
    }
    __syncthreads();
    if (tid < R_) {
        float a = bd0[tid];
        #pragma unroll
        for (int i = 0; i < R_; i++) a += h2[i]*wd0[i*R_+tid];
        land[tid] = a;
    }
    __syncthreads();
    float gt = *gate;
    for (int d = tid; d < D_; d += blockDim.x) {
        float a = topo_b[d];
        #pragma unroll
        for (int i = 0; i < R_; i++) a += land[i]*topo_w[i*D_+d];
        g_topo[b*D_+d] = gt*a;
    }
}

__global__ void softmax_k() {
    long r = blockIdx.x;
    const float4* p4 = (const float4*)(g_scores + r*(long)S_);
    int tid = threadIdx.x, w = tid>>5, l = tid&31;
    __shared__ float red[4];
    float4 v = p4[tid];
    float m = fmaxf(fmaxf(v.x,v.y), fmaxf(v.z,v.w));
    #pragma unroll
    for (int o = 16; o; o >>= 1) m = fmaxf(m, __shfl_xor_sync(0xffffffffu, m, o));
    if (l==0) red[w] = m;
    __syncthreads();
    m = fmaxf(fmaxf(red[0],red[1]), fmaxf(red[2],red[3]));
    __syncthreads();
    v.x = __expf(v.x-m); v.y = __expf(v.y-m); v.z = __expf(v.z-m); v.w = __expf(v.w-m);
    float s = v.x+v.y+v.z+v.w;
    #pragma unroll
    for (int o = 16; o; o >>= 1) s += __shfl_xor_sync(0xffffffffu, s, o);
    if (l==0) red[w] = s;
    __syncthreads();
    s = red[0]+red[1]+red[2]+red[3];
    float inv = __frcp_rn(s);
    __nv_bfloat16 h[4], lo[4];
    splitf(v.x*inv, h[0], lo[0]); splitf(v.y*inv, h[1], lo[1]);
    splitf(v.z*inv, h[2], lo[2]); splitf(v.w*inv, h[3], lo[3]);
    __nv_bfloat16* d = g_ppack + r*1024 + tid*4;
    *(uint2*)d = *(uint2*)h; *(uint2*)(d + 512) = *(uint2*)lo;
}

template<bool FIRST>
__global__ void ln_k(const float* __restrict__ a, const float* __restrict__ br,
                     const float* __restrict__ gamma, const float* __restrict__ beta,
                     float* __restrict__ out, __nv_bfloat16* __restrict__ pack) {
    __shared__ float tv[D_];
    __shared__ float red[8];
    long r = blockIdx.x; int tid = threadIdx.x;
    float loc = 0.f;
    for (int d = tid; d < D_; d += 256) {
        float t = a[r*D_+d] + br[r*D_+d];
        if (FIRST) t += g_topo[(r>>9)*D_ + d];
        tv[d] = t; loc += t;
    }
    float mean = blockReduceSum256(loc, red) * (1.f/D_);
    float lv = 0.f;
    for (int d = tid; d < D_; d += 256) { float c = tv[d]-mean; lv += c*c; }
    float var = blockReduceSum256(lv, red) * (1.f/D_);
    float rs = rsqrtf(var + 1e-5f);
    for (int d = tid; d < D_; d += 256) {
        float o = (tv[d]-mean)*rs*gamma[d] + beta[d];
        out[r*D_+d] = o;
        if (FIRST) { __nv_bfloat16 h, l; splitf(o, h, l); pack[r*(2*D_)+d] = h; pack[r*(2*D_)+D_+d] = l; }
    }
}

// ================= host =================
template<class T> static T* symaddr(const void* sym) {
    void* p = nullptr; cudaGetSymbolAddress(&p, sym); return (T*)p;
}

extern "C" void kernel_launch(void* const* d_in, const int* in_sizes, int n_in,
                              void* d_out, int out_size) {
    const float* x      = (const float*)d_in[0];
    const int*   sidx   = (const int*)  d_in[1];
    const float* w1     = (const float*)d_in[2];
    const float* b1     = (const float*)d_in[3];
    const float* w2     = (const float*)d_in[4];
    const float* b2     = (const float*)d_in[5];
    const float* wd0    = (const float*)d_in[6];
    const float* bd0    = (const float*)d_in[7];
    const float* in_w   = (const float*)d_in[10];
    const float* in_b   = (const float*)d_in[11];
    const float* out_w  = (const float*)d_in[12];
    const float* out_b  = (const float*)d_in[13];
    const float* topo_w = (const float*)d_in[14];
    const float* topo_b = (const float*)d_in[15];
    const float* gate   = (const float*)d_in[16];
    const float* ln1_g  = (const float*)d_in[17];
    const float* ln1_b  = (const float*)d_in[18];
    const float* ln2_g  = (const float*)d_in[19];
    const float* ln2_b  = (const float*)d_in[20];
    const float* ffn_w1 = (const float*)d_in[21];
    const float* ffn_b1 = (const float*)d_in[22];
    const float* ffn_w2 = (const float*)d_in[23];
    const float* ffn_b2 = (const float*)d_in[24];
    float* out = (float*)d_out;

    auto p_xnorm = symaddr<float>(g_xnorm);
    auto p_dist  = symaddr<float>(g_dist);
    auto p_xp    = symaddr<__nv_bfloat16>(g_xpack);
    auto p_sp    = symaddr<__nv_bfloat16>(g_spack);
    auto p_qkvp  = symaddr<__nv_bfloat16>(g_qkvpack);
    auto p_vt    = symaddr<__nv_bfloat16>(g_vtpack);
    auto p_sc    = symaddr<float>(g_scores);
    auto p_pp    = symaddr<__nv_bfloat16>(g_ppack);
    auto p_op    = symaddr<__nv_bfloat16>(g_opack);
    auto p_attnP = symaddr<float>(g_attnP);
    auto p_x1    = symaddr<float>(g_x1);
    auto p_x1p   = symaddr<__nv_bfloat16>(g_x1pack);
    auto p_hp    = symaddr<__nv_bfloat16>(g_hpack);
    auto p_ffn2  = symaddr<float>(g_ffn2);
    auto p_wqkv  = symaddr<__nv_bfloat16>(g_wqkvt);
    auto p_wout  = symaddr<__nv_bfloat16>(g_woutt);
    auto p_wf1   = symaddr<__nv_bfloat16>(g_wf1t);
    auto p_wf2   = symaddr<__nv_bfloat16>(g_wf2t);

    // prep
    init_k<<<1,32>>>();
    xnorm_k<<<BS_,256>>>(x);
    xsplit_k<<<BS_,96>>>(x);
    gatherpack_k<<<dim3(NS_,B_),96>>>(x, sidx);
    wsplit_k<<<dim3(3*D_/32, D_/32), dim3(32,8)>>>(in_w,   p_wqkv, D_,   3*D_);
    wsplit_k<<<dim3(D_/32,   D_/32), dim3(32,8)>>>(out_w,  p_wout, D_,   D_);
    wsplit_k<<<dim3(2*D_/32, D_/32), dim3(32,8)>>>(ffn_w1, p_wf1,  D_,   2*D_);
    wsplit_k<<<dim3(D_/32, 2*D_/32), dim3(32,8)>>>(ffn_w2, p_wf2,  2*D_, D_);

    // cdist -> dist
    hgemm<128,3,false><<<dim3(1,4,B_),256>>>(
        p_xp, p_sp, p_dist, nullptr,
        S_, D_, 2*D_, 2*D_, NS_, D_, D_, 0,
        1, (long)S_*2*D_, 0, (long)NS_*2*D_, 0, (long)S_*NS_, 0,
        0.f, p_xnorm, sidx);
    topk_stats_k<<<BS_/8,256>>>();
    mlp_topo_k<<<B_,256>>>(w1,b1,w2,b2,wd0,bd0,topo_w,topo_b,gate);

    // QKV (packed out)
    hgemm<128,0,true><<<dim3(18,64,1),256>>>(
        p_xp, p_wqkv, p_qkvp, in_b,
        BS_, D_, 2*D_, 2*D_, 6*D_, D_, D_, 3*D_,
        1, 0,0,0,0,0,0, 0.f, nullptr, nullptr);
    vtrans_k<<<dim3(2,16,Z_),dim3(32,8)>>>();

    // scores = QK^T/8
    hgemm<128,2,false><<<dim3(4,4,Z_),256>>>(
        p_qkvp, p_qkvp + D_, p_sc, nullptr,
        S_, HD_, 6*D_, 6*D_, S_, 3*D_, 3*D_, 0,
        H_, (long)S_*6*D_, 64, (long)S_*6*D_, 64,
        (long)H_*S_*S_, (long)S_*S_,
        0.125f, nullptr, nullptr);
    softmax_k<<<Z_*S_,128>>>();

    // O = P V (packed out)
    hgemm<64,0,true><<<dim3(1,4,Z_),256>>>(
        p_pp, p_vt, p_op, nullptr,
        S_, S_, 2*S_, 2*S_, 2*D_, S_, S_, D_,
        H_, (long)H_*S_*2*S_, (long)S_*2*S_, (long)H_*HD_*2*S_, (long)HD_*2*S_,
        (long)S_*2*D_, 64,
        0.f, nullptr, nullptr);

    // attn out projection
    hgemm<128,0,false><<<dim3(6,64,1),256>>>(
        p_op, p_wout, p_attnP, out_b,
        BS_, D_, 2*D_, 2*D_, D_, D_, D_, 0,
        1, 0,0,0,0,0,0, 0.f, nullptr, nullptr);

    ln_k<true><<<BS_,256>>>(x, p_attnP, ln1_g, ln1_b, p_x1, p_x1p);

    // FFN
    hgemm<128,1,true><<<dim3(12,64,1),256>>>(
        p_x1p, p_wf1, p_hp, ffn_b1,
        BS_, D_, 2*D_, 2*D_, 4*D_, D_, D_, 2*D_,
        1, 0,0,0,0,0,0, 0.f, nullptr, nullptr);
    hgemm<128,0,false><<<dim3(6,64,1),256>>>(
        p_hp, p_wf2, p_ffn2, ffn_b2,
        BS_, 2*D_, 4*D_, 4*D_, D_, 2*D_, 2*D_, 0,
        1, 0,0,0,0,0,0, 0.f, nullptr, nullptr);

    ln_k<false><<<BS_,256>>>(p_x1, p_ffn2, ln2_g, ln2_b, out, nullptr);
}

// round 5
// speedup vs baseline: 2.5149x; 1.3507x over previous
#include <cuda_runtime.h>
#include <cuda_fp16.h>
#include <float.h>
#include <cstdint>

#define B_   16
#define S_   512
#define D_   768
#define H_   12
#define HD_  64
#define K_   16
#define NS_  128
#define R_   32
#define BS_  (B_*S_)
#define Z_   (B_*H_)

// ================= PTX helpers (baseline sm_80+ features only) =================
__device__ __forceinline__ uint32_t smem_to_u32(const void* p) {
    uint32_t a;
    asm("{ .reg .u64 t; cvta.to.shared.u64 t, %1; cvt.u32.u64 %0, t; }" : "=r"(a) : "l"(p));
    return a;
}
__device__ __forceinline__ void cpa16(uint32_t dst, const void* src) {
    asm volatile("cp.async.ca.shared.global [%0], [%1], 16;" :: "r"(dst), "l"(src));
}
__device__ __forceinline__ void ldsm4(uint32_t* r, uint32_t addr) {
    asm volatile("ldmatrix.sync.aligned.m8n8.x4.shared.b16 {%0,%1,%2,%3}, [%4];"
        : "=r"(r[0]), "=r"(r[1]), "=r"(r[2]), "=r"(r[3]) : "r"(addr));
}
__device__ __forceinline__ void ldsm2(uint32_t* r, uint32_t addr) {
    asm volatile("ldmatrix.sync.aligned.m8n8.x2.shared.b16 {%0,%1}, [%2];"
        : "=r"(r[0]), "=r"(r[1]) : "r"(addr));
}
__device__ __forceinline__ void mma16816(float* c, const uint32_t* a, const uint32_t* b) {
    asm volatile("mma.sync.aligned.m16n8k16.row.col.f32.f16.f16.f32 "
        "{%0,%1,%2,%3}, {%4,%5,%6,%7}, {%8,%9}, {%0,%1,%2,%3};"
        : "+f"(c[0]), "+f"(c[1]), "+f"(c[2]), "+f"(c[3])
        : "r"(a[0]), "r"(a[1]), "r"(a[2]), "r"(a[3]), "r"(b[0]), "r"(b[1]));
}
__device__ __forceinline__ void splitf(float v, __half& h, __half& l) {
    h = __float2half_rn(v);
    l = __float2half_rn(v - __half2float(h));
}

// ================= scratch =================
__device__ float    g_xnorm[BS_];
__device__ double   g_sum[B_], g_sumsq[B_];
__device__ unsigned g_minb[B_], g_maxb[B_];
__device__ float    g_dist[B_*S_*NS_];
__device__ float    g_topo[B_*D_];
__device__ __align__(16) __half g_xpack [BS_*2*D_];                 // [hi D | lo D]
__device__ __align__(16) __half g_spack [B_*NS_*D_];                // hi only (B side)
__device__ __align__(16) __half g_qkvpack[(size_t)BS_*6*D_];        // [hi 3D | lo 3D]
__device__ __align__(16) __half g_vtpack[(size_t)Z_*HD_*S_];        // V^T hi only
__device__ float    g_scores[(size_t)Z_*S_*S_];
__device__ __align__(16) __half g_ppack [(size_t)Z_*S_*2*S_];       // [hi S | lo S]
__device__ __align__(16) __half g_opack [BS_*2*D_];
__device__ float    g_attnP[BS_*D_];
__device__ float    g_x1[BS_*D_];
__device__ __align__(16) __half g_x1pack[BS_*2*D_];
__device__ __align__(16) __half g_hpack [(size_t)BS_*4*D_];         // [hi 2D | lo 2D]
__device__ float    g_ffn2[BS_*D_];
__device__ __align__(16) __half g_wqkvt[3*D_*D_];                   // hi only, [N][K]
__device__ __align__(16) __half g_woutt[D_*D_];
__device__ __align__(16) __half g_wf1t [2*D_*D_];
__device__ __align__(16) __half g_wf2t [D_*2*D_];

// ================= HMMA GEMM =================
// C[128,BN] per block = A[M,K] * B[N,K]^T.
// A row: hi at [0,Kd), lo at [aHL,aHL+Kd). B row: hi only, ldb stride.
// 2-pass accumulation: ah*bh + al*bh  (dropped term a*bl ~1.6e-4 rel).
// EPI: 0=+bias, 1=gelu(x+bias), 2=*alpha, 3=cdist sqrt. PACKOUT: fp16 hi/lo out.
template<int BN, int EPI, bool PACKOUT>
__global__ __launch_bounds__(256)
void hgemm(const __half* __restrict__ A, const __half* __restrict__ Bm,
           void* __restrict__ Cv, const float* __restrict__ bias,
           int M, int Kd, int lda, int ldb, int ldc, int aHL, int cHL,
           int Hdiv, long sAb, long sAh, long sBb, long sBh, long sCb, long sCh,
           float alpha, const float* __restrict__ xn, const int* __restrict__ sidx)
{
    constexpr int NT = BN/32;
    constexpr int NW = BN/4;
    constexpr int ABYTES = 128*40*2;
    constexpr int BBYTES = BN*40*2;
    __shared__ __half As[2][128*40];
    __shared__ __half Bs[2][BN*40];

    const int tid = threadIdx.x, warp = tid>>5, lane = tid&31;
    const int wm = (warp>>2)*64, wn = (warp&3)*NW;
    const int z = blockIdx.z, zb = z/Hdiv, zh = z - zb*Hdiv;
    A  += zb*sAb + zh*sAh;
    Bm += zb*sBb + zh*sBh;
    const int n0 = blockIdx.x*BN, m0 = blockIdx.y*128;
    const uint32_t sa = smem_to_u32(As), sb = smem_to_u32(Bs);

    float acc[4][NT][4];
    #pragma unroll
    for (int i=0;i<4;i++)
        #pragma unroll
        for (int j=0;j<NT;j++)
            #pragma unroll
            for (int q=0;q<4;q++) acc[i][j][q]=0.f;

    const int kch = Kd>>5, nch = 2*kch;

    // prefetch tile 0
    {
        for (int u = tid; u < 512; u += 256) {
            int r = u>>2, c = u&3;
            cpa16(sa + (r*40+c*8)*2, A + (long)(m0+r)*lda + c*8);
        }
        for (int u = tid; u < BN*4; u += 256) {
            int r = u>>2, c = u&3;
            cpa16(sb + (r*40+c*8)*2, Bm + (long)(n0+r)*ldb + c*8);
        }
        asm volatile("cp.async.commit_group;");
    }

    for (int it = 0; it < nch; ++it) {
        const int buf = it&1;
        if (it+1 < nch) {
            int nit = it+1;
            int seg = nit/kch, kc = nit - seg*kch;
            int ao = (seg ? aHL : 0) + (kc<<5);
            int bo = kc<<5;
            int nb = buf^1;
            for (int u = tid; u < 512; u += 256) {
                int r = u>>2, c = u&3;
                cpa16(sa + nb*ABYTES + (r*40+c*8)*2, A + (long)(m0+r)*lda + ao + c*8);
            }
            for (int u = tid; u < BN*4; u += 256) {
                int r = u>>2, c = u&3;
                cpa16(sb + nb*BBYTES + (r*40+c*8)*2, Bm + (long)(n0+r)*ldb + bo + c*8);
            }
            asm volatile("cp.async.commit_group;");
            asm volatile("cp.async.wait_group 1;");
        } else {
            asm volatile("cp.async.wait_group 0;");
        }
        __syncthreads();

        const uint32_t sab = sa + buf*ABYTES;
        const uint32_t sbb = sb + buf*BBYTES;
        #pragma unroll
        for (int kk = 0; kk < 32; kk += 16) {
            uint32_t af[4][4], bf[NT][2];
            #pragma unroll
            for (int mt = 0; mt < 4; mt++) {
                int r = wm + mt*16 + (lane&15);
                ldsm4(af[mt], sab + (r*40 + kk + (lane>>4)*8)*2);
            }
            #pragma unroll
            for (int nt = 0; nt < NT; nt++) {
                int r = wn + nt*8 + (lane&7);
                int co = kk + ((lane>>3)&1)*8;
                ldsm2(bf[nt], sbb + (r*40 + co)*2);
            }
            #pragma unroll
            for (int mt = 0; mt < 4; mt++)
                #pragma unroll
                for (int nt = 0; nt < NT; nt++)
                    mma16816(acc[mt][nt], af[mt], bf[nt]);
        }
        __syncthreads();
    }

    // ---- epilogue ----
    float* Cf = (float*)Cv;
    __half* Cb = (__half*)Cv;
    const long coff = zb*sCb + zh*sCh;
    #pragma unroll
    for (int mt = 0; mt < 4; mt++) {
        #pragma unroll
        for (int hf = 0; hf < 2; hf++) {
            const int gm = m0 + wm + mt*16 + (lane>>2) + hf*8;
            const float xnr = (EPI==3) ? xn[(long)z*M + gm] : 0.f;
            #pragma unroll
            for (int nt = 0; nt < NT; nt++) {
                const int gn = n0 + wn + nt*8 + (lane&3)*2;
                float v0 = acc[mt][nt][hf*2+0];
                float v1 = acc[mt][nt][hf*2+1];
                if (EPI==0) {
                    if (bias) { v0 += bias[gn]; v1 += bias[gn+1]; }
                } else if (EPI==1) {
                    float t0 = v0 + bias[gn];   v0 = t0 * normcdff(t0);
                    float t1 = v1 + bias[gn+1]; v1 = t1 * normcdff(t1);
                } else if (EPI==2) {
                    v0 *= alpha; v1 *= alpha;
                } else if (EPI==3) {
                    v0 = sqrtf(fmaxf(xnr + xn[(long)z*M + sidx[gn]]   - 2.f*v0, 0.f));
                    v1 = sqrtf(fmaxf(xnr + xn[(long)z*M + sidx[gn+1]] - 2.f*v1, 0.f));
                }
                if (PACKOUT) {
                    __half h0,l0,h1,l1;
                    splitf(v0,h0,l0); splitf(v1,h1,l1);
                    __half2 hh; hh.x=h0; hh.y=h1;
                    __half2 ll; ll.x=l0; ll.y=l1;
                    *(__half2*)(Cb + coff + (long)gm*ldc + gn)       = hh;
                    *(__half2*)(Cb + coff + (long)gm*ldc + cHL + gn) = ll;
                } else {
                    float2 st; st.x=v0; st.y=v1;
                    *(float2*)(Cf + coff + (long)gm*ldc + gn) = st;
                }
            }
        }
    }
}

// ================= pack / transform kernels =================
// fused: split x into fp16 hi/lo AND compute |x|^2 per row. 96 threads/row.
__global__ void xsplit_k(const float* __restrict__ x) {
    __shared__ float red[3];
    long r = blockIdx.x; int t = threadIdx.x;
    const float* s = x + r*D_ + t*8;
    float f[8];
    *(float4*)(f)   = *(const float4*)(s);
    *(float4*)(f+4) = *(const float4*)(s+4);
    __half h[8], l[8];
    float sq = 0.f;
    #pragma unroll
    for (int u = 0; u < 8; u++) { sq += f[u]*f[u]; splitf(f[u], h[u], l[u]); }
    __half* d = g_xpack + r*(2*D_) + t*8;
    *(uint4*)d = *(uint4*)h; *(uint4*)(d + D_) = *(uint4*)l;
    #pragma unroll
    for (int o = 16; o; o >>= 1) sq += __shfl_xor_sync(0xffffffffu, sq, o);
    if ((t&31)==0) red[t>>5] = sq;
    __syncthreads();
    if (t==0) g_xnorm[r] = red[0]+red[1]+red[2];
}

__global__ void gatherpack_k(const float* __restrict__ x, const int* __restrict__ sidx) {
    int j = blockIdx.x, b = blockIdx.y, t = threadIdx.x;
    const float* s = x + ((long)b*S_ + sidx[j])*D_ + t*8;
    __half h[8];
    #pragma unroll
    for (int u = 0; u < 8; u++) h[u] = __float2half_rn(s[u]);
    *(uint4*)(g_spack + ((long)b*NS_ + j)*D_ + t*8) = *(uint4*)h;
}

__global__ void wsplit_k(const float* __restrict__ W, __half* __restrict__ Wt, int Kd, int N) {
    __shared__ float t[32][33];
    int n0 = blockIdx.x*32, k0 = blockIdx.y*32;
    int tx = threadIdx.x, ty = threadIdx.y;
    for (int i = ty; i < 32; i += 8) t[i][tx] = W[(long)(k0+i)*N + n0+tx];
    __syncthreads();
    for (int i = ty; i < 32; i += 8)
        Wt[(long)(n0+i)*Kd + k0+tx] = __float2half_rn(t[tx][i]);
}

__global__ void vtrans_k() {
    __shared__ __half t0[32][33];
    int z = blockIdx.z, b = z/H_, h = z - b*H_;
    int n0 = blockIdx.x*32, s0 = blockIdx.y*32;
    int tx = threadIdx.x, ty = threadIdx.y;
    const __half* src = g_qkvpack + (long)b*S_*4608 + 2*D_ + h*64;
    for (int i = ty; i < 32; i += 8) t0[i][tx] = src[(long)(s0+i)*4608 + n0+tx];
    __syncthreads();
    __half* dst = g_vtpack + (long)z*HD_*S_;
    for (int i = ty; i < 32; i += 8) dst[(long)(n0+i)*S_ + s0+tx] = t0[tx][i];
}

// ================= misc =================
__device__ __forceinline__ float blockReduceSum256(float v, float* red) {
    #pragma unroll
    for (int o = 16; o; o >>= 1) v += __shfl_xor_sync(0xffffffffu, v, o);
    int w = threadIdx.x>>5, l = threadIdx.x&31;
    if (l==0) red[w] = v;
    __syncthreads();
    float r = (threadIdx.x < 8) ? red[threadIdx.x] : 0.f;
    if (w==0) {
        #pragma unroll
        for (int o = 4; o; o >>= 1) r += __shfl_xor_sync(0xffffffffu, r, o);
        if (l==0) red[0] = r;
    }
    __syncthreads();
    float out = red[0];
    __syncthreads();
    return out;
}

__global__ void init_k() {
    int t = threadIdx.x;
    if (t < B_) { g_sum[t]=0.0; g_sumsq[t]=0.0; g_minb[t]=0x7f7fffffu; g_maxb[t]=0u; }
}

__global__ void topk_stats_k() {
    int warp = threadIdx.x >> 5, lane = threadIdx.x & 31;
    long row = (long)blockIdx.x*8 + warp;
    const float4* p = (const float4*)(g_dist + row*NS_);
    float4 v4 = p[lane];
    float v[4] = {v4.x, v4.y, v4.z, v4.w};
    float lsum=0.f, lsq=0.f, mn0=0.f, mx15=0.f;
    #pragma unroll
    for (int it = 0; it < K_; ++it) {
        float lv = fminf(fminf(v[0],v[1]), fminf(v[2],v[3]));
        float m = lv;
        #pragma unroll
        for (int o = 16; o; o >>= 1) m = fminf(m, __shfl_xor_sync(0xffffffffu, m, o));
        unsigned bal = __ballot_sync(0xffffffffu, lv==m);
        if (lane == __ffs(bal)-1) {
            if      (v[0]==m) v[0]=FLT_MAX;
            else if (v[1]==m) v[1]=FLT_MAX;
            else if (v[2]==m) v[2]=FLT_MAX;
            else              v[3]=FLT_MAX;
        }
        lsum += m; lsq += m*m;
        if (it==0) mn0 = m;
        mx15 = m;
    }
    if (lane==0) {
        int b = (int)(row >> 9);
        atomicAdd(&g_sum[b], (double)lsum);
        atomicAdd(&g_sumsq[b], (double)lsq);
        atomicMin(&g_minb[b], __float_as_uint(mn0));
        atomicMax(&g_maxb[b], __float_as_uint(mx15));
    }
}

__global__ void mlp_topo_k(const float* __restrict__ w1, const float* __restrict__ b1,
                           const float* __restrict__ w2, const float* __restrict__ b2,
                           const float* __restrict__ wd0, const float* __restrict__ bd0,
                           const float* __restrict__ topo_w, const float* __restrict__ topo_b,
                           const float* __restrict__ gate) {
    int b = blockIdx.x, tid = threadIdx.x;
    __shared__ float st[6], h1[192], h2[R_], land[R_];
    if (tid==0) {
        double n = 8192.0, s = g_sum[b], sq = g_sumsq[b];
        double mean = s / n;
        double var = (sq - s*s/n) / (n - 1.0);
        float sd = sqrtf(fmaxf((float)var, 0.f));
        st[0]=(float)mean; st[1]=sd;
        st[2]=__uint_as_float(g_minb[b]); st[3]=__uint_as_float(g_maxb[b]);
        st[4]=(float)mean*0.5f; st[5]=sd*0.5f;
    }
    __syncthreads();
    if (tid < 192) {
        float a = b1[tid];
        #pragma unroll
        for (int i = 0; i < 6; i++) a += st[i]*w1[i*192+tid];
        h1[tid] = fmaxf(a, 0.f);
    }
    __syncthreads();
    if (tid < R_) {
        float a = b2[tid];
        for (int i = 0; i < 192; i++) a += h1[i]*w2[i*R_+tid];
        h2[tid] = a;
    }
    __syncthreads();
    if (tid < R_) {
        float a = bd0[tid];
        #pragma unroll
        for (int i = 0; i < R_; i++) a += h2[i]*wd0[i*R_+tid];
        land[tid] = a;
    }
    __syncthreads();
    float gt = *gate;
    for (int d = tid; d < D_; d += blockDim.x) {
        float a = topo_b[d];
        #pragma unroll
        for (int i = 0; i < R_; i++) a += land[i]*topo_w[i*D_+d];
        g_topo[b*D_+d] = gt*a;
    }
}

__global__ void softmax_k() {
    long r = blockIdx.x;
    const float4* p4 = (const float4*)(g_scores + r*(long)S_);
    int tid = threadIdx.x, w = tid>>5, l = tid&31;
    __shared__ float red[4];
    float4 v = p4[tid];
    float m = fmaxf(fmaxf(v.x,v.y), fmaxf(v.z,v.w));
    #pragma unroll
    for (int o = 16; o; o >>= 1) m = fmaxf(m, __shfl_xor_sync(0xffffffffu, m, o));
    if (l==0) red[w] = m;
    __syncthreads();
    m = fmaxf(fmaxf(red[0],red[1]), fmaxf(red[2],red[3]));
    __syncthreads();
    v.x = __expf(v.x-m); v.y = __expf(v.y-m); v.z = __expf(v.z-m); v.w = __expf(v.w-m);
    float s = v.x+v.y+v.z+v.w;
    #pragma unroll
    for (int o = 16; o; o >>= 1) s += __shfl_xor_sync(0xffffffffu, s, o);
    if (l==0) red[w] = s;
    __syncthreads();
    s = red[0]+red[1]+red[2]+red[3];
    float inv = __frcp_rn(s);
    __half h[4], lo[4];
    splitf(v.x*inv, h[0], lo[0]); splitf(v.y*inv, h[1], lo[1]);
    splitf(v.z*inv, h[2], lo[2]); splitf(v.w*inv, h[3], lo[3]);
    __half* d = g_ppack + r*1024 + tid*4;
    *(uint2*)d = *(uint2*)h; *(uint2*)(d + 512) = *(uint2*)lo;
}

template<bool FIRST>
__global__ void ln_k(const float* __restrict__ a, const float* __restrict__ br,
                     const float* __restrict__ gamma, const float* __restrict__ beta,
                     float* __restrict__ out, __half* __restrict__ pack) {
    __shared__ float tv[D_];
    __shared__ float red[8];
    long r = blockIdx.x; int tid = threadIdx.x;
    float loc = 0.f;
    for (int d = tid; d < D_; d += 256) {
        float t = a[r*D_+d] + br[r*D_+d];
        if (FIRST) t += g_topo[(r>>9)*D_ + d];
        tv[d] = t; loc += t;
    }
    float mean = blockReduceSum256(loc, red) * (1.f/D_);
    float lv = 0.f;
    for (int d = tid; d < D_; d += 256) { float c = tv[d]-mean; lv += c*c; }
    float var = blockReduceSum256(lv, red) * (1.f/D_);
    float rs = rsqrtf(var + 1e-5f);
    for (int d = tid; d < D_; d += 256) {
        float o = (tv[d]-mean)*rs*gamma[d] + beta[d];
        out[r*D_+d] = o;
        if (FIRST) { __half h, l; splitf(o, h, l); pack[r*(2*D_)+d] = h; pack[r*(2*D_)+D_+d] = l; }
    }
}

// ================= host =================
template<class T> static T* symaddr(const void* sym) {
    void* p = nullptr; cudaGetSymbolAddress(&p, sym); return (T*)p;
}

extern "C" void kernel_launch(void* const* d_in, const int* in_sizes, int n_in,
                              void* d_out, int out_size) {
    const float* x      = (const float*)d_in[0];
    const int*   sidx   = (const int*)  d_in[1];
    const float* w1     = (const float*)d_in[2];
    const float* b1     = (const float*)d_in[3];
    const float* w2     = (const float*)d_in[4];
    const float* b2     = (const float*)d_in[5];
    const float* wd0    = (const float*)d_in[6];
    const float* bd0    = (const float*)d_in[7];
    const float* in_w   = (const float*)d_in[10];
    const float* in_b   = (const float*)d_in[11];
    const float* out_w  = (const float*)d_in[12];
    const float* out_b  = (const float*)d_in[13];
    const float* topo_w = (const float*)d_in[14];
    const float* topo_b = (const float*)d_in[15];
    const float* gate   = (const float*)d_in[16];
    const float* ln1_g  = (const float*)d_in[17];
    const float* ln1_b  = (const float*)d_in[18];
    const float* ln2_g  = (const float*)d_in[19];
    const float* ln2_b  = (const float*)d_in[20];
    const float* ffn_w1 = (const float*)d_in[21];
    const float* ffn_b1 = (const float*)d_in[22];
    const float* ffn_w2 = (const float*)d_in[23];
    const float* ffn_b2 = (const float*)d_in[24];
    float* out = (float*)d_out;

    auto p_xnorm = symaddr<float>(g_xnorm);
    auto p_dist  = symaddr<float>(g_dist);
    auto p_xp    = symaddr<__half>(g_xpack);
    auto p_sp    = symaddr<__half>(g_spack);
    auto p_qkvp  = symaddr<__half>(g_qkvpack);
    auto p_vt    = symaddr<__half>(g_vtpack);
    auto p_sc    = symaddr<float>(g_scores);
    auto p_pp    = symaddr<__half>(g_ppack);
    auto p_op    = symaddr<__half>(g_opack);
    auto p_attnP = symaddr<float>(g_attnP);
    auto p_x1    = symaddr<float>(g_x1);
    auto p_x1p   = symaddr<__half>(g_x1pack);
    auto p_hp    = symaddr<__half>(g_hpack);
    auto p_ffn2  = symaddr<float>(g_ffn2);
    auto p_wqkv  = symaddr<__half>(g_wqkvt);
    auto p_wout  = symaddr<__half>(g_woutt);
    auto p_wf1   = symaddr<__half>(g_wf1t);
    auto p_wf2   = symaddr<__half>(g_wf2t);

    // prep
    init_k<<<1,32>>>();
    xsplit_k<<<BS_,96>>>(x);
    gatherpack_k<<<dim3(NS_,B_),96>>>(x, sidx);
    wsplit_k<<<dim3(3*D_/32, D_/32), dim3(32,8)>>>(in_w,   p_wqkv, D_,   3*D_);
    wsplit_k<<<dim3(D_/32,   D_/32), dim3(32,8)>>>(out_w,  p_wout, D_,   D_);
    wsplit_k<<<dim3(2*D_/32, D_/32), dim3(32,8)>>>(ffn_w1, p_wf1,  D_,   2*D_);
    wsplit_k<<<dim3(D_/32, 2*D_/32), dim3(32,8)>>>(ffn_w2, p_wf2,  2*D_, D_);

    // cdist -> dist
    hgemm<128,3,false><<<dim3(1,4,B_),256>>>(
        p_xp, p_sp, p_dist, nullptr,
        S_, D_, 2*D_, D_, NS_, D_, 0,
        1, (long)S_*2*D_, 0, (long)NS_*D_, 0, (long)S_*NS_, 0,
        0.f, p_xnorm, sidx);
    topk_stats_k<<<BS_/8,256>>>();
    mlp_topo_k<<<B_,256>>>(w1,b1,w2,b2,wd0,bd0,topo_w,topo_b,gate);

    // QKV (packed out)
    hgemm<128,0,true><<<dim3(18,64,1),256>>>(
        p_xp, p_wqkv, p_qkvp, in_b,
        BS_, D_, 2*D_, D_, 6*D_, D_, 3*D_,
        1, 0,0,0,0,0,0, 0.f, nullptr, nullptr);
    vtrans_k<<<dim3(2,16,Z_),dim3(32,8)>>>();

    // scores = QK^T/8  (A=Q hi/lo, B=K hi)
    hgemm<128,2,false><<<dim3(4,4,Z_),256>>>(
        p_qkvp, p_qkvp + D_, p_sc, nullptr,
        S_, HD_, 6*D_, 6*D_, S_, 3*D_, 0,
        H_, (long)S_*6*D_, 64, (long)S_*6*D_, 64,
        (long)H_*S_*S_, (long)S_*S_,
        0.125f, nullptr, nullptr);
    softmax_k<<<Z_*S_,128>>>();

    // O = P V (A=P hi/lo, B=V^T hi)
    hgemm<64,0,true><<<dim3(1,4,Z_),256>>>(
        p_pp, p_vt, p_op, nullptr,
        S_, S_, 2*S_, S_, 2*D_, S_, D_,
        H_, (long)H_*S_*2*S_, (long)S_*2*S_, (long)H_*HD_*S_, (long)HD_*S_,
        (long)S_*2*D_, 64,
        0.f, nullptr, nullptr);

    // attn out projection
    hgemm<128,0,false><<<dim3(6,64,1),256>>>(
        p_op, p_wout, p_attnP, out_b,
        BS_, D_, 2*D_, D_, D_, D_, 0,
        1, 0,0,0,0,0,0, 0.f, nullptr, nullptr);

    ln_k<true><<<BS_,256>>>(x, p_attnP, ln1_g, ln1_b, p_x1, p_x1p);

    // FFN
    hgemm<128,1,true><<<dim3(12,64,1),256>>>(
        p_x1p, p_wf1, p_hp, ffn_b1,
        BS_, D_, 2*D_, D_, 4*D_, D_, 2*D_,
        1, 0,0,0,0,0,0, 0.f, nullptr, nullptr);
    hgemm<128,0,false><<<dim3(6,64,1),256>>>(
        p_hp, p_wf2, p_ffn2, ffn_b2,
        BS_, 2*D_, 4*D_, 2*D_, D_, 2*D_, 0,
        1, 0,0,0,0,0,0, 0.f, nullptr, nullptr);

    ln_k<false><<<BS_,256>>>(p_x1, p_ffn2, ln2_g, ln2_b, out, nullptr);
}

// round 6
// speedup vs baseline: 4.0323x; 1.6034x over previous
#include <cuda_runtime.h>
#include <cuda_fp16.h>
#include <float.h>
#include <cstdint>

#define B_   16
#define S_   512
#define D_   768
#define H_   12
#define HD_  64
#define K_   16
#define NS_  128
#define R_   32
#define BS_  (B_*S_)
#define Z_   (B_*H_)

// ================= PTX helpers =================
__device__ __forceinline__ uint32_t smem_to_u32(const void* p) {
    uint32_t a;
    asm("{ .reg .u64 t; cvta.to.shared.u64 t, %1; cvt.u32.u64 %0, t; }" : "=r"(a) : "l"(p));
    return a;
}
__device__ __forceinline__ void cpa16(uint32_t dst, const void* src) {
    asm volatile("cp.async.ca.shared.global [%0], [%1], 16;" :: "r"(dst), "l"(src));
}
__device__ __forceinline__ void ldsm4(uint32_t* r, uint32_t addr) {
    asm volatile("ldmatrix.sync.aligned.m8n8.x4.shared.b16 {%0,%1,%2,%3}, [%4];"
        : "=r"(r[0]), "=r"(r[1]), "=r"(r[2]), "=r"(r[3]) : "r"(addr));
}
__device__ __forceinline__ void ldsm2(uint32_t* r, uint32_t addr) {
    asm volatile("ldmatrix.sync.aligned.m8n8.x2.shared.b16 {%0,%1}, [%2];"
        : "=r"(r[0]), "=r"(r[1]) : "r"(addr));
}
__device__ __forceinline__ void mma16816(float* c, const uint32_t* a, const uint32_t* b) {
    asm volatile("mma.sync.aligned.m16n8k16.row.col.f32.f16.f16.f32 "
        "{%0,%1,%2,%3}, {%4,%5,%6,%7}, {%8,%9}, {%0,%1,%2,%3};"
        : "+f"(c[0]), "+f"(c[1]), "+f"(c[2]), "+f"(c[3])
        : "r"(a[0]), "r"(a[1]), "r"(a[2]), "r"(a[3]), "r"(b[0]), "r"(b[1]));
}

// ================= scratch =================
__device__ float    g_xnorm[BS_];
__device__ double   g_sum[B_], g_sumsq[B_];
__device__ unsigned g_minb[B_], g_maxb[B_];
__device__ float    g_dist[B_*S_*NS_];
__device__ float    g_topo[B_*D_];
__device__ __align__(16) __half g_xpack [BS_*D_];
__device__ __align__(16) __half g_spack [B_*NS_*D_];
__device__ __align__(16) __half g_qkvpack[(size_t)BS_*3*D_];
__device__ __align__(16) __half g_vtpack[(size_t)Z_*HD_*S_];
__device__ float    g_scores[(size_t)Z_*S_*S_];
__device__ __align__(16) __half g_ppack [(size_t)Z_*S_*S_];
__device__ __align__(16) __half g_opack [BS_*D_];
__device__ float    g_attnP[BS_*D_];
__device__ float    g_x1[BS_*D_];
__device__ __align__(16) __half g_x1pack[BS_*D_];
__device__ __align__(16) __half g_hpack [(size_t)BS_*2*D_];
__device__ float    g_ffn2[BS_*D_];
__device__ __align__(16) __half g_wqkvt[3*D_*D_];
__device__ __align__(16) __half g_woutt[D_*D_];
__device__ __align__(16) __half g_wf1t [2*D_*D_];
__device__ __align__(16) __half g_wf2t [D_*2*D_];

// ================= HMMA GEMM (pure fp16, 1 pass) =================
// C[128,BN] per block = A[M,K] * B[N,K]^T.
// EPI: 0=+bias, 1=gelu(x+bias), 2=*alpha, 3=cdist sqrt. PACKOUT: fp16 out.
template<int BN, int EPI, bool PACKOUT>
__global__ __launch_bounds__(256)
void hgemm(const __half* __restrict__ A, const __half* __restrict__ Bm,
           void* __restrict__ Cv, const float* __restrict__ bias,
           int M, int Kd, int lda, int ldb, int ldc,
           int Hdiv, long sAb, long sAh, long sBb, long sBh, long sCb, long sCh,
           float alpha, const float* __restrict__ xn, const int* __restrict__ sidx)
{
    constexpr int NT = BN/32;
    constexpr int NW = BN/4;
    constexpr int ABYTES = 128*40*2;
    constexpr int BBYTES = BN*40*2;
    __shared__ __half As[2][128*40];
    __shared__ __half Bs[2][BN*40];

    const int tid = threadIdx.x, warp = tid>>5, lane = tid&31;
    const int wm = (warp>>2)*64, wn = (warp&3)*NW;
    const int z = blockIdx.z, zb = z/Hdiv, zh = z - zb*Hdiv;
    A  += zb*sAb + zh*sAh;
    Bm += zb*sBb + zh*sBh;
    const int n0 = blockIdx.x*BN, m0 = blockIdx.y*128;
    const uint32_t sa = smem_to_u32(As), sb = smem_to_u32(Bs);

    float acc[4][NT][4];
    #pragma unroll
    for (int i=0;i<4;i++)
        #pragma unroll
        for (int j=0;j<NT;j++)
            #pragma unroll
            for (int q=0;q<4;q++) acc[i][j][q]=0.f;

    const int nch = Kd>>5;

    // prefetch tile 0
    {
        for (int u = tid; u < 512; u += 256) {
            int r = u>>2, c = u&3;
            cpa16(sa + (r*40+c*8)*2, A + (long)(m0+r)*lda + c*8);
        }
        for (int u = tid; u < BN*4; u += 256) {
            int r = u>>2, c = u&3;
            cpa16(sb + (r*40+c*8)*2, Bm + (long)(n0+r)*ldb + c*8);
        }
        asm volatile("cp.async.commit_group;");
    }

    for (int it = 0; it < nch; ++it) {
        const int buf = it&1;
        if (it+1 < nch) {
            int ko = (it+1)<<5;
            int nb = buf^1;
            for (int u = tid; u < 512; u += 256) {
                int r = u>>2, c = u&3;
                cpa16(sa + nb*ABYTES + (r*40+c*8)*2, A + (long)(m0+r)*lda + ko + c*8);
            }
            for (int u = tid; u < BN*4; u += 256) {
                int r = u>>2, c = u&3;
                cpa16(sb + nb*BBYTES + (r*40+c*8)*2, Bm + (long)(n0+r)*ldb + ko + c*8);
            }
            asm volatile("cp.async.commit_group;");
            asm volatile("cp.async.wait_group 1;");
        } else {
            asm volatile("cp.async.wait_group 0;");
        }
        __syncthreads();

        const uint32_t sab = sa + buf*ABYTES;
        const uint32_t sbb = sb + buf*BBYTES;
        #pragma unroll
        for (int kk = 0; kk < 32; kk += 16) {
            uint32_t af[4][4], bf[NT][2];
            #pragma unroll
            for (int mt = 0; mt < 4; mt++) {
                int r = wm + mt*16 + (lane&15);
                ldsm4(af[mt], sab + (r*40 + kk + (lane>>4)*8)*2);
            }
            #pragma unroll
            for (int nt = 0; nt < NT; nt++) {
                int r = wn + nt*8 + (lane&7);
                int co = kk + ((lane>>3)&1)*8;
                ldsm2(bf[nt], sbb + (r*40 + co)*2);
            }
            #pragma unroll
            for (int mt = 0; mt < 4; mt++)
                #pragma unroll
                for (int nt = 0; nt < NT; nt++)
                    mma16816(acc[mt][nt], af[mt], bf[nt]);
        }
        __syncthreads();
    }

    // ---- epilogue ----
    float* Cf = (float*)Cv;
    __half* Cb = (__half*)Cv;
    const long coff = zb*sCb + zh*sCh;
    #pragma unroll
    for (int mt = 0; mt < 4; mt++) {
        #pragma unroll
        for (int hf = 0; hf < 2; hf++) {
            const int gm = m0 + wm + mt*16 + (lane>>2) + hf*8;
            const float xnr = (EPI==3) ? xn[(long)z*M + gm] : 0.f;
            #pragma unroll
            for (int nt = 0; nt < NT; nt++) {
                const int gn = n0 + wn + nt*8 + (lane&3)*2;
                float v0 = acc[mt][nt][hf*2+0];
                float v1 = acc[mt][nt][hf*2+1];
                if (EPI==0) {
                    if (bias) { v0 += bias[gn]; v1 += bias[gn+1]; }
                } else if (EPI==1) {
                    float t0 = v0 + bias[gn];   v0 = t0 * normcdff(t0);
                    float t1 = v1 + bias[gn+1]; v1 = t1 * normcdff(t1);
                } else if (EPI==2) {
                    v0 *= alpha; v1 *= alpha;
                } else if (EPI==3) {
                    v0 = sqrtf(fmaxf(xnr + xn[(long)z*M + sidx[gn]]   - 2.f*v0, 0.f));
                    v1 = sqrtf(fmaxf(xnr + xn[(long)z*M + sidx[gn+1]] - 2.f*v1, 0.f));
                }
                if (PACKOUT) {
                    __half2 hh; hh.x = __float2half_rn(v0); hh.y = __float2half_rn(v1);
                    *(__half2*)(Cb + coff + (long)gm*ldc + gn) = hh;
                } else {
                    float2 st; st.x=v0; st.y=v1;
                    *(float2*)(Cf + coff + (long)gm*ldc + gn) = st;
                }
            }
        }
    }
}

// ================= pack / transform kernels =================
__global__ void xsplit_k(const float* __restrict__ x) {
    __shared__ float red[3];
    long r = blockIdx.x; int t = threadIdx.x;   // 96 threads
    const float* s = x + r*D_ + t*8;
    float f[8];
    *(float4*)(f)   = *(const float4*)(s);
    *(float4*)(f+4) = *(const float4*)(s+4);
    __half h[8];
    float sq = 0.f;
    #pragma unroll
    for (int u = 0; u < 8; u++) { sq += f[u]*f[u]; h[u] = __float2half_rn(f[u]); }
    *(uint4*)(g_xpack + r*D_ + t*8) = *(uint4*)h;
    #pragma unroll
    for (int o = 16; o; o >>= 1) sq += __shfl_xor_sync(0xffffffffu, sq, o);
    if ((t&31)==0) red[t>>5] = sq;
    __syncthreads();
    if (t==0) g_xnorm[r] = red[0]+red[1]+red[2];
}

__global__ void gatherpack_k(const float* __restrict__ x, const int* __restrict__ sidx) {
    int j = blockIdx.x, b = blockIdx.y, t = threadIdx.x;
    const float* s = x + ((long)b*S_ + sidx[j])*D_ + t*8;
    __half h[8];
    #pragma unroll
    for (int u = 0; u < 8; u++) h[u] = __float2half_rn(s[u]);
    *(uint4*)(g_spack + ((long)b*NS_ + j)*D_ + t*8) = *(uint4*)h;
}

__global__ void wsplit_k(const float* __restrict__ W, __half* __restrict__ Wt, int Kd, int N) {
    __shared__ float t[32][33];
    int n0 = blockIdx.x*32, k0 = blockIdx.y*32;
    int tx = threadIdx.x, ty = threadIdx.y;
    for (int i = ty; i < 32; i += 8) t[i][tx] = W[(long)(k0+i)*N + n0+tx];
    __syncthreads();
    for (int i = ty; i < 32; i += 8)
        Wt[(long)(n0+i)*Kd + k0+tx] = __float2half_rn(t[tx][i]);
}

__global__ void vtrans_k() {
    __shared__ __half t0[32][33];
    int z = blockIdx.z, b = z/H_, h = z - b*H_;
    int n0 = blockIdx.x*32, s0 = blockIdx.y*32;
    int tx = threadIdx.x, ty = threadIdx.y;
    const __half* src = g_qkvpack + (long)b*S_*(3*D_) + 2*D_ + h*64;
    for (int i = ty; i < 32; i += 8) t0[i][tx] = src[(long)(s0+i)*(3*D_) + n0+tx];
    __syncthreads();
    __half* dst = g_vtpack + (long)z*HD_*S_;
    for (int i = ty; i < 32; i += 8) dst[(long)(n0+i)*S_ + s0+tx] = t0[tx][i];
}

// ================= misc =================
__device__ __forceinline__ float blockReduceSum256(float v, float* red) {
    #pragma unroll
    for (int o = 16; o; o >>= 1) v += __shfl_xor_sync(0xffffffffu, v, o);
    int w = threadIdx.x>>5, l = threadIdx.x&31;
    if (l==0) red[w] = v;
    __syncthreads();
    float r = (threadIdx.x < 8) ? red[threadIdx.x] : 0.f;
    if (w==0) {
        #pragma unroll
        for (int o = 4; o; o >>= 1) r += __shfl_xor_sync(0xffffffffu, r, o);
        if (l==0) red[0] = r;
    }
    __syncthreads();
    float out = red[0];
    __syncthreads();
    return out;
}

__global__ void init_k() {
    int t = threadIdx.x;
    if (t < B_) { g_sum[t]=0.0; g_sumsq[t]=0.0; g_minb[t]=0x7f7fffffu; g_maxb[t]=0u; }
}

__global__ void topk_stats_k() {
    int warp = threadIdx.x >> 5, lane = threadIdx.x & 31;
    long row = (long)blockIdx.x*8 + warp;
    const float4* p = (const float4*)(g_dist + row*NS_);
    float4 v4 = p[lane];
    float v[4] = {v4.x, v4.y, v4.z, v4.w};
    float lsum=0.f, lsq=0.f, mn0=0.f, mx15=0.f;
    #pragma unroll
    for (int it = 0; it < K_; ++it) {
        float lv = fminf(fminf(v[0],v[1]), fminf(v[2],v[3]));
        float m = lv;
        #pragma unroll
        for (int o = 16; o; o >>= 1) m = fminf(m, __shfl_xor_sync(0xffffffffu, m, o));
        unsigned bal = __ballot_sync(0xffffffffu, lv==m);
        if (lane == __ffs(bal)-1) {
            if      (v[0]==m) v[0]=FLT_MAX;
            else if (v[1]==m) v[1]=FLT_MAX;
            else if (v[2]==m) v[2]=FLT_MAX;
            else              v[3]=FLT_MAX;
        }
        lsum += m; lsq += m*m;
        if (it==0) mn0 = m;
        mx15 = m;
    }
    if (lane==0) {
        int b = (int)(row >> 9);
        atomicAdd(&g_sum[b], (double)lsum);
        atomicAdd(&g_sumsq[b], (double)lsq);
        atomicMin(&g_minb[b], __float_as_uint(mn0));
        atomicMax(&g_maxb[b], __float_as_uint(mx15));
    }
}

__global__ void mlp_topo_k(const float* __restrict__ w1, const float* __restrict__ b1,
                           const float* __restrict__ w2, const float* __restrict__ b2,
                           const float* __restrict__ wd0, const float* __restrict__ bd0,
                           const float* __restrict__ topo_w, const float* __restrict__ topo_b,
                           const float* __restrict__ gate) {
    int b = blockIdx.x, tid = threadIdx.x;
    __shared__ float st[6], h1[192], h2[R_], land[R_];
    if (tid==0) {
        double n = 8192.0, s = g_sum[b], sq = g_sumsq[b];
        double mean = s / n;
        double var = (sq - s*s/n) / (n - 1.0);
        float sd = sqrtf(fmaxf((float)var, 0.f));
        st[0]=(float)mean; st[1]=sd;
        st[2]=__uint_as_float(g_minb[b]); st[3]=__uint_as_float(g_maxb[b]);
        st[4]=(float)mean*0.5f; st[5]=sd*0.5f;
    }
    __syncthreads();
    if (tid < 192) {
        float a = b1[tid];
        #pragma unroll
        for (int i = 0; i < 6; i++) a += st[i]*w1[i*192+tid];
        h1[tid] = fmaxf(a, 0.f);
    }
    __syncthreads();
    if (tid < R_) {
        float a = b2[tid];
        for (int i = 0; i < 192; i++) a += h1[i]*w2[i*R_+tid];
        h2[tid] = a;
    }
    __syncthreads();
    if (tid < R_) {
        float a = bd0[tid];
        #pragma unroll
        for (int i = 0; i < R_; i++) a += h2[i]*wd0[i*R_+tid];
        land[tid] = a;
    }
    __syncthreads();
    float gt = *gate;
    for (int d = tid; d < D_; d += blockDim.x) {
        float a = topo_b[d];
        #pragma unroll
        for (int i = 0; i < R_; i++) a += land[i]*topo_w[i*D_+d];
        g_topo[b*D_+d] = gt*a;
    }
}

__global__ void softmax_k() {
    long r = blockIdx.x;
    const float4* p4 = (const float4*)(g_scores + r*(long)S_);
    int tid = threadIdx.x, w = tid>>5, l = tid&31;
    __shared__ float red[4];
    float4 v = p4[tid];
    float m = fmaxf(fmaxf(v.x,v.y), fmaxf(v.z,v.w));
    #pragma unroll
    for (int o = 16; o; o >>= 1) m = fmaxf(m, __shfl_xor_sync(0xffffffffu, m, o));
    if (l==0) red[w] = m;
    __syncthreads();
    m = fmaxf(fmaxf(red[0],red[1]), fmaxf(red[2],red[3]));
    __syncthreads();
    v.x = __expf(v.x-m); v.y = __expf(v.y-m); v.z = __expf(v.z-m); v.w = __expf(v.w-m);
    float s = v.x+v.y+v.z+v.w;
    #pragma unroll
    for (int o = 16; o; o >>= 1) s += __shfl_xor_sync(0xffffffffu, s, o);
    if (l==0) red[w] = s;
    __syncthreads();
    s = red[0]+red[1]+red[2]+red[3];
    float inv = __frcp_rn(s);
    __half h[4];
    h[0]=__float2half_rn(v.x*inv); h[1]=__float2half_rn(v.y*inv);
    h[2]=__float2half_rn(v.z*inv); h[3]=__float2half_rn(v.w*inv);
    *(uint2*)(g_ppack + r*(long)S_ + tid*4) = *(uint2*)h;
}

template<bool FIRST>
__global__ void ln_k(const float* __restrict__ a, const float* __restrict__ br,
                     const float* __restrict__ gamma, const float* __restrict__ beta,
                     float* __restrict__ out, __half* __restrict__ pack) {
    __shared__ float tv[D_];
    __shared__ float red[8];
    long r = blockIdx.x; int tid = threadIdx.x;
    float loc = 0.f;
    for (int d = tid; d < D_; d += 256) {
        float t = a[r*D_+d] + br[r*D_+d];
        if (FIRST) t += g_topo[(r>>9)*D_ + d];
        tv[d] = t; loc += t;
    }
    float mean = blockReduceSum256(loc, red) * (1.f/D_);
    float lv = 0.f;
    for (int d = tid; d < D_; d += 256) { float c = tv[d]-mean; lv += c*c; }
    float var = blockReduceSum256(lv, red) * (1.f/D_);
    float rs = rsqrtf(var + 1e-5f);
    for (int d = tid; d < D_; d += 256) {
        float o = (tv[d]-mean)*rs*gamma[d] + beta[d];
        out[r*D_+d] = o;
        if (FIRST) pack[r*D_+d] = __float2half_rn(o);
    }
}

// ================= host =================
template<class T> static T* symaddr(const void* sym) {
    void* p = nullptr; cudaGetSymbolAddress(&p, sym); return (T*)p;
}

extern "C" void kernel_launch(void* const* d_in, const int* in_sizes, int n_in,
                              void* d_out, int out_size) {
    const float* x      = (const float*)d_in[0];
    const int*   sidx   = (const int*)  d_in[1];
    const float* w1     = (const float*)d_in[2];
    const float* b1     = (const float*)d_in[3];
    const float* w2     = (const float*)d_in[4];
    const float* b2     = (const float*)d_in[5];
    const float* wd0    = (const float*)d_in[6];
    const float* bd0    = (const float*)d_in[7];
    const float* in_w   = (const float*)d_in[10];
    const float* in_b   = (const float*)d_in[11];
    const float* out_w  = (const float*)d_in[12];
    const float* out_b  = (const float*)d_in[13];
    const float* topo_w = (const float*)d_in[14];
    const float* topo_b = (const float*)d_in[15];
    const float* gate   = (const float*)d_in[16];
    const float* ln1_g  = (const float*)d_in[17];
    const float* ln1_b  = (const float*)d_in[18];
    const float* ln2_g  = (const float*)d_in[19];
    const float* ln2_b  = (const float*)d_in[20];
    const float* ffn_w1 = (const float*)d_in[21];
    const float* ffn_b1 = (const float*)d_in[22];
    const float* ffn_w2 = (const float*)d_in[23];
    const float* ffn_b2 = (const float*)d_in[24];
    float* out = (float*)d_out;

    auto p_xnorm = symaddr<float>(g_xnorm);
    auto p_dist  = symaddr<float>(g_dist);
    auto p_xp    = symaddr<__half>(g_xpack);
    auto p_sp    = symaddr<__half>(g_spack);
    auto p_qkvp  = symaddr<__half>(g_qkvpack);
    auto p_vt    = symaddr<__half>(g_vtpack);
    auto p_sc    = symaddr<float>(g_scores);
    auto p_pp    = symaddr<__half>(g_ppack);
    auto p_op    = symaddr<__half>(g_opack);
    auto p_attnP = symaddr<float>(g_attnP);
    auto p_x1    = symaddr<float>(g_x1);
    auto p_x1p   = symaddr<__half>(g_x1pack);
    auto p_hp    = symaddr<__half>(g_hpack);
    auto p_ffn2  = symaddr<float>(g_ffn2);
    auto p_wqkv  = symaddr<__half>(g_wqkvt);
    auto p_wout  = symaddr<__half>(g_woutt);
    auto p_wf1   = symaddr<__half>(g_wf1t);
    auto p_wf2   = symaddr<__half>(g_wf2t);

    // prep
    init_k<<<1,32>>>();
    xsplit_k<<<BS_,96>>>(x);
    gatherpack_k<<<dim3(NS_,B_),96>>>(x, sidx);
    wsplit_k<<<dim3(3*D_/32, D_/32), dim3(32,8)>>>(in_w,   p_wqkv, D_,   3*D_);
    wsplit_k<<<dim3(D_/32,   D_/32), dim3(32,8)>>>(out_w,  p_wout, D_,   D_);
    wsplit_k<<<dim3(2*D_/32, D_/32), dim3(32,8)>>>(ffn_w1, p_wf1,  D_,   2*D_);
    wsplit_k<<<dim3(D_/32, 2*D_/32), dim3(32,8)>>>(ffn_w2, p_wf2,  2*D_, D_);

    // cdist -> dist
    hgemm<128,3,false><<<dim3(1,4,B_),256>>>(
        p_xp, p_sp, p_dist, nullptr,
        S_, D_, D_, D_, NS_,
        1, (long)S_*D_, 0, (long)NS_*D_, 0, (long)S_*NS_, 0,
        0.f, p_xnorm, sidx);
    topk_stats_k<<<BS_/8,256>>>();
    mlp_topo_k<<<B_,256>>>(w1,b1,w2,b2,wd0,bd0,topo_w,topo_b,gate);

    // QKV (packed fp16 out)
    hgemm<128,0,true><<<dim3(18,64,1),256>>>(
        p_xp, p_wqkv, p_qkvp, in_b,
        BS_, D_, D_, D_, 3*D_,
        1, 0,0,0,0,0,0, 0.f, nullptr, nullptr);
    vtrans_k<<<dim3(2,16,Z_),dim3(32,8)>>>();

    // scores = QK^T/8
    hgemm<128,2,false><<<dim3(4,4,Z_),256>>>(
        p_qkvp, p_qkvp + D_, p_sc, nullptr,
        S_, HD_, 3*D_, 3*D_, S_,
        H_, (long)S_*3*D_, 64, (long)S_*3*D_, 64,
        (long)H_*S_*S_, (long)S_*S_,
        0.125f, nullptr, nullptr);
    softmax_k<<<Z_*S_,128>>>();

    // O = P V (packed fp16 out into [B][S][D] head-interleaved)
    hgemm<64,0,true><<<dim3(1,4,Z_),256>>>(
        p_pp, p_vt, p_op, nullptr,
        S_, S_, S_, S_, D_,
        H_, (long)H_*S_*S_, (long)S_*S_, (long)H_*HD_*S_, (long)HD_*S_,
        (long)S_*D_, 64,
        0.f, nullptr, nullptr);

    // attn out projection
    hgemm<128,0,false><<<dim3(6,64,1),256>>>(
        p_op, p_wout, p_attnP, out_b,
        BS_, D_, D_, D_, D_,
        1, 0,0,0,0,0,0, 0.f, nullptr, nullptr);

    ln_k<true><<<BS_,256>>>(x, p_attnP, ln1_g, ln1_b, p_x1, p_x1p);

    // FFN
    hgemm<128,1,true><<<dim3(12,64,1),256>>>(
        p_x1p, p_wf1, p_hp, ffn_b1,
        BS_, D_, D_, D_, 2*D_,
        1, 0,0,0,0,0,0, 0.f, nullptr, nullptr);
    hgemm<128,0,false><<<dim3(6,64,1),256>>>(
        p_hp, p_wf2, p_ffn2, ffn_b2,
        BS_, 2*D_, 2*D_, 2*D_, D_,
        1, 0,0,0,0,0,0, 0.f, nullptr, nullptr);

    ln_k<false><<<BS_,256>>>(p_x1, p_ffn2, ln2_g, ln2_b, out, nullptr);
}

// round 7
// speedup vs baseline: 5.0328x; 1.2481x over previous
#include <cuda_runtime.h>
#include <cuda_fp16.h>
#include <float.h>
#include <cstdint>

#define B_   16
#define S_   512
#define D_   768
#define H_   12
#define HD_  64
#define K_   16
#define NS_  128
#define R_   32
#define BS_  (B_*S_)
#define Z_   (B_*H_)

// ================= PTX helpers =================
__device__ __forceinline__ uint32_t smem_to_u32(const void* p) {
    uint32_t a;
    asm("{ .reg .u64 t; cvta.to.shared.u64 t, %1; cvt.u32.u64 %0, t; }" : "=r"(a) : "l"(p));
    return a;
}
__device__ __forceinline__ void cpa16(uint32_t dst, const void* src) {
    asm volatile("cp.async.ca.shared.global [%0], [%1], 16;" :: "r"(dst), "l"(src));
}
__device__ __forceinline__ void ldsm4(uint32_t* r, uint32_t addr) {
    asm volatile("ldmatrix.sync.aligned.m8n8.x4.shared.b16 {%0,%1,%2,%3}, [%4];"
        : "=r"(r[0]), "=r"(r[1]), "=r"(r[2]), "=r"(r[3]) : "r"(addr));
}
__device__ __forceinline__ void ldsm2(uint32_t* r, uint32_t addr) {
    asm volatile("ldmatrix.sync.aligned.m8n8.x2.shared.b16 {%0,%1}, [%2];"
        : "=r"(r[0]), "=r"(r[1]) : "r"(addr));
}
__device__ __forceinline__ void ldsm2t(uint32_t* r, uint32_t addr) {
    asm volatile("ldmatrix.sync.aligned.m8n8.x2.trans.shared.b16 {%0,%1}, [%2];"
        : "=r"(r[0]), "=r"(r[1]) : "r"(addr));
}
__device__ __forceinline__ void ldsm4t(uint32_t* r, uint32_t addr) {
    asm volatile("ldmatrix.sync.aligned.m8n8.x4.trans.shared.b16 {%0,%1,%2,%3}, [%4];"
        : "=r"(r[0]), "=r"(r[1]), "=r"(r[2]), "=r"(r[3]) : "r"(addr));
}
__device__ __forceinline__ void mma16816(float* c, const uint32_t* a, const uint32_t* b) {
    asm volatile("mma.sync.aligned.m16n8k16.row.col.f32.f16.f16.f32 "
        "{%0,%1,%2,%3}, {%4,%5,%6,%7}, {%8,%9}, {%0,%1,%2,%3};"
        : "+f"(c[0]), "+f"(c[1]), "+f"(c[2]), "+f"(c[3])
        : "r"(a[0]), "r"(a[1]), "r"(a[2]), "r"(a[3]), "r"(b[0]), "r"(b[1]));
}

// ================= scratch =================
__device__ float    g_xnorm[BS_];
__device__ double   g_sum[B_], g_sumsq[B_];
__device__ unsigned g_minb[B_], g_maxb[B_];
__device__ float    g_dist[B_*S_*NS_];
__device__ float    g_topo[B_*D_];
__device__ __align__(16) __half g_xpack [BS_*D_];
__device__ __align__(16) __half g_spack [B_*NS_*D_];
__device__ __align__(16) __half g_qkvpack[(size_t)BS_*3*D_];
__device__ __align__(16) __half g_opack [BS_*D_];
__device__ float    g_attnP[BS_*D_];
__device__ float    g_x1[BS_*D_];
__device__ __align__(16) __half g_x1pack[BS_*D_];
__device__ __align__(16) __half g_hpack [(size_t)BS_*2*D_];
__device__ float    g_ffn2[BS_*D_];
__device__ __align__(16) __half g_wqkvh[D_*3*D_];     // [K][N] fp16
__device__ __align__(16) __half g_wouth[D_*D_];
__device__ __align__(16) __half g_wf1h [D_*2*D_];
__device__ __align__(16) __half g_wf2h [2*D_*D_];

// ================= HMMA GEMM =================
// C[128,BN] = A[M,K] * B.  BNN=true: B stored [K][N] (NN, ldb=N stride);
// BNN=false: B stored [N][K] (NT). EPI: 0=+bias, 1=gelu, 2=*alpha, 3=cdist.
template<int BN, int EPI, bool PACKOUT, bool BNN>
__global__ __launch_bounds__(256)
void hgemm(const __half* __restrict__ A, const __half* __restrict__ Bm,
           void* __restrict__ Cv, const float* __restrict__ bias,
           int M, int Kd, int lda, int ldb, int ldc,
           int Hdiv, long sAb, long sAh, long sBb, long sBh, long sCb, long sCh,
           float alpha, const float* __restrict__ xn, const int* __restrict__ sidx)
{
    constexpr int NT = BN/32;
    constexpr int NW = BN/4;
    constexpr int AH = 128*40;
    constexpr int BH = BNN ? 32*136 : BN*40;
    __shared__ __half As[2][AH];
    __shared__ __half Bs[2][BH];

    const int tid = threadIdx.x, warp = tid>>5, lane = tid&31;
    const int wm = (warp>>2)*64, wn = (warp&3)*NW;
    const int z = blockIdx.z, zb = z/Hdiv, zh = z - zb*Hdiv;
    A  += zb*sAb + zh*sAh;
    Bm += zb*sBb + zh*sBh;
    const int n0 = blockIdx.x*BN, m0 = blockIdx.y*128;
    const uint32_t sa = smem_to_u32(As), sb = smem_to_u32(Bs);

    float acc[4][NT][4];
    #pragma unroll
    for (int i=0;i<4;i++)
        #pragma unroll
        for (int j=0;j<NT;j++)
            #pragma unroll
            for (int q=0;q<4;q++) acc[i][j][q]=0.f;

    const int nch = Kd>>5;

    auto loadA = [&](int ko, int nb) {
        for (int u = tid; u < 512; u += 256) {
            int r = u>>2, c = u&3;
            cpa16(sa + nb*AH*2 + (r*40+c*8)*2, A + (long)(m0+r)*lda + ko + c*8);
        }
    };
    auto loadB = [&](int ko, int nb) {
        if (BNN) {
            for (int u = tid; u < 32*(BN/8); u += 256) {
                int r = u/(BN/8), c = u%(BN/8);
                cpa16(sb + nb*BH*2 + (r*136+c*8)*2, Bm + (long)(ko+r)*ldb + n0 + c*8);
            }
        } else {
            for (int u = tid; u < BN*4; u += 256) {
                int r = u>>2, c = u&3;
                cpa16(sb + nb*BH*2 + (r*40+c*8)*2, Bm + (long)(n0+r)*ldb + ko + c*8);
            }
        }
    };

    loadA(0,0); loadB(0,0);
    asm volatile("cp.async.commit_group;");

    for (int it = 0; it < nch; ++it) {
        const int buf = it&1;
        if (it+1 < nch) {
            loadA((it+1)<<5, buf^1); loadB((it+1)<<5, buf^1);
            asm volatile("cp.async.commit_group;");
            asm volatile("cp.async.wait_group 1;");
        } else {
            asm volatile("cp.async.wait_group 0;");
        }
        __syncthreads();

        const uint32_t sab = sa + buf*AH*2;
        const uint32_t sbb = sb + buf*BH*2;
        #pragma unroll
        for (int kk = 0; kk < 32; kk += 16) {
            uint32_t af[4][4], bf[NT][2];
            #pragma unroll
            for (int mt = 0; mt < 4; mt++) {
                int r = wm + mt*16 + (lane&15);
                ldsm4(af[mt], sab + (r*40 + kk + (lane>>4)*8)*2);
            }
            #pragma unroll
            for (int nt = 0; nt < NT; nt++) {
                if (BNN) {
                    ldsm2t(bf[nt], sbb + ((kk + (lane&15))*136 + wn + nt*8)*2);
                } else {
                    int r = wn + nt*8 + (lane&7);
                    int co = kk + ((lane>>3)&1)*8;
                    ldsm2(bf[nt], sbb + (r*40 + co)*2);
                }
            }
            #pragma unroll
            for (int mt = 0; mt < 4; mt++)
                #pragma unroll
                for (int nt = 0; nt < NT; nt++)
                    mma16816(acc[mt][nt], af[mt], bf[nt]);
        }
        __syncthreads();
    }

    // ---- epilogue ----
    float* Cf = (float*)Cv;
    __half* Cb = (__half*)Cv;
    const long coff = zb*sCb + zh*sCh;
    #pragma unroll
    for (int mt = 0; mt < 4; mt++) {
        #pragma unroll
        for (int hf = 0; hf < 2; hf++) {
            const int gm = m0 + wm + mt*16 + (lane>>2) + hf*8;
            const float xnr = (EPI==3) ? xn[(long)z*M + gm] : 0.f;
            #pragma unroll
            for (int nt = 0; nt < NT; nt++) {
                const int gn = n0 + wn + nt*8 + (lane&3)*2;
                float v0 = acc[mt][nt][hf*2+0];
                float v1 = acc[mt][nt][hf*2+1];
                if (EPI==0) {
                    if (bias) { v0 += bias[gn]; v1 += bias[gn+1]; }
                } else if (EPI==1) {
                    float t0 = v0 + bias[gn];   v0 = t0 * normcdff(t0);
                    float t1 = v1 + bias[gn+1]; v1 = t1 * normcdff(t1);
                } else if (EPI==2) {
                    v0 *= alpha; v1 *= alpha;
                } else if (EPI==3) {
                    v0 = sqrtf(fmaxf(xnr + xn[(long)z*M + sidx[gn]]   - 2.f*v0, 0.f));
                    v1 = sqrtf(fmaxf(xnr + xn[(long)z*M + sidx[gn+1]] - 2.f*v1, 0.f));
                }
                if (PACKOUT) {
                    __half2 hh; hh.x = __float2half_rn(v0); hh.y = __float2half_rn(v1);
                    *(__half2*)(Cb + coff + (long)gm*ldc + gn) = hh;
                } else {
                    float2 st; st.x=v0; st.y=v1;
                    *(float2*)(Cf + coff + (long)gm*ldc + gn) = st;
                }
            }
        }
    }
}

// ================= fused flash attention =================
// grid (4 qblocks, Z). 256 thr = 8 warps, warp owns 16 q rows.
__global__ __launch_bounds__(256)
void flash_k(const __half* __restrict__ qkv, __half* __restrict__ opack) {
    extern __shared__ __half fs[];
    constexpr int LD = 72;
    constexpr int TB = 128*LD;
    const int z = blockIdx.y, b = z/H_, h = z - b*H_;
    const int qb = blockIdx.x;
    const int tid = threadIdx.x, warp = tid>>5, lane = tid&31;
    const int g = lane>>2, t = lane&3;
    const int wm = warp*16;

    const __half* qg = qkv + ((long)b*S_ + qb*128)*2304 + h*64;
    const __half* kg = qkv + (long)b*S_*2304 + 768 + h*64;
    const __half* vg = qkv + (long)b*S_*2304 + 1536 + h*64;
    const uint32_t sq = smem_to_u32(fs);
    const uint32_t sk = sq + TB*2;
    const uint32_t sv = sq + 3*TB*2;

    for (int u = tid; u < 1024; u += 256) {
        int r = u>>3, c = u&7;
        cpa16(sq + (r*LD + c*8)*2, qg + (long)r*2304 + c*8);
        cpa16(sk + (r*LD + c*8)*2, kg + (long)r*2304 + c*8);
        cpa16(sv + (r*LD + c*8)*2, vg + (long)r*2304 + c*8);
    }
    asm volatile("cp.async.commit_group;");
    asm volatile("cp.async.wait_group 0;");
    __syncthreads();

    uint32_t qf[4][4];
    #pragma unroll
    for (int kc = 0; kc < 4; kc++) {
        int r = wm + (lane&15);
        ldsm4(qf[kc], sq + (r*LD + kc*16 + (lane>>4)*8)*2);
    }

    float m0 = -1e30f, m1 = -1e30f, l0 = 0.f, l1 = 0.f;
    float oacc[8][4];
    #pragma unroll
    for (int i=0;i<8;i++) { oacc[i][0]=0.f; oacc[i][1]=0.f; oacc[i][2]=0.f; oacc[i][3]=0.f; }

    for (int kb = 0; kb < 4; ++kb) {
        const int buf = kb&1;
        if (kb) {
            asm volatile("cp.async.wait_group 0;");
            __syncthreads();
        }
        if (kb < 3) {
            const __half* kn = kg + (long)(kb+1)*128*2304;
            const __half* vn = vg + (long)(kb+1)*128*2304;
            const uint32_t dk = sk + (buf^1)*TB*2, dv = sv + (buf^1)*TB*2;
            for (int u = tid; u < 1024; u += 256) {
                int r = u>>3, c = u&7;
                cpa16(dk + (r*LD+c*8)*2, kn + (long)r*2304 + c*8);
                cpa16(dv + (r*LD+c*8)*2, vn + (long)r*2304 + c*8);
            }
            asm volatile("cp.async.commit_group;");
        }
        const uint32_t skb = sk + buf*TB*2, svb = sv + buf*TB*2;

        // S = Q K^T  (16 rows x 128 keys per warp)
        float sacc[16][4];
        #pragma unroll
        for (int i=0;i<16;i++) { sacc[i][0]=0.f; sacc[i][1]=0.f; sacc[i][2]=0.f; sacc[i][3]=0.f; }
        #pragma unroll
        for (int kc = 0; kc < 4; kc++) {
            #pragma unroll
            for (int ntp = 0; ntp < 8; ntp++) {
                uint32_t b4[4];
                int r = ntp*16 + (lane&7) + ((lane>>4)&1)*8;
                int co = kc*16 + ((lane>>3)&1)*8;
                ldsm4(b4, skb + (r*LD + co)*2);
                mma16816(sacc[2*ntp],   qf[kc], b4);
                mma16816(sacc[2*ntp+1], qf[kc], b4+2);
            }
        }
        // scale + online softmax
        float mx0 = -1e30f, mx1 = -1e30f;
        #pragma unroll
        for (int nt=0;nt<16;nt++) {
            sacc[nt][0]*=0.125f; sacc[nt][1]*=0.125f; sacc[nt][2]*=0.125f; sacc[nt][3]*=0.125f;
            mx0 = fmaxf(mx0, fmaxf(sacc[nt][0], sacc[nt][1]));
            mx1 = fmaxf(mx1, fmaxf(sacc[nt][2], sacc[nt][3]));
        }
        mx0 = fmaxf(mx0, __shfl_xor_sync(0xffffffffu, mx0, 1));
        mx0 = fmaxf(mx0, __shfl_xor_sync(0xffffffffu, mx0, 2));
        mx1 = fmaxf(mx1, __shfl_xor_sync(0xffffffffu, mx1, 1));
        mx1 = fmaxf(mx1, __shfl_xor_sync(0xffffffffu, mx1, 2));
        const float mn0 = fmaxf(m0, mx0), mn1 = fmaxf(m1, mx1);
        const float c0 = __expf(m0 - mn0), c1 = __expf(m1 - mn1);
        m0 = mn0; m1 = mn1;
        float rs0 = 0.f, rs1 = 0.f;
        uint32_t ph0[16], ph1[16];
        #pragma unroll
        for (int nt=0;nt<16;nt++) {
            float e0 = __expf(sacc[nt][0]-mn0), e1 = __expf(sacc[nt][1]-mn0);
            float e2 = __expf(sacc[nt][2]-mn1), e3 = __expf(sacc[nt][3]-mn1);
            rs0 += e0+e1; rs1 += e2+e3;
            __half2 p0 = __floats2half2_rn(e0,e1); ph0[nt] = *(uint32_t*)&p0;
            __half2 p1 = __floats2half2_rn(e2,e3); ph1[nt] = *(uint32_t*)&p1;
        }
        rs0 += __shfl_xor_sync(0xffffffffu, rs0, 1);
        rs0 += __shfl_xor_sync(0xffffffffu, rs0, 2);
        rs1 += __shfl_xor_sync(0xffffffffu, rs1, 1);
        rs1 += __shfl_xor_sync(0xffffffffu, rs1, 2);
        l0 = l0*c0 + rs0; l1 = l1*c1 + rs1;
        #pragma unroll
        for (int i=0;i<8;i++) { oacc[i][0]*=c0; oacc[i][1]*=c0; oacc[i][2]*=c1; oacc[i][3]*=c1; }

        // O += P V
        #pragma unroll
        for (int kc = 0; kc < 8; kc++) {
            uint32_t a[4] = { ph0[2*kc], ph1[2*kc], ph0[2*kc+1], ph1[2*kc+1] };
            #pragma unroll
            for (int ntp = 0; ntp < 4; ntp++) {
                uint32_t b4[4];
                int r = kc*16 + (lane&15);
                int co = ntp*16 + (lane>>4)*8;
                ldsm4t(b4, svb + (r*LD + co)*2);
                mma16816(oacc[2*ntp],   a, b4);
                mma16816(oacc[2*ntp+1], a, b4+2);
            }
        }
        __syncthreads();
    }

    const float i0 = 1.0f/l0, i1 = 1.0f/l1;
    __half* o0 = opack + ((long)b*S_ + qb*128 + wm + g)*768 + h*64;
    __half* o1 = o0 + 8*768;
    #pragma unroll
    for (int nt = 0; nt < 8; nt++) {
        __half2 h0 = __floats2half2_rn(oacc[nt][0]*i0, oacc[nt][1]*i0);
        __half2 h1 = __floats2half2_rn(oacc[nt][2]*i1, oacc[nt][3]*i1);
        *(__half2*)(o0 + nt*8 + 2*t) = h0;
        *(__half2*)(o1 + nt*8 + 2*t) = h1;
    }
}

// ================= pack / transform =================
__global__ void xsplit_k(const float* __restrict__ x) {
    __shared__ float red[3];
    long r = blockIdx.x; int t = threadIdx.x;   // 96 threads
    const float* s = x + r*D_ + t*8;
    float f[8];
    *(float4*)(f)   = *(const float4*)(s);
    *(float4*)(f+4) = *(const float4*)(s+4);
    __half h[8];
    float sq = 0.f;
    #pragma unroll
    for (int u = 0; u < 8; u++) { sq += f[u]*f[u]; h[u] = __float2half_rn(f[u]); }
    *(uint4*)(g_xpack + r*D_ + t*8) = *(uint4*)h;
    #pragma unroll
    for (int o = 16; o; o >>= 1) sq += __shfl_xor_sync(0xffffffffu, sq, o);
    if ((t&31)==0) red[t>>5] = sq;
    __syncthreads();
    if (t==0) g_xnorm[r] = red[0]+red[1]+red[2];
}

__global__ void gatherpack_k(const float* __restrict__ x, const int* __restrict__ sidx) {
    int j = blockIdx.x, b = blockIdx.y, t = threadIdx.x;
    const float* s = x + ((long)b*S_ + sidx[j])*D_ + t*8;
    __half h[8];
    #pragma unroll
    for (int u = 0; u < 8; u++) h[u] = __float2half_rn(s[u]);
    *(uint4*)(g_spack + ((long)b*NS_ + j)*D_ + t*8) = *(uint4*)h;
}

__global__ void wconv_k(const float* __restrict__ W, __half* __restrict__ Wh) {
    long i = ((long)blockIdx.x*256 + threadIdx.x)*8;
    float f[8];
    *(float4*)(f)   = *(const float4*)(W+i);
    *(float4*)(f+4) = *(const float4*)(W+i+4);
    __half h[8];
    #pragma unroll
    for (int u = 0; u < 8; u++) h[u] = __float2half_rn(f[u]);
    *(uint4*)(Wh + i) = *(uint4*)h;
}

// ================= misc =================
__device__ __forceinline__ float blockReduceSum256(float v, float* red) {
    #pragma unroll
    for (int o = 16; o; o >>= 1) v += __shfl_xor_sync(0xffffffffu, v, o);
    int w = threadIdx.x>>5, l = threadIdx.x&31;
    if (l==0) red[w] = v;
    __syncthreads();
    float r = (threadIdx.x < 8) ? red[threadIdx.x] : 0.f;
    if (w==0) {
        #pragma unroll
        for (int o = 4; o; o >>= 1) r += __shfl_xor_sync(0xffffffffu, r, o);
        if (l==0) red[0] = r;
    }
    __syncthreads();
    float out = red[0];
    __syncthreads();
    return out;
}

__global__ void init_k() {
    int t = threadIdx.x;
    if (t < B_) { g_sum[t]=0.0; g_sumsq[t]=0.0; g_minb[t]=0x7f7fffffu; g_maxb[t]=0u; }
}

__global__ void topk_stats_k() {
    int warp = threadIdx.x >> 5, lane = threadIdx.x & 31;
    long row = (long)blockIdx.x*8 + warp;
    const float4* p = (const float4*)(g_dist + row*NS_);
    float4 v4 = p[lane];
    float v[4] = {v4.x, v4.y, v4.z, v4.w};
    float lsum=0.f, lsq=0.f, mn0=0.f, mx15=0.f;
    #pragma unroll
    for (int it = 0; it < K_; ++it) {
        float lv = fminf(fminf(v[0],v[1]), fminf(v[2],v[3]));
        float m = lv;
        #pragma unroll
        for (int o = 16; o; o >>= 1) m = fminf(m, __shfl_xor_sync(0xffffffffu, m, o));
        unsigned bal = __ballot_sync(0xffffffffu, lv==m);
        if (lane == __ffs(bal)-1) {
            if      (v[0]==m) v[0]=FLT_MAX;
            else if (v[1]==m) v[1]=FLT_MAX;
            else if (v[2]==m) v[2]=FLT_MAX;
            else              v[3]=FLT_MAX;
        }
        lsum += m; lsq += m*m;
        if (it==0) mn0 = m;
        mx15 = m;
    }
    if (lane==0) {
        int b = (int)(row >> 9);
        atomicAdd(&g_sum[b], (double)lsum);
        atomicAdd(&g_sumsq[b], (double)lsq);
        atomicMin(&g_minb[b], __float_as_uint(mn0));
        atomicMax(&g_maxb[b], __float_as_uint(mx15));
    }
}

__global__ void mlp_topo_k(const float* __restrict__ w1, const float* __restrict__ b1,
                           const float* __restrict__ w2, const float* __restrict__ b2,
                           const float* __restrict__ wd0, const float* __restrict__ bd0,
                           const float* __restrict__ topo_w, const float* __restrict__ topo_b,
                           const float* __restrict__ gate) {
    int b = blockIdx.x, tid = threadIdx.x;
    __shared__ float st[6], h1[192], h2[R_], land[R_];
    if (tid==0) {
        double n = 8192.0, s = g_sum[b], sq = g_sumsq[b];
        double mean = s / n;
        double var = (sq - s*s/n) / (n - 1.0);
        float sd = sqrtf(fmaxf((float)var, 0.f));
        st[0]=(float)mean; st[1]=sd;
        st[2]=__uint_as_float(g_minb[b]); st[3]=__uint_as_float(g_maxb[b]);
        st[4]=(float)mean*0.5f; st[5]=sd*0.5f;
    }
    __syncthreads();
    if (tid < 192) {
        float a = b1[tid];
        #pragma unroll
        for (int i = 0; i < 6; i++) a += st[i]*w1[i*192+tid];
        h1[tid] = fmaxf(a, 0.f);
    }
    __syncthreads();
    if (tid < R_) {
        float a = b2[tid];
        for (int i = 0; i < 192; i++) a += h1[i]*w2[i*R_+tid];
        h2[tid] = a;
    }
    __syncthreads();
    if (tid < R_) {
        float a = bd0[tid];
        #pragma unroll
        for (int i = 0; i < R_; i++) a += h2[i]*wd0[i*R_+tid];
        land[tid] = a;
    }
    __syncthreads();
    float gt = *gate;
    for (int d = tid; d < D_; d += blockDim.x) {
        float a = topo_b[d];
        #pragma unroll
        for (int i = 0; i < R_; i++) a += land[i]*topo_w[i*D_+d];
        g_topo[b*D_+d] = gt*a;
    }
}

template<bool FIRST>
__global__ void ln_k(const float* __restrict__ a, const float* __restrict__ br,
                     const float* __restrict__ gamma, const float* __restrict__ beta,
                     float* __restrict__ out, __half* __restrict__ pack) {
    __shared__ float tv[D_];
    __shared__ float red[8];
    long r = blockIdx.x; int tid = threadIdx.x;
    float loc = 0.f;
    for (int d = tid; d < D_; d += 256) {
        float t = a[r*D_+d] + br[r*D_+d];
        if (FIRST) t += g_topo[(r>>9)*D_ + d];
        tv[d] = t; loc += t;
    }
    float mean = blockReduceSum256(loc, red) * (1.f/D_);
    float lv = 0.f;
    for (int d = tid; d < D_; d += 256) { float c = tv[d]-mean; lv += c*c; }
    float var = blockReduceSum256(lv, red) * (1.f/D_);
    float rs = rsqrtf(var + 1e-5f);
    for (int d = tid; d < D_; d += 256) {
        float o = (tv[d]-mean)*rs*gamma[d] + beta[d];
        out[r*D_+d] = o;
        if (FIRST) pack[r*D_+d] = __float2half_rn(o);
    }
}

// ================= host =================
template<class T> static T* symaddr(const void* sym) {
    void* p = nullptr; cudaGetSymbolAddress(&p, sym); return (T*)p;
}

extern "C" void kernel_launch(void* const* d_in, const int* in_sizes, int n_in,
                              void* d_out, int out_size) {
    const float* x      = (const float*)d_in[0];
    const int*   sidx   = (const int*)  d_in[1];
    const float* w1     = (const float*)d_in[2];
    const float* b1     = (const float*)d_in[3];
    const float* w2     = (const float*)d_in[4];
    const float* b2     = (const float*)d_in[5];
    const float* wd0    = (const float*)d_in[6];
    const float* bd0    = (const float*)d_in[7];
    const float* in_w   = (const float*)d_in[10];
    const float* in_b   = (const float*)d_in[11];
    const float* out_w  = (const float*)d_in[12];
    const float* out_b  = (const float*)d_in[13];
    const float* topo_w = (const float*)d_in[14];
    const float* topo_b = (const float*)d_in[15];
    const float* gate   = (const float*)d_in[16];
    const float* ln1_g  = (const float*)d_in[17];
    const float* ln1_b  = (const float*)d_in[18];
    const float* ln2_g  = (const float*)d_in[19];
    const float* ln2_b  = (const float*)d_in[20];
    const float* ffn_w1 = (const float*)d_in[21];
    const float* ffn_b1 = (const float*)d_in[22];
    const float* ffn_w2 = (const float*)d_in[23];
    const float* ffn_b2 = (const float*)d_in[24];
    float* out = (float*)d_out;

    auto p_xnorm = symaddr<float>(g_xnorm);
    auto p_dist  = symaddr<float>(g_dist);
    auto p_xp    = symaddr<__half>(g_xpack);
    auto p_sp    = symaddr<__half>(g_spack);
    auto p_qkvp  = symaddr<__half>(g_qkvpack);
    auto p_op    = symaddr<__half>(g_opack);
    auto p_attnP = symaddr<float>(g_attnP);
    auto p_x1    = symaddr<float>(g_x1);
    auto p_x1p   = symaddr<__half>(g_x1pack);
    auto p_hp    = symaddr<__half>(g_hpack);
    auto p_ffn2  = symaddr<float>(g_ffn2);
    auto p_wqkv  = symaddr<__half>(g_wqkvh);
    auto p_wout  = symaddr<__half>(g_wouth);
    auto p_wf1   = symaddr<__half>(g_wf1h);
    auto p_wf2   = symaddr<__half>(g_wf2h);

    constexpr int FSMEM = 5*128*72*2;   // 92160
    cudaFuncSetAttribute(flash_k, cudaFuncAttributeMaxDynamicSharedMemorySize, FSMEM);

    // prep
    init_k<<<1,32>>>();
    xsplit_k<<<BS_,96>>>(x);
    gatherpack_k<<<dim3(NS_,B_),96>>>(x, sidx);
    wconv_k<<<(D_*3*D_)/2048,256>>>(in_w,   p_wqkv);
    wconv_k<<<(D_*D_)/2048,  256>>>(out_w,  p_wout);
    wconv_k<<<(D_*2*D_)/2048,256>>>(ffn_w1, p_wf1);
    wconv_k<<<(2*D_*D_)/2048,256>>>(ffn_w2, p_wf2);

    // cdist -> dist (NT)
    hgemm<64,3,false,false><<<dim3(2,4,B_),256>>>(
        p_xp, p_sp, p_dist, nullptr,
        S_, D_, D_, D_, NS_,
        1, (long)S_*D_, 0, (long)NS_*D_, 0, (long)S_*NS_, 0,
        0.f, p_xnorm, sidx);
    topk_stats_k<<<BS_/8,256>>>();
    mlp_topo_k<<<B_,256>>>(w1,b1,w2,b2,wd0,bd0,topo_w,topo_b,gate);

    // QKV projection (NN, packed fp16 out)
    hgemm<128,0,true,true><<<dim3(18,64,1),256>>>(
        p_xp, p_wqkv, p_qkvp, in_b,
        BS_, D_, D_, 3*D_, 3*D_,
        1, 0,0,0,0,0,0, 0.f, nullptr, nullptr);

    // fused attention
    flash_k<<<dim3(4,Z_),256,FSMEM>>>(p_qkvp, p_op);

    // attn out projection (NN)
    hgemm<128,0,false,true><<<dim3(6,64,1),256>>>(
        p_op, p_wout, p_attnP, out_b,
        BS_, D_, D_, D_, D_,
        1, 0,0,0,0,0,0, 0.f, nullptr, nullptr);

    ln_k<true><<<BS_,256>>>(x, p_attnP, ln1_g, ln1_b, p_x1, p_x1p);

    // FFN (NN)
    hgemm<128,1,true,true><<<dim3(12,64,1),256>>>(
        p_x1p, p_wf1, p_hp, ffn_b1,
        BS_, D_, D_, 2*D_, 2*D_,
        1, 0,0,0,0,0,0, 0.f, nullptr, nullptr);
    hgemm<128,0,false,true><<<dim3(6,64,1),256>>>(
        p_hp, p_wf2, p_ffn2, ffn_b2,
        BS_, 2*D_, 2*D_, D_, D_,
        1, 0,0,0,0,0,0, 0.f, nullptr, nullptr);

    ln_k<false><<<BS_,256>>>(p_x1, p_ffn2, ln2_g, ln2_b, out, nullptr);
}

// round 8
// speedup vs baseline: 5.2736x; 1.0478x over previous
#include <cuda_runtime.h>
#include <cuda_fp16.h>
#include <float.h>
#include <cstdint>

#define B_   16
#define S_   512
#define D_   768
#define H_   12
#define HD_  64
#define K_   16
#define NS_  128
#define R_   32
#define BS_  (B_*S_)
#define Z_   (B_*H_)

// ================= PTX helpers =================
__device__ __forceinline__ uint32_t smem_to_u32(const void* p) {
    uint32_t a;
    asm("{ .reg .u64 t; cvta.to.shared.u64 t, %1; cvt.u32.u64 %0, t; }" : "=r"(a) : "l"(p));
    return a;
}
__device__ __forceinline__ void cpa16(uint32_t dst, const void* src) {
    asm volatile("cp.async.ca.shared.global [%0], [%1], 16;" :: "r"(dst), "l"(src));
}
__device__ __forceinline__ void ldsm4(uint32_t* r, uint32_t addr) {
    asm volatile("ldmatrix.sync.aligned.m8n8.x4.shared.b16 {%0,%1,%2,%3}, [%4];"
        : "=r"(r[0]), "=r"(r[1]), "=r"(r[2]), "=r"(r[3]) : "r"(addr));
}
__device__ __forceinline__ void ldsm2(uint32_t* r, uint32_t addr) {
    asm volatile("ldmatrix.sync.aligned.m8n8.x2.shared.b16 {%0,%1}, [%2];"
        : "=r"(r[0]), "=r"(r[1]) : "r"(addr));
}
__device__ __forceinline__ void ldsm2t(uint32_t* r, uint32_t addr) {
    asm volatile("ldmatrix.sync.aligned.m8n8.x2.trans.shared.b16 {%0,%1}, [%2];"
        : "=r"(r[0]), "=r"(r[1]) : "r"(addr));
}
__device__ __forceinline__ void ldsm4t(uint32_t* r, uint32_t addr) {
    asm volatile("ldmatrix.sync.aligned.m8n8.x4.trans.shared.b16 {%0,%1,%2,%3}, [%4];"
        : "=r"(r[0]), "=r"(r[1]), "=r"(r[2]), "=r"(r[3]) : "r"(addr));
}
__device__ __forceinline__ void mma16816(float* c, const uint32_t* a, const uint32_t* b) {
    asm volatile("mma.sync.aligned.m16n8k16.row.col.f32.f16.f16.f32 "
        "{%0,%1,%2,%3}, {%4,%5,%6,%7}, {%8,%9}, {%0,%1,%2,%3};"
        : "+f"(c[0]), "+f"(c[1]), "+f"(c[2]), "+f"(c[3])
        : "r"(a[0]), "r"(a[1]), "r"(a[2]), "r"(a[3]), "r"(b[0]), "r"(b[1]));
}

// ================= scratch =================
__device__ float    g_xnorm[BS_];
__device__ double   g_sum[B_], g_sumsq[B_];
__device__ unsigned g_minb[B_], g_maxb[B_];
__device__ float    g_dist[B_*S_*NS_];
__device__ float    g_topo[B_*D_];
__device__ __align__(16) __half g_xpack [BS_*D_];
__device__ __align__(16) __half g_spack [B_*NS_*D_];
__device__ __align__(16) __half g_qkvpack[(size_t)BS_*3*D_];
__device__ __align__(16) __half g_opack [BS_*D_];
__device__ float    g_attnP[BS_*D_];
__device__ float    g_x1[BS_*D_];
__device__ __align__(16) __half g_x1pack[BS_*D_];
__device__ __align__(16) __half g_hpack [(size_t)BS_*2*D_];
__device__ float    g_ffn2[BS_*D_];
__device__ __align__(16) __half g_wqkvh[D_*3*D_];     // [K][N] fp16
__device__ __align__(16) __half g_wouth[D_*D_];
__device__ __align__(16) __half g_wf1h [D_*2*D_];
__device__ __align__(16) __half g_wf2h [2*D_*D_];

// ================= HMMA GEMM (3-stage pipeline) =================
// C[128,BN] = A[M,K] * B.  BNN=true: B stored [K][N]; false: [N][K].
// EPI: 0=+bias, 1=gelu, 2=*alpha, 3=cdist.
template<int BN, int EPI, bool PACKOUT, bool BNN>
__global__ __launch_bounds__(256,2)
void hgemm(const __half* __restrict__ A, const __half* __restrict__ Bm,
           void* __restrict__ Cv, const float* __restrict__ bias,
           int M, int Kd, int lda, int ldb, int ldc,
           int Hdiv, long sAb, long sAh, long sBb, long sBh, long sCb, long sCh,
           float alpha, const float* __restrict__ xn, const int* __restrict__ sidx)
{
    constexpr int NT = BN/32;
    constexpr int NW = BN/4;
    constexpr int AH = 128*40;
    constexpr int BH = BNN ? 32*136 : BN*40;
    constexpr int NS = 3;
    __shared__ __half As[NS][AH];
    __shared__ __half Bs[NS][BH];

    const int tid = threadIdx.x, warp = tid>>5, lane = tid&31;
    const int wm = (warp>>2)*64, wn = (warp&3)*NW;
    const int z = blockIdx.z, zb = z/Hdiv, zh = z - zb*Hdiv;
    A  += zb*sAb + zh*sAh;
    Bm += zb*sBb + zh*sBh;
    const int n0 = blockIdx.x*BN, m0 = blockIdx.y*128;
    const uint32_t sa = smem_to_u32(As), sb = smem_to_u32(Bs);

    float acc[4][NT][4];
    #pragma unroll
    for (int i=0;i<4;i++)
        #pragma unroll
        for (int j=0;j<NT;j++)
            #pragma unroll
            for (int q=0;q<4;q++) acc[i][j][q]=0.f;

    const int nch = Kd>>5;

    auto loadA = [&](int ko, int st) {
        for (int u = tid; u < 512; u += 256) {
            int r = u>>2, c = u&3;
            cpa16(sa + st*AH*2 + (r*40+c*8)*2, A + (long)(m0+r)*lda + ko + c*8);
        }
    };
    auto loadB = [&](int ko, int st) {
        if (BNN) {
            for (int u = tid; u < 32*(BN/8); u += 256) {
                int r = u/(BN/8), c = u%(BN/8);
                cpa16(sb + st*BH*2 + (r*136+c*8)*2, Bm + (long)(ko+r)*ldb + n0 + c*8);
            }
        } else {
            for (int u = tid; u < BN*4; u += 256) {
                int r = u>>2, c = u&3;
                cpa16(sb + st*BH*2 + (r*40+c*8)*2, Bm + (long)(n0+r)*ldb + ko + c*8);
            }
        }
    };

    // prime stages 0,1
    loadA(0,0); loadB(0,0);
    asm volatile("cp.async.commit_group;");
    if (nch > 1) { loadA(32,1); loadB(32,1); }
    asm volatile("cp.async.commit_group;");

    int st = 0;
    for (int it = 0; it < nch; ++it) {
        asm volatile("cp.async.wait_group 1;");
        __syncthreads();

        const uint32_t sab = sa + st*AH*2;
        const uint32_t sbb = sb + st*BH*2;
        #pragma unroll
        for (int kk = 0; kk < 32; kk += 16) {
            uint32_t af[4][4], bf[NT][2];
            #pragma unroll
            for (int mt = 0; mt < 4; mt++) {
                int r = wm + mt*16 + (lane&15);
                ldsm4(af[mt], sab + (r*40 + kk + (lane>>4)*8)*2);
            }
            #pragma unroll
            for (int nt = 0; nt < NT; nt++) {
                if (BNN) {
                    ldsm2t(bf[nt], sbb + ((kk + (lane&15))*136 + wn + nt*8)*2);
                } else {
                    int r = wn + nt*8 + (lane&7);
                    int co = kk + ((lane>>3)&1)*8;
                    ldsm2(bf[nt], sbb + (r*40 + co)*2);
                }
            }
            #pragma unroll
            for (int mt = 0; mt < 4; mt++)
                #pragma unroll
                for (int nt = 0; nt < NT; nt++)
                    mma16816(acc[mt][nt], af[mt], bf[nt]);
        }
        __syncthreads();
        if (it+2 < nch) {
            loadA((it+2)<<5, (st+2)%NS); loadB((it+2)<<5, (st+2)%NS);
        }
        asm volatile("cp.async.commit_group;");
        st = (st+1)%NS;
    }

    // ---- epilogue ----
    float* Cf = (float*)Cv;
    __half* Cb = (__half*)Cv;
    const long coff = zb*sCb + zh*sCh;
    #pragma unroll
    for (int mt = 0; mt < 4; mt++) {
        #pragma unroll
        for (int hf = 0; hf < 2; hf++) {
            const int gm = m0 + wm + mt*16 + (lane>>2) + hf*8;
            const float xnr = (EPI==3) ? xn[(long)z*M + gm] : 0.f;
            #pragma unroll
            for (int nt = 0; nt < NT; nt++) {
                const int gn = n0 + wn + nt*8 + (lane&3)*2;
                float v0 = acc[mt][nt][hf*2+0];
                float v1 = acc[mt][nt][hf*2+1];
                if (EPI==0) {
                    if (bias) { v0 += bias[gn]; v1 += bias[gn+1]; }
                } else if (EPI==1) {
                    float t0 = v0 + bias[gn];   v0 = t0 * normcdff(t0);
                    float t1 = v1 + bias[gn+1]; v1 = t1 * normcdff(t1);
                } else if (EPI==2) {
                    v0 *= alpha; v1 *= alpha;
                } else if (EPI==3) {
                    v0 = sqrtf(fmaxf(xnr + xn[(long)z*M + sidx[gn]]   - 2.f*v0, 0.f));
                    v1 = sqrtf(fmaxf(xnr + xn[(long)z*M + sidx[gn+1]] - 2.f*v1, 0.f));
                }
                if (PACKOUT) {
                    __half2 hh; hh.x = __float2half_rn(v0); hh.y = __float2half_rn(v1);
                    *(__half2*)(Cb + coff + (long)gm*ldc + gn) = hh;
                } else {
                    float2 st2; st2.x=v0; st2.y=v1;
                    *(float2*)(Cf + coff + (long)gm*ldc + gn) = st2;
                }
            }
        }
    }
}

// ================= fused flash attention =================
__global__ __launch_bounds__(256)
void flash_k(const __half* __restrict__ qkv, __half* __restrict__ opack) {
    extern __shared__ __half fs[];
    constexpr int LD = 72;
    constexpr int TB = 128*LD;
    const int z = blockIdx.y, b = z/H_, h = z - b*H_;
    const int qb = blockIdx.x;
    const int tid = threadIdx.x, warp = tid>>5, lane = tid&31;
    const int g = lane>>2, t = lane&3;
    const int wm = warp*16;

    const __half* qg = qkv + ((long)b*S_ + qb*128)*2304 + h*64;
    const __half* kg = qkv + (long)b*S_*2304 + 768 + h*64;
    const __half* vg = qkv + (long)b*S_*2304 + 1536 + h*64;
    const uint32_t sq = smem_to_u32(fs);
    const uint32_t sk = sq + TB*2;
    const uint32_t sv = sq + 3*TB*2;

    for (int u = tid; u < 1024; u += 256) {
        int r = u>>3, c = u&7;
        cpa16(sq + (r*LD + c*8)*2, qg + (long)r*2304 + c*8);
        cpa16(sk + (r*LD + c*8)*2, kg + (long)r*2304 + c*8);
        cpa16(sv + (r*LD + c*8)*2, vg + (long)r*2304 + c*8);
    }
    asm volatile("cp.async.commit_group;");
    asm volatile("cp.async.wait_group 0;");
    __syncthreads();

    uint32_t qf[4][4];
    #pragma unroll
    for (int kc = 0; kc < 4; kc++) {
        int r = wm + (lane&15);
        ldsm4(qf[kc], sq + (r*LD + kc*16 + (lane>>4)*8)*2);
    }

    float m0 = -1e30f, m1 = -1e30f, l0 = 0.f, l1 = 0.f;
    float oacc[8][4];
    #pragma unroll
    for (int i=0;i<8;i++) { oacc[i][0]=0.f; oacc[i][1]=0.f; oacc[i][2]=0.f; oacc[i][3]=0.f; }

    for (int kb = 0; kb < 4; ++kb) {
        const int buf = kb&1;
        if (kb) {
            asm volatile("cp.async.wait_group 0;");
            __syncthreads();
        }
        if (kb < 3) {
            const __half* kn = kg + (long)(kb+1)*128*2304;
            const __half* vn = vg + (long)(kb+1)*128*2304;
            const uint32_t dk = sk + (buf^1)*TB*2, dv = sv + (buf^1)*TB*2;
            for (int u = tid; u < 1024; u += 256) {
                int r = u>>3, c = u&7;
                cpa16(dk + (r*LD+c*8)*2, kn + (long)r*2304 + c*8);
                cpa16(dv + (r*LD+c*8)*2, vn + (long)r*2304 + c*8);
            }
            asm volatile("cp.async.commit_group;");
        }
        const uint32_t skb = sk + buf*TB*2, svb = sv + buf*TB*2;

        float sacc[16][4];
        #pragma unroll
        for (int i=0;i<16;i++) { sacc[i][0]=0.f; sacc[i][1]=0.f; sacc[i][2]=0.f; sacc[i][3]=0.f; }
        #pragma unroll
        for (int kc = 0; kc < 4; kc++) {
            #pragma unroll
            for (int ntp = 0; ntp < 8; ntp++) {
                uint32_t b4[4];
                int r = ntp*16 + (lane&7) + ((lane>>4)&1)*8;
                int co = kc*16 + ((lane>>3)&1)*8;
                ldsm4(b4, skb + (r*LD + co)*2);
                mma16816(sacc[2*ntp],   qf[kc], b4);
                mma16816(sacc[2*ntp+1], qf[kc], b4+2);
            }
        }
        float mx0 = -1e30f, mx1 = -1e30f;
        #pragma unroll
        for (int nt=0;nt<16;nt++) {
            sacc[nt][0]*=0.125f; sacc[nt][1]*=0.125f; sacc[nt][2]*=0.125f; sacc[nt][3]*=0.125f;
            mx0 = fmaxf(mx0, fmaxf(sacc[nt][0], sacc[nt][1]));
            mx1 = fmaxf(mx1, fmaxf(sacc[nt][2], sacc[nt][3]));
        }
        mx0 = fmaxf(mx0, __shfl_xor_sync(0xffffffffu, mx0, 1));
        mx0 = fmaxf(mx0, __shfl_xor_sync(0xffffffffu, mx0, 2));
        mx1 = fmaxf(mx1, __shfl_xor_sync(0xffffffffu, mx1, 1));
        mx1 = fmaxf(mx1, __shfl_xor_sync(0xffffffffu, mx1, 2));
        const float mn0 = fmaxf(m0, mx0), mn1 = fmaxf(m1, mx1);
        const float c0 = __expf(m0 - mn0), c1 = __expf(m1 - mn1);
        m0 = mn0; m1 = mn1;
        float rs0 = 0.f, rs1 = 0.f;
        uint32_t ph0[16], ph1[16];
        #pragma unroll
        for (int nt=0;nt<16;nt++) {
            float e0 = __expf(sacc[nt][0]-mn0), e1 = __expf(sacc[nt][1]-mn0);
            float e2 = __expf(sacc[nt][2]-mn1), e3 = __expf(sacc[nt][3]-mn1);
            rs0 += e0+e1; rs1 += e2+e3;
            __half2 p0 = __floats2half2_rn(e0,e1); ph0[nt] = *(uint32_t*)&p0;
            __half2 p1 = __floats2half2_rn(e2,e3); ph1[nt] = *(uint32_t*)&p1;
        }
        rs0 += __shfl_xor_sync(0xffffffffu, rs0, 1);
        rs0 += __shfl_xor_sync(0xffffffffu, rs0, 2);
        rs1 += __shfl_xor_sync(0xffffffffu, rs1, 1);
        rs1 += __shfl_xor_sync(0xffffffffu, rs1, 2);
        l0 = l0*c0 + rs0; l1 = l1*c1 + rs1;
        #pragma unroll
        for (int i=0;i<8;i++) { oacc[i][0]*=c0; oacc[i][1]*=c0; oacc[i][2]*=c1; oacc[i][3]*=c1; }

        #pragma unroll
        for (int kc = 0; kc < 8; kc++) {
            uint32_t a[4] = { ph0[2*kc], ph1[2*kc], ph0[2*kc+1], ph1[2*kc+1] };
            #pragma unroll
            for (int ntp = 0; ntp < 4; ntp++) {
                uint32_t b4[4];
                int r = kc*16 + (lane&15);
                int co = ntp*16 + (lane>>4)*8;
                ldsm4t(b4, svb + (r*LD + co)*2);
                mma16816(oacc[2*ntp],   a, b4);
                mma16816(oacc[2*ntp+1], a, b4+2);
            }
        }
        __syncthreads();
    }

    const float i0 = 1.0f/l0, i1 = 1.0f/l1;
    __half* o0 = opack + ((long)b*S_ + qb*128 + wm + g)*768 + h*64;
    __half* o1 = o0 + 8*768;
    #pragma unroll
    for (int nt = 0; nt < 8; nt++) {
        __half2 h0 = __floats2half2_rn(oacc[nt][0]*i0, oacc[nt][1]*i0);
        __half2 h1 = __floats2half2_rn(oacc[nt][2]*i1, oacc[nt][3]*i1);
        *(__half2*)(o0 + nt*8 + 2*t) = h0;
        *(__half2*)(o1 + nt*8 + 2*t) = h1;
    }
}

// ================= pack / transform =================
__global__ void xsplit_k(const float* __restrict__ x) {
    __shared__ float red[3];
    long r = blockIdx.x; int t = threadIdx.x;
    const float* s = x + r*D_ + t*8;
    float f[8];
    *(float4*)(f)   = *(const float4*)(s);
    *(float4*)(f+4) = *(const float4*)(s+4);
    __half h[8];
    float sq = 0.f;
    #pragma unroll
    for (int u = 0; u < 8; u++) { sq += f[u]*f[u]; h[u] = __float2half_rn(f[u]); }
    *(uint4*)(g_xpack + r*D_ + t*8) = *(uint4*)h;
    #pragma unroll
    for (int o = 16; o; o >>= 1) sq += __shfl_xor_sync(0xffffffffu, sq, o);
    if ((t&31)==0) red[t>>5] = sq;
    __syncthreads();
    if (t==0) g_xnorm[r] = red[0]+red[1]+red[2];
}

__global__ void gatherpack_k(const float* __restrict__ x, const int* __restrict__ sidx) {
    int j = blockIdx.x, b = blockIdx.y, t = threadIdx.x;
    const float* s = x + ((long)b*S_ + sidx[j])*D_ + t*8;
    __half h[8];
    #pragma unroll
    for (int u = 0; u < 8; u++) h[u] = __float2half_rn(s[u]);
    *(uint4*)(g_spack + ((long)b*NS_ + j)*D_ + t*8) = *(uint4*)h;
}

// one launch converting all four weight matrices (segments by block index)
__global__ void wconv_all_k(const float* __restrict__ w0, const float* __restrict__ w1,
                            const float* __restrict__ w2, const float* __restrict__ w3) {
    // sizes /2048 blocks: 864, 288, 576, 576
    int bid = blockIdx.x;
    const float* W; __half* Wh; long base;
    if (bid < 864)      { W = w0; Wh = g_wqkvh; base = bid; }
    else if (bid < 1152){ W = w1; Wh = g_wouth; base = bid - 864; }
    else if (bid < 1728){ W = w2; Wh = g_wf1h;  base = bid - 1152; }
    else                { W = w3; Wh = g_wf2h;  base = bid - 1728; }
    long i = (base*256 + threadIdx.x)*8;
    float f[8];
    *(float4*)(f)   = *(const float4*)(W+i);
    *(float4*)(f+4) = *(const float4*)(W+i+4);
    __half h[8];
    #pragma unroll
    for (int u = 0; u < 8; u++) h[u] = __float2half_rn(f[u]);
    *(uint4*)(Wh + i) = *(uint4*)h;
}

// ================= misc =================
__device__ __forceinline__ float blockReduceSum256(float v, float* red) {
    #pragma unroll
    for (int o = 16; o; o >>= 1) v += __shfl_xor_sync(0xffffffffu, v, o);
    int w = threadIdx.x>>5, l = threadIdx.x&31;
    if (l==0) red[w] = v;
    __syncthreads();
    float r = (threadIdx.x < 8) ? red[threadIdx.x] : 0.f;
    if (w==0) {
        #pragma unroll
        for (int o = 4; o; o >>= 1) r += __shfl_xor_sync(0xffffffffu, r, o);
        if (l==0) red[0] = r;
    }
    __syncthreads();
    float out = red[0];
    __syncthreads();
    return out;
}

__global__ void init_k() {
    int t = threadIdx.x;
    if (t < B_) { g_sum[t]=0.0; g_sumsq[t]=0.0; g_minb[t]=0x7f7fffffu; g_maxb[t]=0u; }
}

__global__ void topk_stats_k() {
    int warp = threadIdx.x >> 5, lane = threadIdx.x & 31;
    long row = (long)blockIdx.x*8 + warp;
    const float4* p = (const float4*)(g_dist + row*NS_);
    float4 v4 = p[lane];
    float v[4] = {v4.x, v4.y, v4.z, v4.w};
    float lsum=0.f, lsq=0.f, mn0=0.f, mx15=0.f;
    #pragma unroll
    for (int it = 0; it < K_; ++it) {
        float lv = fminf(fminf(v[0],v[1]), fminf(v[2],v[3]));
        float m = lv;
        #pragma unroll
        for (int o = 16; o; o >>= 1) m = fminf(m, __shfl_xor_sync(0xffffffffu, m, o));
        unsigned bal = __ballot_sync(0xffffffffu, lv==m);
        if (lane == __ffs(bal)-1) {
            if      (v[0]==m) v[0]=FLT_MAX;
            else if (v[1]==m) v[1]=FLT_MAX;
            else if (v[2]==m) v[2]=FLT_MAX;
            else              v[3]=FLT_MAX;
        }
        lsum += m; lsq += m*m;
        if (it==0) mn0 = m;
        mx15 = m;
    }
    if (lane==0) {
        int b = (int)(row >> 9);
        atomicAdd(&g_sum[b], (double)lsum);
        atomicAdd(&g_sumsq[b], (double)lsq);
        atomicMin(&g_minb[b], __float_as_uint(mn0));
        atomicMax(&g_maxb[b], __float_as_uint(mx15));
    }
}

__global__ void mlp_topo_k(const float* __restrict__ w1, const float* __restrict__ b1,
                           const float* __restrict__ w2, const float* __restrict__ b2,
                           const float* __restrict__ wd0, const float* __restrict__ bd0,
                           const float* __restrict__ topo_w, const float* __restrict__ topo_b,
                           const float* __restrict__ gate) {
    int b = blockIdx.x, tid = threadIdx.x;
    __shared__ float st[6], h1[192], h2[R_], land[R_];
    if (tid==0) {
        double n = 8192.0, s = g_sum[b], sq = g_sumsq[b];
        double mean = s / n;
        double var = (sq - s*s/n) / (n - 1.0);
        float sd = sqrtf(fmaxf((float)var, 0.f));
        st[0]=(float)mean; st[1]=sd;
        st[2]=__uint_as_float(g_minb[b]); st[3]=__uint_as_float(g_maxb[b]);
        st[4]=(float)mean*0.5f; st[5]=sd*0.5f;
    }
    __syncthreads();
    if (tid < 192) {
        float a = b1[tid];
        #pragma unroll
        for (int i = 0; i < 6; i++) a += st[i]*w1[i*192+tid];
        h1[tid] = fmaxf(a, 0.f);
    }
    __syncthreads();
    if (tid < R_) {
        float a = b2[tid];
        for (int i = 0; i < 192; i++) a += h1[i]*w2[i*R_+tid];
        h2[tid] = a;
    }
    __syncthreads();
    if (tid < R_) {
        float a = bd0[tid];
        #pragma unroll
        for (int i = 0; i < R_; i++) a += h2[i]*wd0[i*R_+tid];
        land[tid] = a;
    }
    __syncthreads();
    float gt = *gate;
    for (int d = tid; d < D_; d += blockDim.x) {
        float a = topo_b[d];
        #pragma unroll
        for (int i = 0; i < R_; i++) a += land[i]*topo_w[i*D_+d];
        g_topo[b*D_+d] = gt*a;
    }
}

template<bool FIRST>
__global__ void ln_k(const float* __restrict__ a, const float* __restrict__ br,
                     const float* __restrict__ gamma, const float* __restrict__ beta,
                     float* __restrict__ out, __half* __restrict__ pack) {
    __shared__ float tv[D_];
    __shared__ float red[8];
    long r = blockIdx.x; int tid = threadIdx.x;
    float loc = 0.f;
    for (int d = tid; d < D_; d += 256) {
        float t = a[r*D_+d] + br[r*D_+d];
        if (FIRST) t += g_topo[(r>>9)*D_ + d];
        tv[d] = t; loc += t;
    }
    float mean = blockReduceSum256(loc, red) * (1.f/D_);
    float lv = 0.f;
    for (int d = tid; d < D_; d += 256) { float c = tv[d]-mean; lv += c*c; }
    float var = blockReduceSum256(lv, red) * (1.f/D_);
    float rs = rsqrtf(var + 1e-5f);
    for (int d = tid; d < D_; d += 256) {
        float o = (tv[d]-mean)*rs*gamma[d] + beta[d];
        out[r*D_+d] = o;
        if (FIRST) pack[r*D_+d] = __float2half_rn(o);
    }
}

// ================= host =================
template<class T> static T* symaddr(const void* sym) {
    void* p = nullptr; cudaGetSymbolAddress(&p, sym); return (T*)p;
}

extern "C" void kernel_launch(void* const* d_in, const int* in_sizes, int n_in,
                              void* d_out, int out_size) {
    const float* x      = (const float*)d_in[0];
    const int*   sidx   = (const int*)  d_in[1];
    const float* w1     = (const float*)d_in[2];
    const float* b1     = (const float*)d_in[3];
    const float* w2     = (const float*)d_in[4];
    const float* b2     = (const float*)d_in[5];
    const float* wd0    = (const float*)d_in[6];
    const float* bd0    = (const float*)d_in[7];
    const float* in_w   = (const float*)d_in[10];
    const float* in_b   = (const float*)d_in[11];
    const float* out_w  = (const float*)d_in[12];
    const float* out_b  = (const float*)d_in[13];
    const float* topo_w = (const float*)d_in[14];
    const float* topo_b = (const float*)d_in[15];
    const float* gate   = (const float*)d_in[16];
    const float* ln1_g  = (const float*)d_in[17];
    const float* ln1_b  = (const float*)d_in[18];
    const float* ln2_g  = (const float*)d_in[19];
    const float* ln2_b  = (const float*)d_in[20];
    const float* ffn_w1 = (const float*)d_in[21];
    const float* ffn_b1 = (const float*)d_in[22];
    const float* ffn_w2 = (const float*)d_in[23];
    const float* ffn_b2 = (const float*)d_in[24];
    float* out = (float*)d_out;

    auto p_xnorm = symaddr<float>(g_xnorm);
    auto p_dist  = symaddr<float>(g_dist);
    auto p_xp    = symaddr<__half>(g_xpack);
    auto p_sp    = symaddr<__half>(g_spack);
    auto p_qkvp  = symaddr<__half>(g_qkvpack);
    auto p_op    = symaddr<__half>(g_opack);
    auto p_attnP = symaddr<float>(g_attnP);
    auto p_x1    = symaddr<float>(g_x1);
    auto p_x1p   = symaddr<__half>(g_x1pack);
    auto p_hp    = symaddr<__half>(g_hpack);
    auto p_ffn2  = symaddr<float>(g_ffn2);
    auto p_wqkv  = symaddr<__half>(g_wqkvh);
    auto p_wout  = symaddr<__half>(g_wouth);
    auto p_wf1   = symaddr<__half>(g_wf1h);
    auto p_wf2   = symaddr<__half>(g_wf2h);

    constexpr int FSMEM = 5*128*72*2;   // 92160
    cudaFuncSetAttribute(flash_k, cudaFuncAttributeMaxDynamicSharedMemorySize, FSMEM);

    // prep
    init_k<<<1,32>>>();
    xsplit_k<<<BS_,96>>>(x);
    gatherpack_k<<<dim3(NS_,B_),96>>>(x, sidx);
    wconv_all_k<<<2304,256>>>(in_w, out_w, ffn_w1, ffn_w2);

    // cdist -> dist (NT)
    hgemm<64,3,false,false><<<dim3(2,4,B_),256>>>(
        p_xp, p_sp, p_dist, nullptr,
        S_, D_, D_, D_, NS_,
        1, (long)S_*D_, 0, (long)NS_*D_, 0, (long)S_*NS_, 0,
        0.f, p_xnorm, sidx);
    topk_stats_k<<<BS_/8,256>>>();
    mlp_topo_k<<<B_,256>>>(w1,b1,w2,b2,wd0,bd0,topo_w,topo_b,gate);

    // QKV projection (NN, packed fp16 out)
    hgemm<128,0,true,true><<<dim3(18,64,1),256>>>(
        p_xp, p_wqkv, p_qkvp, in_b,
        BS_, D_, D_, 3*D_, 3*D_,
        1, 0,0,0,0,0,0, 0.f, nullptr, nullptr);

    // fused attention
    flash_k<<<dim3(4,Z_),256,FSMEM>>>(p_qkvp, p_op);

    // attn out projection (NN)
    hgemm<128,0,false,true><<<dim3(6,64,1),256>>>(
        p_op, p_wout, p_attnP, out_b,
        BS_, D_, D_, D_, D_,
        1, 0,0,0,0,0,0, 0.f, nullptr, nullptr);

    ln_k<true><<<BS_,256>>>(x, p_attnP, ln1_g, ln1_b, p_x1, p_x1p);

    // FFN (NN)
    hgemm<128,1,true,true><<<dim3(12,64,1),256>>>(
        p_x1p, p_wf1, p_hp, ffn_b1,
        BS_, D_, D_, 2*D_, 2*D_,
        1, 0,0,0,0,0,0, 0.f, nullptr, nullptr);
    hgemm<128,0,false,true><<<dim3(6,64,1),256>>>(
        p_hp, p_wf2, p_ffn2, ffn_b2,
        BS_, 2*D_, 2*D_, D_, D_,
        1, 0,0,0,0,0,0, 0.f, nullptr, nullptr);

    ln_k<false><<<BS_,256>>>(p_x1, p_ffn2, ln2_g, ln2_b, out, nullptr);
}

// round 9
// speedup vs baseline: 5.3603x; 1.0164x over previous
#include <cuda_runtime.h>
#include <cuda_fp16.h>
#include <float.h>
#include <cstdint>

#define B_   16
#define S_   512
#define D_   768
#define H_   12
#define HD_  64
#define K_   16
#define NS_  128
#define R_   32
#define BS_  (B_*S_)
#define Z_   (B_*H_)

// ================= PTX helpers =================
__device__ __forceinline__ uint32_t smem_to_u32(const void* p) {
    uint32_t a;
    asm("{ .reg .u64 t; cvta.to.shared.u64 t, %1; cvt.u32.u64 %0, t; }" : "=r"(a) : "l"(p));
    return a;
}
__device__ __forceinline__ void cpa16(uint32_t dst, const void* src) {
    asm volatile("cp.async.ca.shared.global [%0], [%1], 16;" :: "r"(dst), "l"(src));
}
__device__ __forceinline__ void ldsm4(uint32_t* r, uint32_t addr) {
    asm volatile("ldmatrix.sync.aligned.m8n8.x4.shared.b16 {%0,%1,%2,%3}, [%4];"
        : "=r"(r[0]), "=r"(r[1]), "=r"(r[2]), "=r"(r[3]) : "r"(addr));
}
__device__ __forceinline__ void ldsm2(uint32_t* r, uint32_t addr) {
    asm volatile("ldmatrix.sync.aligned.m8n8.x2.shared.b16 {%0,%1}, [%2];"
        : "=r"(r[0]), "=r"(r[1]) : "r"(addr));
}
__device__ __forceinline__ void ldsm4t(uint32_t* r, uint32_t addr) {
    asm volatile("ldmatrix.sync.aligned.m8n8.x4.trans.shared.b16 {%0,%1,%2,%3}, [%4];"
        : "=r"(r[0]), "=r"(r[1]), "=r"(r[2]), "=r"(r[3]) : "r"(addr));
}
__device__ __forceinline__ void mma16816(float* c, const uint32_t* a, const uint32_t* b) {
    asm volatile("mma.sync.aligned.m16n8k16.row.col.f32.f16.f16.f32 "
        "{%0,%1,%2,%3}, {%4,%5,%6,%7}, {%8,%9}, {%0,%1,%2,%3};"
        : "+f"(c[0]), "+f"(c[1]), "+f"(c[2]), "+f"(c[3])
        : "r"(a[0]), "r"(a[1]), "r"(a[2]), "r"(a[3]), "r"(b[0]), "r"(b[1]));
}

// ================= scratch =================
__device__ float    g_xnorm[BS_];
__device__ double   g_sum[B_], g_sumsq[B_];
__device__ unsigned g_minb[B_], g_maxb[B_];
__device__ float    g_dist[B_*S_*NS_];
__device__ float    g_topo[B_*D_];
__device__ __align__(16) __half g_xpack [BS_*D_];
__device__ __align__(16) __half g_spack [B_*NS_*D_];
__device__ __align__(16) __half g_qkvpack[(size_t)BS_*3*D_];
__device__ __align__(16) __half g_opack [BS_*D_];
__device__ float    g_attnP[BS_*D_];
__device__ float    g_x1[BS_*D_];
__device__ __align__(16) __half g_x1pack[BS_*D_];
__device__ __align__(16) __half g_hpack [(size_t)BS_*2*D_];
__device__ float    g_ffn2[BS_*D_];
__device__ __align__(16) __half g_wqkvh[D_*3*D_];     // [K][N] fp16
__device__ __align__(16) __half g_wouth[D_*D_];
__device__ __align__(16) __half g_wf1h [D_*2*D_];
__device__ __align__(16) __half g_wf2h [2*D_*D_];

// ================= HMMA GEMM (3-stage pipeline) =================
// C[128,BN] = A[M,K] * B.  BNN=true: B stored [K][N]; false: [N][K].
// EPI: 0=+bias, 1=gelu, 2=*alpha, 3=cdist.
template<int BN, int EPI, bool PACKOUT, bool BNN>
__global__ __launch_bounds__(256,2)
void hgemm(const __half* __restrict__ A, const __half* __restrict__ Bm,
           void* __restrict__ Cv, const float* __restrict__ bias,
           int M, int Kd, int lda, int ldb, int ldc,
           int Hdiv, long sAb, long sAh, long sBb, long sBh, long sCb, long sCh,
           float alpha, const float* __restrict__ xn, const int* __restrict__ sidx)
{
    constexpr int NT = BN/32;
    constexpr int NW = BN/4;
    constexpr int AH = 128*40;
    constexpr int BH = BNN ? 32*136 : BN*40;
    constexpr int NSTG = 3;
    __shared__ __half As[NSTG][AH];
    __shared__ __half Bs[NSTG][BH];

    const int tid = threadIdx.x, warp = tid>>5, lane = tid&31;
    const int wm = (warp>>2)*64, wn = (warp&3)*NW;
    const int z = blockIdx.z, zb = z/Hdiv, zh = z - zb*Hdiv;
    A  += zb*sAb + zh*sAh;
    Bm += zb*sBb + zh*sBh;
    const int n0 = blockIdx.x*BN, m0 = blockIdx.y*128;
    const uint32_t sa = smem_to_u32(As), sb = smem_to_u32(Bs);

    float acc[4][NT][4];
    #pragma unroll
    for (int i=0;i<4;i++)
        #pragma unroll
        for (int j=0;j<NT;j++)
            #pragma unroll
            for (int q=0;q<4;q++) acc[i][j][q]=0.f;

    const int nch = Kd>>5;

    auto loadA = [&](int ko, int st) {
        for (int u = tid; u < 512; u += 256) {
            int r = u>>2, c = u&3;
            cpa16(sa + st*AH*2 + (r*40+c*8)*2, A + (long)(m0+r)*lda + ko + c*8);
        }
    };
    auto loadB = [&](int ko, int st) {
        if (BNN) {
            for (int u = tid; u < 32*(BN/8); u += 256) {
                int r = u/(BN/8), c = u%(BN/8);
                cpa16(sb + st*BH*2 + (r*136+c*8)*2, Bm + (long)(ko+r)*ldb + n0 + c*8);
            }
        } else {
            for (int u = tid; u < BN*4; u += 256) {
                int r = u>>2, c = u&3;
                cpa16(sb + st*BH*2 + (r*40+c*8)*2, Bm + (long)(n0+r)*ldb + ko + c*8);
            }
        }
    };

    // prime stages 0,1
    loadA(0,0); loadB(0,0);
    asm volatile("cp.async.commit_group;");
    if (nch > 1) { loadA(32,1); loadB(32,1); }
    asm volatile("cp.async.commit_group;");

    int st = 0;
    for (int it = 0; it < nch; ++it) {
        asm volatile("cp.async.wait_group 1;");
        __syncthreads();

        const uint32_t sab = sa + st*AH*2;
        const uint32_t sbb = sb + st*BH*2;
        #pragma unroll
        for (int kk = 0; kk < 32; kk += 16) {
            uint32_t af[4][4], bf[NT][2];
            #pragma unroll
            for (int mt = 0; mt < 4; mt++) {
                int r = wm + mt*16 + (lane&15);
                ldsm4(af[mt], sab + (r*40 + kk + (lane>>4)*8)*2);
            }
            if (BNN) {
                #pragma unroll
                for (int np = 0; np < NT/2; np++) {
                    uint32_t b4[4];
                    // 16(k) x 16(n) transposed block -> two adjacent n-tiles
                    int r = kk + (lane&15);
                    int co = wn + np*16 + (lane>>4)*8;
                    ldsm4t(b4, sbb + (r*136 + co)*2);
                    bf[2*np][0]   = b4[0]; bf[2*np][1]   = b4[1];
                    bf[2*np+1][0] = b4[2]; bf[2*np+1][1] = b4[3];
                }
            } else {
                #pragma unroll
                for (int nt = 0; nt < NT; nt++) {
                    int r = wn + nt*8 + (lane&7);
                    int co = kk + ((lane>>3)&1)*8;
                    ldsm2(bf[nt], sbb + (r*40 + co)*2);
                }
            }
            #pragma unroll
            for (int mt = 0; mt < 4; mt++)
                #pragma unroll
                for (int nt = 0; nt < NT; nt++)
                    mma16816(acc[mt][nt], af[mt], bf[nt]);
        }
        __syncthreads();
        if (it+2 < nch) {
            loadA((it+2)<<5, (st+2)%NSTG); loadB((it+2)<<5, (st+2)%NSTG);
        }
        asm volatile("cp.async.commit_group;");
        st = (st+1)%NSTG;
    }

    // ---- epilogue ----
    float* Cf = (float*)Cv;
    __half* Cb = (__half*)Cv;
    const long coff = zb*sCb + zh*sCh;
    #pragma unroll
    for (int mt = 0; mt < 4; mt++) {
        #pragma unroll
        for (int hf = 0; hf < 2; hf++) {
            const int gm = m0 + wm + mt*16 + (lane>>2) + hf*8;
            const float xnr = (EPI==3) ? xn[(long)z*M + gm] : 0.f;
            #pragma unroll
            for (int nt = 0; nt < NT; nt++) {
                const int gn = n0 + wn + nt*8 + (lane&3)*2;
                float v0 = acc[mt][nt][hf*2+0];
                float v1 = acc[mt][nt][hf*2+1];
                if (EPI==0) {
                    if (bias) { v0 += bias[gn]; v1 += bias[gn+1]; }
                } else if (EPI==1) {
                    float t0 = v0 + bias[gn];   v0 = t0 * normcdff(t0);
                    float t1 = v1 + bias[gn+1]; v1 = t1 * normcdff(t1);
                } else if (EPI==2) {
                    v0 *= alpha; v1 *= alpha;
                } else if (EPI==3) {
                    v0 = sqrtf(fmaxf(xnr + xn[(long)z*M + sidx[gn]]   - 2.f*v0, 0.f));
                    v1 = sqrtf(fmaxf(xnr + xn[(long)z*M + sidx[gn+1]] - 2.f*v1, 0.f));
                }
                if (PACKOUT) {
                    __half2 hh; hh.x = __float2half_rn(v0); hh.y = __float2half_rn(v1);
                    *(__half2*)(Cb + coff + (long)gm*ldc + gn) = hh;
                } else {
                    float2 st2; st2.x=v0; st2.y=v1;
                    *(float2*)(Cf + coff + (long)gm*ldc + gn) = st2;
                }
            }
        }
    }
}

// ================= fused flash attention =================
__global__ __launch_bounds__(256)
void flash_k(const __half* __restrict__ qkv, __half* __restrict__ opack) {
    extern __shared__ __half fs[];
    constexpr int LD = 72;
    constexpr int TB = 128*LD;
    const int z = blockIdx.y, b = z/H_, h = z - b*H_;
    const int qb = blockIdx.x;
    const int tid = threadIdx.x, warp = tid>>5, lane = tid&31;
    const int g = lane>>2, t = lane&3;
    const int wm = warp*16;

    const __half* qg = qkv + ((long)b*S_ + qb*128)*2304 + h*64;
    const __half* kg = qkv + (long)b*S_*2304 + 768 + h*64;
    const __half* vg = qkv + (long)b*S_*2304 + 1536 + h*64;
    const uint32_t sq = smem_to_u32(fs);
    const uint32_t sk = sq + TB*2;
    const uint32_t sv = sq + 3*TB*2;

    for (int u = tid; u < 1024; u += 256) {
        int r = u>>3, c = u&7;
        cpa16(sq + (r*LD + c*8)*2, qg + (long)r*2304 + c*8);
        cpa16(sk + (r*LD + c*8)*2, kg + (long)r*2304 + c*8);
        cpa16(sv + (r*LD + c*8)*2, vg + (long)r*2304 + c*8);
    }
    asm volatile("cp.async.commit_group;");
    asm volatile("cp.async.wait_group 0;");
    __syncthreads();

    uint32_t qf[4][4];
    #pragma unroll
    for (int kc = 0; kc < 4; kc++) {
        int r = wm + (lane&15);
        ldsm4(qf[kc], sq + (r*LD + kc*16 + (lane>>4)*8)*2);
    }

    float m0 = -1e30f, m1 = -1e30f, l0 = 0.f, l1 = 0.f;
    float oacc[8][4];
    #pragma unroll
    for (int i=0;i<8;i++) { oacc[i][0]=0.f; oacc[i][1]=0.f; oacc[i][2]=0.f; oacc[i][3]=0.f; }

    for (int kb = 0; kb < 4; ++kb) {
        const int buf = kb&1;
        if (kb) {
            asm volatile("cp.async.wait_group 0;");
            __syncthreads();
        }
        if (kb < 3) {
            const __half* kn = kg + (long)(kb+1)*128*2304;
            const __half* vn = vg + (long)(kb+1)*128*2304;
            const uint32_t dk = sk + (buf^1)*TB*2, dv = sv + (buf^1)*TB*2;
            for (int u = tid; u < 1024; u += 256) {
                int r = u>>3, c = u&7;
                cpa16(dk + (r*LD+c*8)*2, kn + (long)r*2304 + c*8);
                cpa16(dv + (r*LD+c*8)*2, vn + (long)r*2304 + c*8);
            }
            asm volatile("cp.async.commit_group;");
        }
        const uint32_t skb = sk + buf*TB*2, svb = sv + buf*TB*2;

        float sacc[16][4];
        #pragma unroll
        for (int i=0;i<16;i++) { sacc[i][0]=0.f; sacc[i][1]=0.f; sacc[i][2]=0.f; sacc[i][3]=0.f; }
        #pragma unroll
        for (int kc = 0; kc < 4; kc++) {
            #pragma unroll
            for (int ntp = 0; ntp < 8; ntp++) {
                uint32_t b4[4];
                int r = ntp*16 + (lane&7) + ((lane>>4)&1)*8;
                int co = kc*16 + ((lane>>3)&1)*8;
                ldsm4(b4, skb + (r*LD + co)*2);
                mma16816(sacc[2*ntp],   qf[kc], b4);
                mma16816(sacc[2*ntp+1], qf[kc], b4+2);
            }
        }
        float mx0 = -1e30f, mx1 = -1e30f;
        #pragma unroll
        for (int nt=0;nt<16;nt++) {
            sacc[nt][0]*=0.125f; sacc[nt][1]*=0.125f; sacc[nt][2]*=0.125f; sacc[nt][3]*=0.125f;
            mx0 = fmaxf(mx0, fmaxf(sacc[nt][0], sacc[nt][1]));
            mx1 = fmaxf(mx1, fmaxf(sacc[nt][2], sacc[nt][3]));
        }
        mx0 = fmaxf(mx0, __shfl_xor_sync(0xffffffffu, mx0, 1));
        mx0 = fmaxf(mx0, __shfl_xor_sync(0xffffffffu, mx0, 2));
        mx1 = fmaxf(mx1, __shfl_xor_sync(0xffffffffu, mx1, 1));
        mx1 = fmaxf(mx1, __shfl_xor_sync(0xffffffffu, mx1, 2));
        const float mn0 = fmaxf(m0, mx0), mn1 = fmaxf(m1, mx1);
        const float c0 = __expf(m0 - mn0), c1 = __expf(m1 - mn1);
        m0 = mn0; m1 = mn1;
        float rs0 = 0.f, rs1 = 0.f;
        uint32_t ph0[16], ph1[16];
        #pragma unroll
        for (int nt=0;nt<16;nt++) {
            float e0 = __expf(sacc[nt][0]-mn0), e1 = __expf(sacc[nt][1]-mn0);
            float e2 = __expf(sacc[nt][2]-mn1), e3 = __expf(sacc[nt][3]-mn1);
            rs0 += e0+e1; rs1 += e2+e3;
            __half2 p0 = __floats2half2_rn(e0,e1); ph0[nt] = *(uint32_t*)&p0;
            __half2 p1 = __floats2half2_rn(e2,e3); ph1[nt] = *(uint32_t*)&p1;
        }
        rs0 += __shfl_xor_sync(0xffffffffu, rs0, 1);
        rs0 += __shfl_xor_sync(0xffffffffu, rs0, 2);
        rs1 += __shfl_xor_sync(0xffffffffu, rs1, 1);
        rs1 += __shfl_xor_sync(0xffffffffu, rs1, 2);
        l0 = l0*c0 + rs0; l1 = l1*c1 + rs1;
        #pragma unroll
        for (int i=0;i<8;i++) { oacc[i][0]*=c0; oacc[i][1]*=c0; oacc[i][2]*=c1; oacc[i][3]*=c1; }

        #pragma unroll
        for (int kc = 0; kc < 8; kc++) {
            uint32_t a[4] = { ph0[2*kc], ph1[2*kc], ph0[2*kc+1], ph1[2*kc+1] };
            #pragma unroll
            for (int ntp = 0; ntp < 4; ntp++) {
                uint32_t b4[4];
                int r = kc*16 + (lane&15);
                int co = ntp*16 + (lane>>4)*8;
                ldsm4t(b4, svb + (r*LD + co)*2);
                mma16816(oacc[2*ntp],   a, b4);
                mma16816(oacc[2*ntp+1], a, b4+2);
            }
        }
        __syncthreads();
    }

    const float i0 = 1.0f/l0, i1 = 1.0f/l1;
    __half* o0 = opack + ((long)b*S_ + qb*128 + wm + g)*768 + h*64;
    __half* o1 = o0 + 8*768;
    #pragma unroll
    for (int nt = 0; nt < 8; nt++) {
        __half2 h0 = __floats2half2_rn(oacc[nt][0]*i0, oacc[nt][1]*i0);
        __half2 h1 = __floats2half2_rn(oacc[nt][2]*i1, oacc[nt][3]*i1);
        *(__half2*)(o0 + nt*8 + 2*t) = h0;
        *(__half2*)(o1 + nt*8 + 2*t) = h1;
    }
}

// ================= pack / transform =================
__global__ void xsplit_k(const float* __restrict__ x) {
    __shared__ float red[3];
    long r = blockIdx.x; int t = threadIdx.x;
    const float* s = x + r*D_ + t*8;
    float f[8];
    *(float4*)(f)   = *(const float4*)(s);
    *(float4*)(f+4) = *(const float4*)(s+4);
    __half h[8];
    float sq = 0.f;
    #pragma unroll
    for (int u = 0; u < 8; u++) { sq += f[u]*f[u]; h[u] = __float2half_rn(f[u]); }
    *(uint4*)(g_xpack + r*D_ + t*8) = *(uint4*)h;
    #pragma unroll
    for (int o = 16; o; o >>= 1) sq += __shfl_xor_sync(0xffffffffu, sq, o);
    if ((t&31)==0) red[t>>5] = sq;
    __syncthreads();
    if (t==0) g_xnorm[r] = red[0]+red[1]+red[2];
}

// copy fp16 rows from g_xpack (runs after xsplit_k)
__global__ void gatherpack_k(const int* __restrict__ sidx) {
    int j = blockIdx.x, b = blockIdx.y, t = threadIdx.x;
    const __half* s = g_xpack + ((long)b*S_ + sidx[j])*D_ + t*8;
    *(uint4*)(g_spack + ((long)b*NS_ + j)*D_ + t*8) = *(const uint4*)s;
}

// one launch converting all four weight matrices
__global__ void wconv_all_k(const float* __restrict__ w0, const float* __restrict__ w1,
                            const float* __restrict__ w2, const float* __restrict__ w3) {
    int bid = blockIdx.x;
    const float* W; __half* Wh; long base;
    if (bid < 864)      { W = w0; Wh = g_wqkvh; base = bid; }
    else if (bid < 1152){ W = w1; Wh = g_wouth; base = bid - 864; }
    else if (bid < 1728){ W = w2; Wh = g_wf1h;  base = bid - 1152; }
    else                { W = w3; Wh = g_wf2h;  base = bid - 1728; }
    long i = (base*256 + threadIdx.x)*8;
    float f[8];
    *(float4*)(f)   = *(const float4*)(W+i);
    *(float4*)(f+4) = *(const float4*)(W+i+4);
    __half h[8];
    #pragma unroll
    for (int u = 0; u < 8; u++) h[u] = __float2half_rn(f[u]);
    *(uint4*)(Wh + i) = *(uint4*)h;
}

// ================= misc =================
__device__ __forceinline__ float blockReduceSum256(float v, float* red) {
    #pragma unroll
    for (int o = 16; o; o >>= 1) v += __shfl_xor_sync(0xffffffffu, v, o);
    int w = threadIdx.x>>5, l = threadIdx.x&31;
    if (l==0) red[w] = v;
    __syncthreads();
    float r = (threadIdx.x < 8) ? red[threadIdx.x] : 0.f;
    if (w==0) {
        #pragma unroll
        for (int o = 4; o; o >>= 1) r += __shfl_xor_sync(0xffffffffu, r, o);
        if (l==0) red[0] = r;
    }
    __syncthreads();
    float out = red[0];
    __syncthreads();
    return out;
}

__global__ void init_k() {
    int t = threadIdx.x;
    if (t < B_) { g_sum[t]=0.0; g_sumsq[t]=0.0; g_minb[t]=0x7f7fffffu; g_maxb[t]=0u; }
}

__global__ void topk_stats_k() {
    int warp = threadIdx.x >> 5, lane = threadIdx.x & 31;
    long row = (long)blockIdx.x*8 + warp;
    const float4* p = (const float4*)(g_dist + row*NS_);
    float4 v4 = p[lane];
    float v[4] = {v4.x, v4.y, v4.z, v4.w};
    float lsum=0.f, lsq=0.f, mn0=0.f, mx15=0.f;
    #pragma unroll
    for (int it = 0; it < K_; ++it) {
        float lv = fminf(fminf(v[0],v[1]), fminf(v[2],v[3]));
        float m = lv;
        #pragma unroll
        for (int o = 16; o; o >>= 1) m = fminf(m, __shfl_xor_sync(0xffffffffu, m, o));
        unsigned bal = __ballot_sync(0xffffffffu, lv==m);
        if (lane == __ffs(bal)-1) {
            if      (v[0]==m) v[0]=FLT_MAX;
            else if (v[1]==m) v[1]=FLT_MAX;
            else if (v[2]==m) v[2]=FLT_MAX;
            else              v[3]=FLT_MAX;
        }
        lsum += m; lsq += m*m;
        if (it==0) mn0 = m;
        mx15 = m;
    }
    if (lane==0) {
        int b = (int)(row >> 9);
        atomicAdd(&g_sum[b], (double)lsum);
        atomicAdd(&g_sumsq[b], (double)lsq);
        atomicMin(&g_minb[b], __float_as_uint(mn0));
        atomicMax(&g_maxb[b], __float_as_uint(mx15));
    }
}

__global__ void mlp_topo_k(const float* __restrict__ w1, const float* __restrict__ b1,
                           const float* __restrict__ w2, const float* __restrict__ b2,
                           const float* __restrict__ wd0, const float* __restrict__ bd0,
                           const float* __restrict__ topo_w, const float* __restrict__ topo_b,
                           const float* __restrict__ gate) {
    int b = blockIdx.x, tid = threadIdx.x;
    __shared__ float st[6], h1[192], h2[R_], land[R_];
    if (tid==0) {
        double n = 8192.0, s = g_sum[b], sq = g_sumsq[b];
        double mean = s / n;
        double var = (sq - s*s/n) / (n - 1.0);
        float sd = sqrtf(fmaxf((float)var, 0.f));
        st[0]=(float)mean; st[1]=sd;
        st[2]=__uint_as_float(g_minb[b]); st[3]=__uint_as_float(g_maxb[b]);
        st[4]=(float)mean*0.5f; st[5]=sd*0.5f;
    }
    __syncthreads();
    if (tid < 192) {
        float a = b1[tid];
        #pragma unroll
        for (int i = 0; i < 6; i++) a += st[i]*w1[i*192+tid];
        h1[tid] = fmaxf(a, 0.f);
    }
    __syncthreads();
    if (tid < R_) {
        float a = b2[tid];
        for (int i = 0; i < 192; i++) a += h1[i]*w2[i*R_+tid];
        h2[tid] = a;
    }
    __syncthreads();
    if (tid < R_) {
        float a = bd0[tid];
        #pragma unroll
        for (int i = 0; i < R_; i++) a += h2[i]*wd0[i*R_+tid];
        land[tid] = a;
    }
    __syncthreads();
    float gt = *gate;
    for (int d = tid; d < D_; d += blockDim.x) {
        float a = topo_b[d];
        #pragma unroll
        for (int i = 0; i < R_; i++) a += land[i]*topo_w[i*D_+d];
        g_topo[b*D_+d] = gt*a;
    }
}

template<bool FIRST>
__global__ void ln_k(const float* __restrict__ a, const float* __restrict__ br,
                     const float* __restrict__ gamma, const float* __restrict__ beta,
                     float* __restrict__ out, __half* __restrict__ pack) {
    __shared__ float tv[D_];
    __shared__ float red[8];
    long r = blockIdx.x; int tid = threadIdx.x;
    float loc = 0.f;
    for (int d = tid; d < D_; d += 256) {
        float t = a[r*D_+d] + br[r*D_+d];
        if (FIRST) t += g_topo[(r>>9)*D_ + d];
        tv[d] = t; loc += t;
    }
    float mean = blockReduceSum256(loc, red) * (1.f/D_);
    float lv = 0.f;
    for (int d = tid; d < D_; d += 256) { float c = tv[d]-mean; lv += c*c; }
    float var = blockReduceSum256(lv, red) * (1.f/D_);
    float rs = rsqrtf(var + 1e-5f);
    for (int d = tid; d < D_; d += 256) {
        float o = (tv[d]-mean)*rs*gamma[d] + beta[d];
        out[r*D_+d] = o;
        if (FIRST) pack[r*D_+d] = __float2half_rn(o);
    }
}

// ================= host =================
template<class T> static T* symaddr(const void* sym) {
    void* p = nullptr; cudaGetSymbolAddress(&p, sym); return (T*)p;
}

extern "C" void kernel_launch(void* const* d_in, const int* in_sizes, int n_in,
                              void* d_out, int out_size) {
    const float* x      = (const float*)d_in[0];
    const int*   sidx   = (const int*)  d_in[1];
    const float* w1     = (const float*)d_in[2];
    const float* b1     = (const float*)d_in[3];
    const float* w2     = (const float*)d_in[4];
    const float* b2     = (const float*)d_in[5];
    const float* wd0    = (const float*)d_in[6];
    const float* bd0    = (const float*)d_in[7];
    const float* in_w   = (const float*)d_in[10];
    const float* in_b   = (const float*)d_in[11];
    const float* out_w  = (const float*)d_in[12];
    const float* out_b  = (const float*)d_in[13];
    const float* topo_w = (const float*)d_in[14];
    const float* topo_b = (const float*)d_in[15];
    const float* gate   = (const float*)d_in[16];
    const float* ln1_g  = (const float*)d_in[17];
    const float* ln1_b  = (const float*)d_in[18];
    const float* ln2_g  = (const float*)d_in[19];
    const float* ln2_b  = (const float*)d_in[20];
    const float* ffn_w1 = (const float*)d_in[21];
    const float* ffn_b1 = (const float*)d_in[22];
    const float* ffn_w2 = (const float*)d_in[23];
    const float* ffn_b2 = (const float*)d_in[24];
    float* out = (float*)d_out;

    auto p_xnorm = symaddr<float>(g_xnorm);
    auto p_dist  = symaddr<float>(g_dist);
    auto p_xp    = symaddr<__half>(g_xpack);
    auto p_sp    = symaddr<__half>(g_spack);
    auto p_qkvp  = symaddr<__half>(g_qkvpack);
    auto p_op    = symaddr<__half>(g_opack);
    auto p_attnP = symaddr<float>(g_attnP);
    auto p_x1    = symaddr<float>(g_x1);
    auto p_x1p   = symaddr<__half>(g_x1pack);
    auto p_hp    = symaddr<__half>(g_hpack);
    auto p_ffn2  = symaddr<float>(g_ffn2);
    auto p_wqkv  = symaddr<__half>(g_wqkvh);
    auto p_wout  = symaddr<__half>(g_wouth);
    auto p_wf1   = symaddr<__half>(g_wf1h);
    auto p_wf2   = symaddr<__half>(g_wf2h);

    constexpr int FSMEM = 5*128*72*2;   // 92160
    cudaFuncSetAttribute(flash_k, cudaFuncAttributeMaxDynamicSharedMemorySize, FSMEM);

    // prep
    init_k<<<1,32>>>();
    xsplit_k<<<BS_,96>>>(x);
    gatherpack_k<<<dim3(NS_,B_),96>>>(sidx);
    wconv_all_k<<<2304,256>>>(in_w, out_w, ffn_w1, ffn_w2);

    // cdist -> dist (NT)
    hgemm<64,3,false,false><<<dim3(2,4,B_),256>>>(
        p_xp, p_sp, p_dist, nullptr,
        S_, D_, D_, D_, NS_,
        1, (long)S_*D_, 0, (long)NS_*D_, 0, (long)S_*NS_, 0,
        0.f, p_xnorm, sidx);
    topk_stats_k<<<BS_/8,256>>>();
    mlp_topo_k<<<B_,256>>>(w1,b1,w2,b2,wd0,bd0,topo_w,topo_b,gate);

    // QKV projection (NN, packed fp16 out)
    hgemm<128,0,true,true><<<dim3(18,64,1),256>>>(
        p_xp, p_wqkv, p_qkvp, in_b,
        BS_, D_, D_, 3*D_, 3*D_,
        1, 0,0,0,0,0,0, 0.f, nullptr, nullptr);

    // fused attention
    flash_k<<<dim3(4,Z_),256,FSMEM>>>(p_qkvp, p_op);

    // attn out projection (NN)
    hgemm<128,0,false,true><<<dim3(6,64,1),256>>>(
        p_op, p_wout, p_attnP, out_b,
        BS_, D_, D_, D_, D_,
        1, 0,0,0,0,0,0, 0.f, nullptr, nullptr);

    ln_k<true><<<BS_,256>>>(x, p_attnP, ln1_g, ln1_b, p_x1, p_x1p);

    // FFN (NN)
    hgemm<128,1,true,true><<<dim3(12,64,1),256>>>(
        p_x1p, p_wf1, p_hp, ffn_b1,
        BS_, D_, D_, 2*D_, 2*D_,
        1, 0,0,0,0,0,0, 0.f, nullptr, nullptr);
    hgemm<128,0,false,true><<<dim3(6,64,1),256>>>(
        p_hp, p_wf2, p_ffn2, ffn_b2,
        BS_, 2*D_, 2*D_, D_, D_,
        1, 0,0,0,0,0,0, 0.f, nullptr, nullptr);

    ln_k<false><<<BS_,256>>>(p_x1, p_ffn2, ln2_g, ln2_b, out, nullptr);
}

// round 10
// speedup vs baseline: 5.4964x; 1.0254x over previous
#include <cuda_runtime.h>
#include <cuda_fp16.h>
#include <float.h>
#include <cstdint>

#define B_   16
#define S_   512
#define D_   768
#define H_   12
#define HD_  64
#define K_   16
#define NS_  128
#define R_   32
#define BS_  (B_*S_)
#define Z_   (B_*H_)

// ================= PTX helpers =================
__device__ __forceinline__ uint32_t smem_to_u32(const void* p) {
    uint32_t a;
    asm("{ .reg .u64 t; cvta.to.shared.u64 t, %1; cvt.u32.u64 %0, t; }" : "=r"(a) : "l"(p));
    return a;
}
__device__ __forceinline__ void cpa16(uint32_t dst, const void* src) {
    asm volatile("cp.async.ca.shared.global [%0], [%1], 16;" :: "r"(dst), "l"(src));
}
__device__ __forceinline__ void ldsm4(uint32_t* r, uint32_t addr) {
    asm volatile("ldmatrix.sync.aligned.m8n8.x4.shared.b16 {%0,%1,%2,%3}, [%4];"
        : "=r"(r[0]), "=r"(r[1]), "=r"(r[2]), "=r"(r[3]) : "r"(addr));
}
__device__ __forceinline__ void ldsm2(uint32_t* r, uint32_t addr) {
    asm volatile("ldmatrix.sync.aligned.m8n8.x2.shared.b16 {%0,%1}, [%2];"
        : "=r"(r[0]), "=r"(r[1]) : "r"(addr));
}
__device__ __forceinline__ void ldsm4t(uint32_t* r, uint32_t addr) {
    asm volatile("ldmatrix.sync.aligned.m8n8.x4.trans.shared.b16 {%0,%1,%2,%3}, [%4];"
        : "=r"(r[0]), "=r"(r[1]), "=r"(r[2]), "=r"(r[3]) : "r"(addr));
}
__device__ __forceinline__ void mma16816(float* c, const uint32_t* a, const uint32_t* b) {
    asm volatile("mma.sync.aligned.m16n8k16.row.col.f32.f16.f16.f32 "
        "{%0,%1,%2,%3}, {%4,%5,%6,%7}, {%8,%9}, {%0,%1,%2,%3};"
        : "+f"(c[0]), "+f"(c[1]), "+f"(c[2]), "+f"(c[3])
        : "r"(a[0]), "r"(a[1]), "r"(a[2]), "r"(a[3]), "r"(b[0]), "r"(b[1]));
}

// ================= scratch =================
__device__ float    g_xnorm[BS_];
__device__ double   g_sum[B_], g_sumsq[B_];
__device__ unsigned g_minb[B_], g_maxb[B_];
__device__ float    g_dist[B_*S_*NS_];
__device__ float    g_topo[B_*D_];
__device__ __align__(16) __half g_xpack [BS_*D_];
__device__ __align__(16) __half g_spack [B_*NS_*D_];
__device__ __align__(16) __half g_qkvpack[(size_t)BS_*3*D_];
__device__ __align__(16) __half g_opack [BS_*D_];
__device__ float    g_attnP[BS_*D_];
__device__ float    g_x1[BS_*D_];
__device__ __align__(16) __half g_x1pack[BS_*D_];
__device__ __align__(16) __half g_hpack [(size_t)BS_*2*D_];
__device__ float    g_ffn2[BS_*D_];
__device__ __align__(16) __half g_wqkvh[D_*3*D_];     // [K][N] fp16
__device__ __align__(16) __half g_wouth[D_*D_];
__device__ __align__(16) __half g_wf1h [D_*2*D_];
__device__ __align__(16) __half g_wf2h [2*D_*D_];

// ================= HMMA GEMM (3-stage pipeline, BK=64) =================
// C[128,BN] = A[M,K] * B.  BNN=true: B stored [K][N]; false: B stored [N][K].
// EPI: 0=+bias, 1=gelu, 2=*alpha, 3=cdist.
template<int BN, int EPI, bool PACKOUT, bool BNN>
__global__ __launch_bounds__(256,2)
void hgemm(const __half* __restrict__ A, const __half* __restrict__ Bm,
           void* __restrict__ Cv, const float* __restrict__ bias,
           int M, int Kd, int lda, int ldb, int ldc,
           int Hdiv, long sAb, long sAh, long sBb, long sBh, long sCb, long sCh,
           float alpha, const float* __restrict__ xn, const int* __restrict__ sidx)
{
    constexpr int NT = BN/32;
    constexpr int NW = BN/4;
    constexpr int AH = 128*72;                         // halfs per A stage (BK=64 + 8 pad)
    constexpr int BH = BNN ? 64*136 : BN*72;           // halfs per B stage
    constexpr int NSTG = 3;
    extern __shared__ __half dsm[];

    const int tid = threadIdx.x, warp = tid>>5, lane = tid&31;
    const int wm = (warp>>2)*64, wn = (warp&3)*NW;
    const int z = blockIdx.z, zb = z/Hdiv, zh = z - zb*Hdiv;
    A  += zb*sAb + zh*sAh;
    Bm += zb*sBb + zh*sBh;
    const int n0 = blockIdx.x*BN, m0 = blockIdx.y*128;
    const uint32_t sa = smem_to_u32(dsm);
    const uint32_t sb = sa + NSTG*AH*2;

    float acc[4][NT][4];
    #pragma unroll
    for (int i=0;i<4;i++)
        #pragma unroll
        for (int j=0;j<NT;j++)
            #pragma unroll
            for (int q=0;q<4;q++) acc[i][j][q]=0.f;

    const int nch = Kd>>6;

    auto loadA = [&](int ko, int st) {
        #pragma unroll 4
        for (int u = tid; u < 1024; u += 256) {
            int r = u>>3, c = u&7;
            cpa16(sa + st*AH*2 + (r*72+c*8)*2, A + (long)(m0+r)*lda + ko + c*8);
        }
    };
    auto loadB = [&](int ko, int st) {
        if (BNN) {
            #pragma unroll 4
            for (int u = tid; u < 64*(BN/8); u += 256) {
                int r = u/(BN/8), c = u%(BN/8);
                cpa16(sb + st*BH*2 + (r*136+c*8)*2, Bm + (long)(ko+r)*ldb + n0 + c*8);
            }
        } else {
            #pragma unroll 2
            for (int u = tid; u < BN*8; u += 256) {
                int r = u>>3, c = u&7;
                cpa16(sb + st*BH*2 + (r*72+c*8)*2, Bm + (long)(n0+r)*ldb + ko + c*8);
            }
        }
    };

    // prime stages 0,1
    loadA(0,0); loadB(0,0);
    asm volatile("cp.async.commit_group;");
    if (nch > 1) { loadA(64,1); loadB(64,1); }
    asm volatile("cp.async.commit_group;");

    int st = 0;
    for (int it = 0; it < nch; ++it) {
        asm volatile("cp.async.wait_group 1;");
        __syncthreads();

        const uint32_t sab = sa + st*AH*2;
        const uint32_t sbb = sb + st*BH*2;
        #pragma unroll
        for (int kk = 0; kk < 64; kk += 16) {
            uint32_t af[4][4], bf[NT][2];
            #pragma unroll
            for (int mt = 0; mt < 4; mt++) {
                int r = wm + mt*16 + (lane&15);
                ldsm4(af[mt], sab + (r*72 + kk + (lane>>4)*8)*2);
            }
            if (BNN) {
                #pragma unroll
                for (int np = 0; np < NT/2; np++) {
                    uint32_t b4[4];
                    int r = kk + (lane&15);
                    int co = wn + np*16 + (lane>>4)*8;
                    ldsm4t(b4, sbb + (r*136 + co)*2);
                    bf[2*np][0]   = b4[0]; bf[2*np][1]   = b4[1];
                    bf[2*np+1][0] = b4[2]; bf[2*np+1][1] = b4[3];
                }
            } else {
                #pragma unroll
                for (int nt = 0; nt < NT; nt++) {
                    int r = wn + nt*8 + (lane&7);
                    int co = kk + ((lane>>3)&1)*8;
                    ldsm2(bf[nt], sbb + (r*72 + co)*2);
                }
            }
            #pragma unroll
            for (int mt = 0; mt < 4; mt++)
                #pragma unroll
                for (int nt = 0; nt < NT; nt++)
                    mma16816(acc[mt][nt], af[mt], bf[nt]);
        }
        __syncthreads();
        if (it+2 < nch) {
            loadA((it+2)<<6, (st+2)%NSTG); loadB((it+2)<<6, (st+2)%NSTG);
        }
        asm volatile("cp.async.commit_group;");
        st = (st+1)%NSTG;
    }

    // ---- epilogue ----
    float* Cf = (float*)Cv;
    __half* Cb = (__half*)Cv;
    const long coff = zb*sCb + zh*sCh;
    #pragma unroll
    for (int mt = 0; mt < 4; mt++) {
        #pragma unroll
        for (int hf = 0; hf < 2; hf++) {
            const int gm = m0 + wm + mt*16 + (lane>>2) + hf*8;
            const float xnr = (EPI==3) ? xn[(long)z*M + gm] : 0.f;
            #pragma unroll
            for (int nt = 0; nt < NT; nt++) {
                const int gn = n0 + wn + nt*8 + (lane&3)*2;
                float v0 = acc[mt][nt][hf*2+0];
                float v1 = acc[mt][nt][hf*2+1];
                if (EPI==0) {
                    if (bias) { v0 += bias[gn]; v1 += bias[gn+1]; }
                } else if (EPI==1) {
                    float t0 = v0 + bias[gn];   v0 = t0 * normcdff(t0);
                    float t1 = v1 + bias[gn+1]; v1 = t1 * normcdff(t1);
                } else if (EPI==2) {
                    v0 *= alpha; v1 *= alpha;
                } else if (EPI==3) {
                    v0 = sqrtf(fmaxf(xnr + xn[(long)z*M + sidx[gn]]   - 2.f*v0, 0.f));
                    v1 = sqrtf(fmaxf(xnr + xn[(long)z*M + sidx[gn+1]] - 2.f*v1, 0.f));
                }
                if (PACKOUT) {
                    __half2 hh; hh.x = __float2half_rn(v0); hh.y = __float2half_rn(v1);
                    *(__half2*)(Cb + coff + (long)gm*ldc + gn) = hh;
                } else {
                    float2 st2; st2.x=v0; st2.y=v1;
                    *(float2*)(Cf + coff + (long)gm*ldc + gn) = st2;
                }
            }
        }
    }
}

// ================= fused flash attention =================
__global__ __launch_bounds__(256)
void flash_k(const __half* __restrict__ qkv, __half* __restrict__ opack) {
    extern __shared__ __half fs[];
    constexpr int LD = 72;
    constexpr int TB = 128*LD;
    const int z = blockIdx.y, b = z/H_, h = z - b*H_;
    const int qb = blockIdx.x;
    const int tid = threadIdx.x, warp = tid>>5, lane = tid&31;
    const int g = lane>>2, t = lane&3;
    const int wm = warp*16;

    const __half* qg = qkv + ((long)b*S_ + qb*128)*2304 + h*64;
    const __half* kg = qkv + (long)b*S_*2304 + 768 + h*64;
    const __half* vg = qkv + (long)b*S_*2304 + 1536 + h*64;
    const uint32_t sq = smem_to_u32(fs);
    const uint32_t sk = sq + TB*2;
    const uint32_t sv = sq + 3*TB*2;

    for (int u = tid; u < 1024; u += 256) {
        int r = u>>3, c = u&7;
        cpa16(sq + (r*LD + c*8)*2, qg + (long)r*2304 + c*8);
        cpa16(sk + (r*LD + c*8)*2, kg + (long)r*2304 + c*8);
        cpa16(sv + (r*LD + c*8)*2, vg + (long)r*2304 + c*8);
    }
    asm volatile("cp.async.commit_group;");
    asm volatile("cp.async.wait_group 0;");
    __syncthreads();

    uint32_t qf[4][4];
    #pragma unroll
    for (int kc = 0; kc < 4; kc++) {
        int r = wm + (lane&15);
        ldsm4(qf[kc], sq + (r*LD + kc*16 + (lane>>4)*8)*2);
    }

    float m0 = -1e30f, m1 = -1e30f, l0 = 0.f, l1 = 0.f;
    float oacc[8][4];
    #pragma unroll
    for (int i=0;i<8;i++) { oacc[i][0]=0.f; oacc[i][1]=0.f; oacc[i][2]=0.f; oacc[i][3]=0.f; }

    for (int kb = 0; kb < 4; ++kb) {
        const int buf = kb&1;
        if (kb) {
            asm volatile("cp.async.wait_group 0;");
            __syncthreads();
        }
        if (kb < 3) {
            const __half* kn = kg + (long)(kb+1)*128*2304;
            const __half* vn = vg + (long)(kb+1)*128*2304;
            const uint32_t dk = sk + (buf^1)*TB*2, dv = sv + (buf^1)*TB*2;
            for (int u = tid; u < 1024; u += 256) {
                int r = u>>3, c = u&7;
                cpa16(dk + (r*LD+c*8)*2, kn + (long)r*2304 + c*8);
                cpa16(dv + (r*LD+c*8)*2, vn + (long)r*2304 + c*8);
            }
            asm volatile("cp.async.commit_group;");
        }
        const uint32_t skb = sk + buf*TB*2, svb = sv + buf*TB*2;

        float sacc[16][4];
        #pragma unroll
        for (int i=0;i<16;i++) { sacc[i][0]=0.f; sacc[i][1]=0.f; sacc[i][2]=0.f; sacc[i][3]=0.f; }
        #pragma unroll
        for (int kc = 0; kc < 4; kc++) {
            #pragma unroll
            for (int ntp = 0; ntp < 8; ntp++) {
                uint32_t b4[4];
                int r = ntp*16 + (lane&7) + ((lane>>4)&1)*8;
                int co = kc*16 + ((lane>>3)&1)*8;
                ldsm4(b4, skb + (r*LD + co)*2);
                mma16816(sacc[2*ntp],   qf[kc], b4);
                mma16816(sacc[2*ntp+1], qf[kc], b4+2);
            }
        }
        float mx0 = -1e30f, mx1 = -1e30f;
        #pragma unroll
        for (int nt=0;nt<16;nt++) {
            sacc[nt][0]*=0.125f; sacc[nt][1]*=0.125f; sacc[nt][2]*=0.125f; sacc[nt][3]*=0.125f;
            mx0 = fmaxf(mx0, fmaxf(sacc[nt][0], sacc[nt][1]));
            mx1 = fmaxf(mx1, fmaxf(sacc[nt][2], sacc[nt][3]));
        }
        mx0 = fmaxf(mx0, __shfl_xor_sync(0xffffffffu, mx0, 1));
        mx0 = fmaxf(mx0, __shfl_xor_sync(0xffffffffu, mx0, 2));
        mx1 = fmaxf(mx1, __shfl_xor_sync(0xffffffffu, mx1, 1));
        mx1 = fmaxf(mx1, __shfl_xor_sync(0xffffffffu, mx1, 2));
        const float mn0 = fmaxf(m0, mx0), mn1 = fmaxf(m1, mx1);
        const float c0 = __expf(m0 - mn0), c1 = __expf(m1 - mn1);
        m0 = mn0; m1 = mn1;
        float rs0 = 0.f, rs1 = 0.f;
        uint32_t ph0[16], ph1[16];
        #pragma unroll
        for (int nt=0;nt<16;nt++) {
            float e0 = __expf(sacc[nt][0]-mn0), e1 = __expf(sacc[nt][1]-mn0);
            float e2 = __expf(sacc[nt][2]-mn1), e3 = __expf(sacc[nt][3]-mn1);
            rs0 += e0+e1; rs1 += e2+e3;
            __half2 p0 = __floats2half2_rn(e0,e1); ph0[nt] = *(uint32_t*)&p0;
            __half2 p1 = __floats2half2_rn(e2,e3); ph1[nt] = *(uint32_t*)&p1;
        }
        rs0 += __shfl_xor_sync(0xffffffffu, rs0, 1);
        rs0 += __shfl_xor_sync(0xffffffffu, rs0, 2);
        rs1 += __shfl_xor_sync(0xffffffffu, rs1, 1);
        rs1 += __shfl_xor_sync(0xffffffffu, rs1, 2);
        l0 = l0*c0 + rs0; l1 = l1*c1 + rs1;
        #pragma unroll
        for (int i=0;i<8;i++) { oacc[i][0]*=c0; oacc[i][1]*=c0; oacc[i][2]*=c1; oacc[i][3]*=c1; }

        #pragma unroll
        for (int kc = 0; kc < 8; kc++) {
            uint32_t a[4] = { ph0[2*kc], ph1[2*kc], ph0[2*kc+1], ph1[2*kc+1] };
            #pragma unroll
            for (int ntp = 0; ntp < 4; ntp++) {
                uint32_t b4[4];
                int r = kc*16 + (lane&15);
                int co = ntp*16 + (lane>>4)*8;
                ldsm4t(b4, svb + (r*LD + co)*2);
                mma16816(oacc[2*ntp],   a, b4);
                mma16816(oacc[2*ntp+1], a, b4+2);
            }
        }
        __syncthreads();
    }

    const float i0 = 1.0f/l0, i1 = 1.0f/l1;
    __half* o0 = opack + ((long)b*S_ + qb*128 + wm + g)*768 + h*64;
    __half* o1 = o0 + 8*768;
    #pragma unroll
    for (int nt = 0; nt < 8; nt++) {
        __half2 h0 = __floats2half2_rn(oacc[nt][0]*i0, oacc[nt][1]*i0);
        __half2 h1 = __floats2half2_rn(oacc[nt][2]*i1, oacc[nt][3]*i1);
        *(__half2*)(o0 + nt*8 + 2*t) = h0;
        *(__half2*)(o1 + nt*8 + 2*t) = h1;
    }
}

// ================= pack / transform =================
__global__ void xsplit_k(const float* __restrict__ x) {
    __shared__ float red[3];
    long r = blockIdx.x; int t = threadIdx.x;
    const float* s = x + r*D_ + t*8;
    float f[8];
    *(float4*)(f)   = *(const float4*)(s);
    *(float4*)(f+4) = *(const float4*)(s+4);
    __half h[8];
    float sq = 0.f;
    #pragma unroll
    for (int u = 0; u < 8; u++) { sq += f[u]*f[u]; h[u] = __float2half_rn(f[u]); }
    *(uint4*)(g_xpack + r*D_ + t*8) = *(uint4*)h;
    #pragma unroll
    for (int o = 16; o; o >>= 1) sq += __shfl_xor_sync(0xffffffffu, sq, o);
    if ((t&31)==0) red[t>>5] = sq;
    __syncthreads();
    if (t==0) g_xnorm[r] = red[0]+red[1]+red[2];
}

__global__ void gatherpack_k(const int* __restrict__ sidx) {
    int j = blockIdx.x, b = blockIdx.y, t = threadIdx.x;
    const __half* s = g_xpack + ((long)b*S_ + sidx[j])*D_ + t*8;
    *(uint4*)(g_spack + ((long)b*NS_ + j)*D_ + t*8) = *(const uint4*)s;
}

__global__ void wconv_all_k(const float* __restrict__ w0, const float* __restrict__ w1,
                            const float* __restrict__ w2, const float* __restrict__ w3) {
    int bid = blockIdx.x;
    const float* W; __half* Wh; long base;
    if (bid < 864)      { W = w0; Wh = g_wqkvh; base = bid; }
    else if (bid < 1152){ W = w1; Wh = g_wouth; base = bid - 864; }
    else if (bid < 1728){ W = w2; Wh = g_wf1h;  base = bid - 1152; }
    else                { W = w3; Wh = g_wf2h;  base = bid - 1728; }
    long i = (base*256 + threadIdx.x)*8;
    float f[8];
    *(float4*)(f)   = *(const float4*)(W+i);
    *(float4*)(f+4) = *(const float4*)(W+i+4);
    __half h[8];
    #pragma unroll
    for (int u = 0; u < 8; u++) h[u] = __float2half_rn(f[u]);
    *(uint4*)(Wh + i) = *(uint4*)h;
}

// ================= misc =================
__device__ __forceinline__ float blockReduceSum256(float v, float* red) {
    #pragma unroll
    for (int o = 16; o; o >>= 1) v += __shfl_xor_sync(0xffffffffu, v, o);
    int w = threadIdx.x>>5, l = threadIdx.x&31;
    if (l==0) red[w] = v;
    __syncthreads();
    float r = (threadIdx.x < 8) ? red[threadIdx.x] : 0.f;
    if (w==0) {
        #pragma unroll
        for (int o = 4; o; o >>= 1) r += __shfl_xor_sync(0xffffffffu, r, o);
        if (l==0) red[0] = r;
    }
    __syncthreads();
    float out = red[0];
    __syncthreads();
    return out;
}

__global__ void init_k() {
    int t = threadIdx.x;
    if (t < B_) { g_sum[t]=0.0; g_sumsq[t]=0.0; g_minb[t]=0x7f7fffffu; g_maxb[t]=0u; }
}

__global__ void topk_stats_k() {
    int warp = threadIdx.x >> 5, lane = threadIdx.x & 31;
    long row = (long)blockIdx.x*8 + warp;
    const float4* p = (const float4*)(g_dist + row*NS_);
    float4 v4 = p[lane];
    float v[4] = {v4.x, v4.y, v4.z, v4.w};
    float lsum=0.f, lsq=0.f, mn0=0.f, mx15=0.f;
    #pragma unroll
    for (int it = 0; it < K_; ++it) {
        float lv = fminf(fminf(v[0],v[1]), fminf(v[2],v[3]));
        float m = lv;
        #pragma unroll
        for (int o = 16; o; o >>= 1) m = fminf(m, __shfl_xor_sync(0xffffffffu, m, o));
        unsigned bal = __ballot_sync(0xffffffffu, lv==m);
        if (lane == __ffs(bal)-1) {
            if      (v[0]==m) v[0]=FLT_MAX;
            else if (v[1]==m) v[1]=FLT_MAX;
            else if (v[2]==m) v[2]=FLT_MAX;
            else              v[3]=FLT_MAX;
        }
        lsum += m; lsq += m*m;
        if (it==0) mn0 = m;
        mx15 = m;
    }
    if (lane==0) {
        int b = (int)(row >> 9);
        atomicAdd(&g_sum[b], (double)lsum);
        atomicAdd(&g_sumsq[b], (double)lsq);
        atomicMin(&g_minb[b], __float_as_uint(mn0));
        atomicMax(&g_maxb[b], __float_as_uint(mx15));
    }
}

__global__ void mlp_topo_k(const float* __restrict__ w1, const float* __restrict__ b1,
                           const float* __restrict__ w2, const float* __restrict__ b2,
                           const float* __restrict__ wd0, const float* __restrict__ bd0,
                           const float* __restrict__ topo_w, const float* __restrict__ topo_b,
                           const float* __restrict__ gate) {
    int b = blockIdx.x, tid = threadIdx.x;
    __shared__ float st[6], h1[192], h2[R_], land[R_];
    if (tid==0) {
        double n = 8192.0, s = g_sum[b], sq = g_sumsq[b];
        double mean = s / n;
        double var = (sq - s*s/n) / (n - 1.0);
        float sd = sqrtf(fmaxf((float)var, 0.f));
        st[0]=(float)mean; st[1]=sd;
        st[2]=__uint_as_float(g_minb[b]); st[3]=__uint_as_float(g_maxb[b]);
        st[4]=(float)mean*0.5f; st[5]=sd*0.5f;
    }
    __syncthreads();
    if (tid < 192) {
        float a = b1[tid];
        #pragma unroll
        for (int i = 0; i < 6; i++) a += st[i]*w1[i*192+tid];
        h1[tid] = fmaxf(a, 0.f);
    }
    __syncthreads();
    if (tid < R_) {
        float a = b2[tid];
        for (int i = 0; i < 192; i++) a += h1[i]*w2[i*R_+tid];
        h2[tid] = a;
    }
    __syncthreads();
    if (tid < R_) {
        float a = bd0[tid];
        #pragma unroll
        for (int i = 0; i < R_; i++) a += h2[i]*wd0[i*R_+tid];
        land[tid] = a;
    }
    __syncthreads();
    float gt = *gate;
    for (int d = tid; d < D_; d += blockDim.x) {
        float a = topo_b[d];
        #pragma unroll
        for (int i = 0; i < R_; i++) a += land[i]*topo_w[i*D_+d];
        g_topo[b*D_+d] = gt*a;
    }
}

template<bool FIRST>
__global__ void ln_k(const float* __restrict__ a, const float* __restrict__ br,
                     const float* __restrict__ gamma, const float* __restrict__ beta,
                     float* __restrict__ out, __half* __restrict__ pack) {
    __shared__ float tv[D_];
    __shared__ float red[8];
    long r = blockIdx.x; int tid = threadIdx.x;
    float loc = 0.f;
    for (int d = tid; d < D_; d += 256) {
        float t = a[r*D_+d] + br[r*D_+d];
        if (FIRST) t += g_topo[(r>>9)*D_ + d];
        tv[d] = t; loc += t;
    }
    float mean = blockReduceSum256(loc, red) * (1.f/D_);
    float lv = 0.f;
    for (int d = tid; d < D_; d += 256) { float c = tv[d]-mean; lv += c*c; }
    float var = blockReduceSum256(lv, red) * (1.f/D_);
    float rs = rsqrtf(var + 1e-5f);
    for (int d = tid; d < D_; d += 256) {
        float o = (tv[d]-mean)*rs*gamma[d] + beta[d];
        out[r*D_+d] = o;
        if (FIRST) pack[r*D_+d] = __float2half_rn(o);
    }
}

// ================= host =================
template<class T> static T* symaddr(const void* sym) {
    void* p = nullptr; cudaGetSymbolAddress(&p, sym); return (T*)p;
}

extern "C" void kernel_launch(void* const* d_in, const int* in_sizes, int n_in,
                              void* d_out, int out_size) {
    const float* x      = (const float*)d_in[0];
    const int*   sidx   = (const int*)  d_in[1];
    const float* w1     = (const float*)d_in[2];
    const float* b1     = (const float*)d_in[3];
    const float* w2     = (const float*)d_in[4];
    const float* b2     = (const float*)d_in[5];
    const float* wd0    = (const float*)d_in[6];
    const float* bd0    = (const float*)d_in[7];
    const float* in_w   = (const float*)d_in[10];
    const float* in_b   = (const float*)d_in[11];
    const float* out_w  = (const float*)d_in[12];
    const float* out_b  = (const float*)d_in[13];
    const float* topo_w = (const float*)d_in[14];
    const float* topo_b = (const float*)d_in[15];
    const float* gate   = (const float*)d_in[16];
    const float* ln1_g  = (const float*)d_in[17];
    const float* ln1_b  = (const float*)d_in[18];
    const float* ln2_g  = (const float*)d_in[19];
    const float* ln2_b  = (const float*)d_in[20];
    const float* ffn_w1 = (const float*)d_in[21];
    const float* ffn_b1 = (const float*)d_in[22];
    const float* ffn_w2 = (const float*)d_in[23];
    const float* ffn_b2 = (const float*)d_in[24];
    float* out = (float*)d_out;

    auto p_xnorm = symaddr<float>(g_xnorm);
    auto p_dist  = symaddr<float>(g_dist);
    auto p_xp    = symaddr<__half>(g_xpack);
    auto p_sp    = symaddr<__half>(g_spack);
    auto p_qkvp  = symaddr<__half>(g_qkvpack);
    auto p_op    = symaddr<__half>(g_opack);
    auto p_attnP = symaddr<float>(g_attnP);
    auto p_x1    = symaddr<float>(g_x1);
    auto p_x1p   = symaddr<__half>(g_x1pack);
    auto p_hp    = symaddr<__half>(g_hpack);
    auto p_ffn2  = symaddr<float>(g_ffn2);
    auto p_wqkv  = symaddr<__half>(g_wqkvh);
    auto p_wout  = symaddr<__half>(g_wouth);
    auto p_wf1   = symaddr<__half>(g_wf1h);
    auto p_wf2   = symaddr<__half>(g_wf2h);

    // dynamic smem sizes: 3 stages of (A:128x72 + B)
    constexpr int SM_BNN = 3*(128*72 + 64*136)*2;   // 105216
    constexpr int SM_NT  = 3*(128*72 + 64*72)*2;    // 82944
    constexpr int FSMEM  = 5*128*72*2;              // 92160
    cudaFuncSetAttribute(hgemm<128,0,true ,true >, cudaFuncAttributeMaxDynamicSharedMemorySize, SM_BNN);
    cudaFuncSetAttribute(hgemm<128,0,false,true >, cudaFuncAttributeMaxDynamicSharedMemorySize, SM_BNN);
    cudaFuncSetAttribute(hgemm<128,1,true ,true >, cudaFuncAttributeMaxDynamicSharedMemorySize, SM_BNN);
    cudaFuncSetAttribute(hgemm<64, 3,false,false>, cudaFuncAttributeMaxDynamicSharedMemorySize, SM_NT);
    cudaFuncSetAttribute(flash_k, cudaFuncAttributeMaxDynamicSharedMemorySize, FSMEM);

    // prep
    init_k<<<1,32>>>();
    xsplit_k<<<BS_,96>>>(x);
    gatherpack_k<<<dim3(NS_,B_),96>>>(sidx);
    wconv_all_k<<<2304,256>>>(in_w, out_w, ffn_w1, ffn_w2);

    // cdist -> dist (NT)
    hgemm<64,3,false,false><<<dim3(2,4,B_),256,SM_NT>>>(
        p_xp, p_sp, p_dist, nullptr,
        S_, D_, D_, D_, NS_,
        1, (long)S_*D_, 0, (long)NS_*D_, 0, (long)S_*NS_, 0,
        0.f, p_xnorm, sidx);
    topk_stats_k<<<BS_/8,256>>>();
    mlp_topo_k<<<B_,256>>>(w1,b1,w2,b2,wd0,bd0,topo_w,topo_b,gate);

    // QKV projection (NN, packed fp16 out)
    hgemm<128,0,true,true><<<dim3(18,64,1),256,SM_BNN>>>(
        p_xp, p_wqkv, p_qkvp, in_b,
        BS_, D_, D_, 3*D_, 3*D_,
        1, 0,0,0,0,0,0, 0.f, nullptr, nullptr);

    // fused attention
    flash_k<<<dim3(4,Z_),256,FSMEM>>>(p_qkvp, p_op);

    // attn out projection (NN)
    hgemm<128,0,false,true><<<dim3(6,64,1),256,SM_BNN>>>(
        p_op, p_wout, p_attnP, out_b,
        BS_, D_, D_, D_, D_,
        1, 0,0,0,0,0,0, 0.f, nullptr, nullptr);

    ln_k<true><<<BS_,256>>>(x, p_attnP, ln1_g, ln1_b, p_x1, p_x1p);

    // FFN (NN)
    hgemm<128,1,true,true><<<dim3(12,64,1),256,SM_BNN>>>(
        p_x1p, p_wf1, p_hp, ffn_b1,
        BS_, D_, D_, 2*D_, 2*D_,
        1, 0,0,0,0,0,0, 0.f, nullptr, nullptr);
    hgemm<128,0,false,true><<<dim3(6,64,1),256,SM_BNN>>>(
        p_hp, p_wf2, p_ffn2, ffn_b2,
        BS_, 2*D_, 2*D_, D_, D_,
        1, 0,0,0,0,0,0, 0.f, nullptr, nullptr);

    ln_k<false><<<BS_,256>>>(p_x1, p_ffn2, ln2_g, ln2_b, out, nullptr);
}